// round 7
// baseline (speedup 1.0000x reference)
#include <cuda_runtime.h>
#include <stdint.h>
#include <stddef.h>

#define B_ 4
#define S_ 2048
#define HID_ 768
#define H_ 12
#define D_ 64
#define BH_ 48
#define MROWS 8192
#define OUTE 6291456
#define SCALE_ 0.125f

// Scratch: q, k, v (BHSD each) + context (row-major [8192,768])
__device__ float g_scratch[4ull * 6291456ull];
// Bitmask: [B][S][S/32]
__device__ uint32_t g_bm[524288];

// ---------------------------------------------------------------------------
__device__ __forceinline__ uint32_t f2t(float f) {
    uint32_t r;
    asm("cvt.rna.tf32.f32 %0, %1;" : "=r"(r) : "f"(f));
    return r;
}

__device__ __forceinline__ void mma8(float* c,
    uint32_t a0, uint32_t a1, uint32_t a2, uint32_t a3,
    uint32_t b0, uint32_t b1)
{
    asm volatile(
        "mma.sync.aligned.m16n8k8.row.col.f32.tf32.tf32.f32 "
        "{%0,%1,%2,%3}, {%4,%5,%6,%7}, {%8,%9}, {%0,%1,%2,%3};"
        : "+f"(c[0]), "+f"(c[1]), "+f"(c[2]), "+f"(c[3])
        : "r"(a0), "r"(a1), "r"(a2), "r"(a3), "r"(b0), "r"(b1));
}

// ---------------------------------------------------------------------------
// Bitmask builder: mask int32 -> bits (1 = masked)
// ---------------------------------------------------------------------------
__global__ __launch_bounds__(256) void build_bitmask(
    const int* __restrict__ mask, uint32_t* __restrict__ bm)
{
    int idx = blockIdx.x * 256 + threadIdx.x;
    const int* p = mask + (size_t)idx * 32;
    uint32_t r = 0;
#pragma unroll
    for (int j = 0; j < 8; j++) {
        int4 v = *(const int4*)(p + 4 * j);
        r |= (v.x != 0 ? 1u : 0u) << (4 * j);
        r |= (v.y != 0 ? 1u : 0u) << (4 * j + 1);
        r |= (v.z != 0 ? 1u : 0u) << (4 * j + 2);
        r |= (v.w != 0 ? 1u : 0u) << (4 * j + 3);
    }
    bm[idx] = r;
}

// ---------------------------------------------------------------------------
// Projection GEMMs (R4 version - proven fastest)
// ---------------------------------------------------------------------------
template <int MODE>
__device__ __forceinline__ void gemm_core(
    const float* __restrict__ X, const float* __restrict__ W,
    const float* __restrict__ bias, float* __restrict__ out,
    uint32_t (*Xs)[36], uint32_t (*Ws)[136], int m0, int n0)
{
    const int tid  = threadIdx.x;
    const int w    = tid >> 5;
    const int lane = tid & 31;
    const int g    = lane >> 2;
    const int t    = lane & 3;
    const int wm   = (w & 1) * 64;
    const int wn   = (w >> 1) * 32;

    float acc[4][4][4];
#pragma unroll
    for (int mi = 0; mi < 4; mi++)
#pragma unroll
        for (int ni = 0; ni < 4; ni++)
#pragma unroll
            for (int r = 0; r < 4; r++) acc[mi][ni][r] = 0.f;

    for (int k0 = 0; k0 < HID_; k0 += 32) {
#pragma unroll
        for (int i = 0; i < 4; i++) {
            int f = tid + 256 * i;
            int r = f >> 3, q = f & 7;
            float4 v = *(const float4*)(X + (size_t)(m0 + r) * HID_ + k0 + q * 4);
            *(uint4*)&Xs[r][q * 4] = make_uint4(f2t(v.x), f2t(v.y), f2t(v.z), f2t(v.w));
        }
#pragma unroll
        for (int i = 0; i < 4; i++) {
            int f = tid + 256 * i;
            int r = f >> 5, q = f & 31;
            float4 v = *(const float4*)(W + (size_t)(k0 + r) * HID_ + n0 + q * 4);
            *(uint4*)&Ws[r][q * 4] = make_uint4(f2t(v.x), f2t(v.y), f2t(v.z), f2t(v.w));
        }
        __syncthreads();
#pragma unroll
        for (int kk = 0; kk < 32; kk += 8) {
            uint32_t a[4][4], b[4][2];
#pragma unroll
            for (int mi = 0; mi < 4; mi++) {
                int mr = wm + 16 * mi + g;
                a[mi][0] = Xs[mr][kk + t];     a[mi][1] = Xs[mr + 8][kk + t];
                a[mi][2] = Xs[mr][kk + t + 4]; a[mi][3] = Xs[mr + 8][kk + t + 4];
            }
#pragma unroll
            for (int ni = 0; ni < 4; ni++) {
                b[ni][0] = Ws[kk + t][wn + 8 * ni + g];
                b[ni][1] = Ws[kk + t + 4][wn + 8 * ni + g];
            }
#pragma unroll
            for (int mi = 0; mi < 4; mi++)
#pragma unroll
                for (int ni = 0; ni < 4; ni++)
                    mma8(acc[mi][ni], a[mi][0], a[mi][1], a[mi][2], a[mi][3],
                         b[ni][0], b[ni][1]);
        }
        __syncthreads();
    }

#pragma unroll
    for (int mi = 0; mi < 4; mi++) {
        int r0 = m0 + wm + 16 * mi + g;
        int r1 = r0 + 8;
#pragma unroll
        for (int ni = 0; ni < 4; ni++) {
            int col = n0 + wn + 8 * ni + 2 * t;
            float bb0 = bias[col], bb1 = bias[col + 1];
            float2 v0 = make_float2(acc[mi][ni][0] + bb0, acc[mi][ni][1] + bb1);
            float2 v1 = make_float2(acc[mi][ni][2] + bb0, acc[mi][ni][3] + bb1);
            if (MODE == 0) {
                int h = col >> 6, d = col & 63;
                int b0r = r0 >> 11, s0 = r0 & 2047;
                int b1r = r1 >> 11, s1 = r1 & 2047;
                *(float2*)&out[(((size_t)(b0r * H_ + h) * S_ + s0) << 6) + d] = v0;
                *(float2*)&out[(((size_t)(b1r * H_ + h) * S_ + s1) << 6) + d] = v1;
            } else {
                *(float2*)&out[(size_t)r0 * HID_ + col] = v0;
                *(float2*)&out[(size_t)r1 * HID_ + col] = v1;
            }
        }
    }
}

__global__ __launch_bounds__(256, 2) void gemm_qkv(
    const float* __restrict__ Xq, const float* __restrict__ Xk, const float* __restrict__ Xv,
    const float* __restrict__ Wq, const float* __restrict__ Wk, const float* __restrict__ Wv,
    const float* __restrict__ bq, const float* __restrict__ bk, const float* __restrict__ bv,
    float* __restrict__ oq, float* __restrict__ ok, float* __restrict__ ov)
{
    __shared__ uint32_t Xs[128][36];
    __shared__ uint32_t Ws[32][136];
    const int z = blockIdx.z;
    const float* X    = (z == 0) ? Xq : (z == 1) ? Xk : Xv;
    const float* W    = (z == 0) ? Wq : (z == 1) ? Wk : Wv;
    const float* bias = (z == 0) ? bq : (z == 1) ? bk : bv;
    float* out        = (z == 0) ? oq : (z == 1) ? ok : ov;
    gemm_core<0>(X, W, bias, out, Xs, Ws, blockIdx.y * 128, blockIdx.x * 128);
}

__global__ __launch_bounds__(256, 2) void gemm_out(
    const float* __restrict__ X, const float* __restrict__ W,
    const float* __restrict__ bias, float* __restrict__ out)
{
    __shared__ uint32_t Xs[128][36];
    __shared__ uint32_t Ws[32][136];
    gemm_core<1>(X, W, bias, out, Xs, Ws, blockIdx.y * 128, blockIdx.x * 128);
}

// ---------------------------------------------------------------------------
// Fused attention, 64 q-rows per block, 3 CTAs/SM.
// 8 warps = 4 q-groups (16 rows) x 2 k/n-halves (32 wide).
// Pass 1: rowsum of masked exp(score) (no max subtraction; scores are O(1)).
// Pass 2: recompute scores, p = exp(s)*Sinv, write probs once, PV mma.
// Smem: Qs[64][68] Ks[64][68] Vs[64][72] Ps[64][76] Ssum[64][2] Sinv[64]
// ---------------------------------------------------------------------------
#define QP_ 68
#define VP_ 72
#define PP_ 76
#define Q_OFF 0
#define K_OFF (64 * QP_)
#define V_OFF (K_OFF + 64 * QP_)
#define P_OFF (V_OFF + 64 * VP_)
#define SS_OFF (P_OFF + 64 * PP_)
#define SI_OFF (SS_OFF + 128)
#define FUSED_WORDS (SI_OFF + 64)
#define FUSED_SMEM (FUSED_WORDS * 4)

__global__ __launch_bounds__(256, 3) void fused_attn(
    const float* __restrict__ qg, const float* __restrict__ kg,
    const float* __restrict__ vg, const uint32_t* __restrict__ bm,
    float* __restrict__ probs, float* __restrict__ ctx)
{
    extern __shared__ uint32_t sh[];
    uint32_t* Qs = sh + Q_OFF;
    uint32_t* Ks = sh + K_OFF;
    uint32_t* Vs = sh + V_OFF;
    uint32_t* Ps = sh + P_OFF;
    float* Ssum  = (float*)(sh + SS_OFF);   // [64][2]
    float* Sinv  = (float*)(sh + SI_OFF);   // [64]

    const int tid  = threadIdx.x;
    const int w    = tid >> 5;
    const int lane = tid & 31;
    const int g    = lane >> 2;
    const int t    = lane & 3;
    const int wq   = w >> 1;          // 0..3 q-group
    const int kh   = w & 1;           // 0..1 k/n half
    const int wr   = wq * 16;
    const int q0   = blockIdx.x * 64;
    const int bh   = blockIdx.y;
    const int bb   = bh / H_;
    const int h    = bh % H_;
    const float* qbase = qg + (size_t)bh * S_ * D_;
    const float* kbase = kg + (size_t)bh * S_ * D_;
    const float* vbase = vg + (size_t)bh * S_ * D_;

    const int lr0 = wr + g;           // local rows
    const int lr1 = lr0 + 8;
    const int r0  = q0 + lr0;         // global q rows
    const int r1  = q0 + lr1;
    const uint32_t* bm0 = bm + ((size_t)bb * S_ + r0) * 64 + kh;
    const uint32_t* bm1 = bm + ((size_t)bb * S_ + r1) * 64 + kh;

    // Load Q tile 64x64 (256 units: row = tid>>2, 16-col group = tid&3)
    {
        int r = tid >> 2, j = tid & 3;
        const float* src = qbase + (size_t)(q0 + r) * D_ + 16 * j;
        uint32_t* dst = &Qs[r * QP_ + 16 * j];
#pragma unroll
        for (int q = 0; q < 4; q++) {
            float4 v = *(const float4*)(src + 4 * q);
            *(uint4*)&dst[4 * q] = make_uint4(f2t(v.x), f2t(v.y), f2t(v.z), f2t(v.w));
        }
    }
    __syncthreads();

    float s0v = 0.f, s1v = 0.f;

    // ---------------- Pass 1: row sums ----------------
    for (int k0 = 0; k0 < S_; k0 += 64) {
        {
            int r = tid >> 2, j = tid & 3;
            const float* src = kbase + (size_t)(k0 + r) * D_ + 16 * j;
            uint32_t* dst = &Ks[r * QP_ + 16 * j];
#pragma unroll
            for (int q = 0; q < 4; q++) {
                float4 v = *(const float4*)(src + 4 * q);
                *(uint4*)&dst[4 * q] = make_uint4(f2t(v.x), f2t(v.y), f2t(v.z), f2t(v.w));
            }
        }
        __syncthreads();

        float acc[4][4];
#pragma unroll
        for (int ni = 0; ni < 4; ni++)
#pragma unroll
            for (int r = 0; r < 4; r++) acc[ni][r] = 0.f;

#pragma unroll
        for (int kk = 0; kk < 64; kk += 8) {
            uint32_t a0 = Qs[lr0 * QP_ + kk + t];
            uint32_t a1 = Qs[lr1 * QP_ + kk + t];
            uint32_t a2 = Qs[lr0 * QP_ + kk + t + 4];
            uint32_t a3 = Qs[lr1 * QP_ + kk + t + 4];
#pragma unroll
            for (int ni = 0; ni < 4; ni++) {
                int nr = kh * 32 + 8 * ni + g;
                uint32_t b0 = Ks[nr * QP_ + kk + t];
                uint32_t b1 = Ks[nr * QP_ + kk + t + 4];
                mma8(acc[ni], a0, a1, a2, a3, b0, b1);
            }
        }

        uint32_t w0 = bm0[k0 >> 5];
        uint32_t w1 = bm1[k0 >> 5];
#pragma unroll
        for (int ni = 0; ni < 4; ni++) {
            int bit = 8 * ni + 2 * t;
            float e00 = ((w0 >> bit) & 1)       ? 0.f : __expf(acc[ni][0] * SCALE_);
            float e01 = ((w0 >> (bit + 1)) & 1) ? 0.f : __expf(acc[ni][1] * SCALE_);
            float e10 = ((w1 >> bit) & 1)       ? 0.f : __expf(acc[ni][2] * SCALE_);
            float e11 = ((w1 >> (bit + 1)) & 1) ? 0.f : __expf(acc[ni][3] * SCALE_);
            s0v += e00 + e01;
            s1v += e10 + e11;
        }
        __syncthreads();
    }

    // Quad reduce and combine halves
    s0v += __shfl_xor_sync(0xffffffffu, s0v, 1);
    s0v += __shfl_xor_sync(0xffffffffu, s0v, 2);
    s1v += __shfl_xor_sync(0xffffffffu, s1v, 1);
    s1v += __shfl_xor_sync(0xffffffffu, s1v, 2);
    if (t == 0) {
        Ssum[lr0 * 2 + kh] = s0v;
        Ssum[lr1 * 2 + kh] = s1v;
    }
    __syncthreads();
    if (tid < 64)
        Sinv[tid] = 1.f / (Ssum[tid * 2] + Ssum[tid * 2 + 1]);
    __syncthreads();

    const float inv0 = Sinv[lr0];
    const float inv1 = Sinv[lr1];

    float accv[4][4];
#pragma unroll
    for (int ni = 0; ni < 4; ni++)
#pragma unroll
        for (int r = 0; r < 4; r++) accv[ni][r] = 0.f;

    float* pr0 = probs + ((size_t)bh * S_ + r0) * S_;
    float* pr1 = probs + ((size_t)bh * S_ + r1) * S_;

    // ---------------- Pass 2: probs + PV ----------------
    for (int k0 = 0; k0 < S_; k0 += 64) {
        {
            int r = tid >> 2, j = tid & 3;
            const float* ksrc = kbase + (size_t)(k0 + r) * D_ + 16 * j;
            const float* vsrc = vbase + (size_t)(k0 + r) * D_ + 16 * j;
            uint32_t* kdst = &Ks[r * QP_ + 16 * j];
            uint32_t* vdst = &Vs[r * VP_ + 16 * j];
#pragma unroll
            for (int q = 0; q < 4; q++) {
                float4 v = *(const float4*)(ksrc + 4 * q);
                *(uint4*)&kdst[4 * q] = make_uint4(f2t(v.x), f2t(v.y), f2t(v.z), f2t(v.w));
            }
#pragma unroll
            for (int q = 0; q < 4; q++) {
                float4 v = *(const float4*)(vsrc + 4 * q);
                *(uint4*)&vdst[4 * q] = make_uint4(f2t(v.x), f2t(v.y), f2t(v.z), f2t(v.w));
            }
        }
        __syncthreads();

        float acc[4][4];
#pragma unroll
        for (int ni = 0; ni < 4; ni++)
#pragma unroll
            for (int r = 0; r < 4; r++) acc[ni][r] = 0.f;

#pragma unroll
        for (int kk = 0; kk < 64; kk += 8) {
            uint32_t a0 = Qs[lr0 * QP_ + kk + t];
            uint32_t a1 = Qs[lr1 * QP_ + kk + t];
            uint32_t a2 = Qs[lr0 * QP_ + kk + t + 4];
            uint32_t a3 = Qs[lr1 * QP_ + kk + t + 4];
#pragma unroll
            for (int ni = 0; ni < 4; ni++) {
                int nr = kh * 32 + 8 * ni + g;
                uint32_t b0 = Ks[nr * QP_ + kk + t];
                uint32_t b1 = Ks[nr * QP_ + kk + t + 4];
                mma8(acc[ni], a0, a1, a2, a3, b0, b1);
            }
        }

        uint32_t w0 = bm0[k0 >> 5];
        uint32_t w1 = bm1[k0 >> 5];
#pragma unroll
        for (int ni = 0; ni < 4; ni++) {
            int bit = 8 * ni + 2 * t;
            float p00 = ((w0 >> bit) & 1)       ? 0.f : __expf(acc[ni][0] * SCALE_) * inv0;
            float p01 = ((w0 >> (bit + 1)) & 1) ? 0.f : __expf(acc[ni][1] * SCALE_) * inv0;
            float p10 = ((w1 >> bit) & 1)       ? 0.f : __expf(acc[ni][2] * SCALE_) * inv1;
            float p11 = ((w1 >> (bit + 1)) & 1) ? 0.f : __expf(acc[ni][3] * SCALE_) * inv1;
            int c = k0 + kh * 32 + 8 * ni + 2 * t;
            *(float2*)(pr0 + c) = make_float2(p00, p01);
            *(float2*)(pr1 + c) = make_float2(p10, p11);
            int cl = kh * 32 + 8 * ni + 2 * t;
            *(uint2*)&Ps[lr0 * PP_ + cl] = make_uint2(f2t(p00), f2t(p01));
            *(uint2*)&Ps[lr1 * PP_ + cl] = make_uint2(f2t(p10), f2t(p11));
        }
        __syncthreads();   // Ps complete (both halves of each row)

#pragma unroll
        for (int kk = 0; kk < 64; kk += 8) {
            uint32_t a0 = Ps[lr0 * PP_ + kk + t];
            uint32_t a1 = Ps[lr1 * PP_ + kk + t];
            uint32_t a2 = Ps[lr0 * PP_ + kk + t + 4];
            uint32_t a3 = Ps[lr1 * PP_ + kk + t + 4];
#pragma unroll
            for (int ni = 0; ni < 4; ni++) {
                int nc = kh * 32 + 8 * ni + g;
                uint32_t b0 = Vs[(kk + t) * VP_ + nc];
                uint32_t b1 = Vs[(kk + t + 4) * VP_ + nc];
                mma8(accv[ni], a0, a1, a2, a3, b0, b1);
            }
        }
        __syncthreads();   // done with Ks/Vs before next tile load
    }

    // Epilogue: ctx rows r0,r1, cols h*64 + kh*32 + 8ni + 2t
#pragma unroll
    for (int ni = 0; ni < 4; ni++) {
        int col = h * D_ + kh * 32 + 8 * ni + 2 * t;
        *(float2*)&ctx[((size_t)(bb * S_ + r0)) * HID_ + col] =
            make_float2(accv[ni][0], accv[ni][1]);
        *(float2*)&ctx[((size_t)(bb * S_ + r1)) * HID_ + col] =
            make_float2(accv[ni][2], accv[ni][3]);
    }
}

// ---------------------------------------------------------------------------
extern "C" void kernel_launch(void* const* d_in, const int* in_sizes, int n_in,
                              void* d_out, int out_size)
{
    (void)in_sizes; (void)n_in; (void)out_size;
    const float* Q  = (const float*)d_in[0];
    const float* K  = (const float*)d_in[1];
    const float* V  = (const float*)d_in[2];
    const int*   mask = (const int*)d_in[3];
    const float* Wq = (const float*)d_in[4];
    const float* bq = (const float*)d_in[5];
    const float* Wk = (const float*)d_in[6];
    const float* bk = (const float*)d_in[7];
    const float* Wv = (const float*)d_in[8];
    const float* bv = (const float*)d_in[9];
    const float* Wo = (const float*)d_in[10];
    const float* bo = (const float*)d_in[11];

    float* out   = (float*)d_out;
    float* probs = out + OUTE;

    float* scratch = nullptr;
    cudaGetSymbolAddress((void**)&scratch, g_scratch);
    uint32_t* bmp = nullptr;
    cudaGetSymbolAddress((void**)&bmp, g_bm);
    float* gq   = scratch;
    float* gk   = scratch + (size_t)OUTE;
    float* gv   = scratch + 2ull * OUTE;
    float* gctx = scratch + 3ull * OUTE;

    cudaFuncSetAttribute(fused_attn, cudaFuncAttributeMaxDynamicSharedMemorySize,
                         FUSED_SMEM);

    build_bitmask<<<2048, 256>>>(mask, bmp);
    gemm_qkv<<<dim3(HID_ / 128, MROWS / 128, 3), 256>>>(
        Q, K, V, Wq, Wk, Wv, bq, bk, bv, gq, gk, gv);
    fused_attn<<<dim3(S_ / 64, BH_), 256, FUSED_SMEM>>>(gq, gk, gv, bmp, probs, gctx);
    gemm_out<<<dim3(HID_ / 128, MROWS / 128), 256>>>(gctx, Wo, bo, out);
}

// round 8
// speedup vs baseline: 1.3406x; 1.3406x over previous
#include <cuda_runtime.h>
#include <cuda_fp16.h>
#include <stdint.h>
#include <stddef.h>

#define B_ 4
#define S_ 2048
#define HID_ 768
#define H_ 12
#define D_ 64
#define BH_ 48
#define MROWS 8192
#define OUTE 6291456
#define SCALE_ 0.125f

// Scratch: q, k, v (BHSD each) + context (row-major [8192,768])
__device__ float g_scratch[4ull * 6291456ull];
// Bitmask: [B][S][S/32]
__device__ uint32_t g_bm[524288];

// ---------------------------------------------------------------------------
__device__ __forceinline__ uint32_t ph2(float a, float b) {
    __half2 h = __floats2half2_rn(a, b);
    return *(uint32_t*)&h;
}

// m16n8k16 fp16 mma, fp32 accumulate
__device__ __forceinline__ void mma16(float* c,
    uint32_t a0, uint32_t a1, uint32_t a2, uint32_t a3,
    uint32_t b0, uint32_t b1)
{
    asm volatile(
        "mma.sync.aligned.m16n8k16.row.col.f32.f16.f16.f32 "
        "{%0,%1,%2,%3}, {%4,%5,%6,%7}, {%8,%9}, {%0,%1,%2,%3};"
        : "+f"(c[0]), "+f"(c[1]), "+f"(c[2]), "+f"(c[3])
        : "r"(a0), "r"(a1), "r"(a2), "r"(a3), "r"(b0), "r"(b1));
}

// ---------------------------------------------------------------------------
// Bitmask builder: mask int32 -> bits (1 = masked)
// ---------------------------------------------------------------------------
__global__ __launch_bounds__(256) void build_bitmask(
    const int* __restrict__ mask, uint32_t* __restrict__ bm)
{
    int idx = blockIdx.x * 256 + threadIdx.x;
    const int* p = mask + (size_t)idx * 32;
    uint32_t r = 0;
#pragma unroll
    for (int j = 0; j < 8; j++) {
        int4 v = *(const int4*)(p + 4 * j);
        r |= (v.x != 0 ? 1u : 0u) << (4 * j);
        r |= (v.y != 0 ? 1u : 0u) << (4 * j + 1);
        r |= (v.z != 0 ? 1u : 0u) << (4 * j + 2);
        r |= (v.w != 0 ? 1u : 0u) << (4 * j + 3);
    }
    bm[idx] = r;
}

// ---------------------------------------------------------------------------
// Projection GEMM fp16: C[8192,768] = X @ W + bias
// Block 128x128, BK=32, 8 warps (2x4), warp 64x32, m16n8k16.
// Xs: [128 m][16 k2] pitch 20 words (half2). Ws: [128 n][16 k2] pitch 20.
// ---------------------------------------------------------------------------
template <int MODE>
__device__ __forceinline__ void gemm_core(
    const float* __restrict__ X, const float* __restrict__ W,
    const float* __restrict__ bias, float* __restrict__ out,
    uint32_t* Xs, uint32_t* Ws, int m0, int n0)
{
    const int tid  = threadIdx.x;
    const int w    = tid >> 5;
    const int lane = tid & 31;
    const int g    = lane >> 2;
    const int t    = lane & 3;
    const int wm   = (w & 1) * 64;
    const int wn   = (w >> 1) * 32;

    float acc[4][4][4];
#pragma unroll
    for (int mi = 0; mi < 4; mi++)
#pragma unroll
        for (int ni = 0; ni < 4; ni++)
#pragma unroll
            for (int r = 0; r < 4; r++) acc[mi][ni][r] = 0.f;

    for (int k0 = 0; k0 < HID_; k0 += 32) {
        // X tile 128x32 -> half2 [row][k2], 256 units
        {
            int r = tid >> 1, j = tid & 1;
            const float* src = X + (size_t)(m0 + r) * HID_ + k0 + 16 * j;
            float4 v0 = *(const float4*)(src);
            float4 v1 = *(const float4*)(src + 4);
            float4 v2 = *(const float4*)(src + 8);
            float4 v3 = *(const float4*)(src + 12);
            uint32_t* dst = Xs + r * 20 + 8 * j;
            *(uint4*)(dst)     = make_uint4(ph2(v0.x, v0.y), ph2(v0.z, v0.w),
                                            ph2(v1.x, v1.y), ph2(v1.z, v1.w));
            *(uint4*)(dst + 4) = make_uint4(ph2(v2.x, v2.y), ph2(v2.z, v2.w),
                                            ph2(v3.x, v3.y), ph2(v3.z, v3.w));
        }
        // W tile 32x128 -> transposed half2 [n][k2], 512 units
#pragma unroll
        for (int i = 0; i < 2; i++) {
            int u = tid + 256 * i;
            int k2 = u & 15;          // 0..15
            int n4 = u >> 4;          // 0..31
            int n  = n0 + 4 * n4;
            const float* lo = W + (size_t)(k0 + 2 * k2) * HID_ + n;
            const float* hi = lo + HID_;
            float4 vl = *(const float4*)lo;
            float4 vh = *(const float4*)hi;
            Ws[(4 * n4 + 0) * 20 + k2] = ph2(vl.x, vh.x);
            Ws[(4 * n4 + 1) * 20 + k2] = ph2(vl.y, vh.y);
            Ws[(4 * n4 + 2) * 20 + k2] = ph2(vl.z, vh.z);
            Ws[(4 * n4 + 3) * 20 + k2] = ph2(vl.w, vh.w);
        }
        __syncthreads();

#pragma unroll
        for (int s = 0; s < 2; s++) {       // two k16 steps
            int s8 = s * 8;
            uint32_t a[4][4], b[4][2];
#pragma unroll
            for (int mi = 0; mi < 4; mi++) {
                int mr = wm + 16 * mi + g;
                a[mi][0] = Xs[mr * 20 + s8 + t];
                a[mi][1] = Xs[(mr + 8) * 20 + s8 + t];
                a[mi][2] = Xs[mr * 20 + s8 + t + 4];
                a[mi][3] = Xs[(mr + 8) * 20 + s8 + t + 4];
            }
#pragma unroll
            for (int ni = 0; ni < 4; ni++) {
                int nr = wn + 8 * ni + g;
                b[ni][0] = Ws[nr * 20 + s8 + t];
                b[ni][1] = Ws[nr * 20 + s8 + t + 4];
            }
#pragma unroll
            for (int mi = 0; mi < 4; mi++)
#pragma unroll
                for (int ni = 0; ni < 4; ni++)
                    mma16(acc[mi][ni], a[mi][0], a[mi][1], a[mi][2], a[mi][3],
                          b[ni][0], b[ni][1]);
        }
        __syncthreads();
    }

#pragma unroll
    for (int mi = 0; mi < 4; mi++) {
        int r0 = m0 + wm + 16 * mi + g;
        int r1 = r0 + 8;
#pragma unroll
        for (int ni = 0; ni < 4; ni++) {
            int col = n0 + wn + 8 * ni + 2 * t;
            float bb0 = bias[col], bb1 = bias[col + 1];
            float2 v0 = make_float2(acc[mi][ni][0] + bb0, acc[mi][ni][1] + bb1);
            float2 v1 = make_float2(acc[mi][ni][2] + bb0, acc[mi][ni][3] + bb1);
            if (MODE == 0) {
                int h = col >> 6, d = col & 63;
                int b0r = r0 >> 11, s0 = r0 & 2047;
                int b1r = r1 >> 11, s1 = r1 & 2047;
                *(float2*)&out[(((size_t)(b0r * H_ + h) * S_ + s0) << 6) + d] = v0;
                *(float2*)&out[(((size_t)(b1r * H_ + h) * S_ + s1) << 6) + d] = v1;
            } else {
                *(float2*)&out[(size_t)r0 * HID_ + col] = v0;
                *(float2*)&out[(size_t)r1 * HID_ + col] = v1;
            }
        }
    }
}

__global__ __launch_bounds__(256, 2) void gemm_qkv(
    const float* __restrict__ Xq, const float* __restrict__ Xk, const float* __restrict__ Xv,
    const float* __restrict__ Wq, const float* __restrict__ Wk, const float* __restrict__ Wv,
    const float* __restrict__ bq, const float* __restrict__ bk, const float* __restrict__ bv,
    float* __restrict__ oq, float* __restrict__ ok, float* __restrict__ ov)
{
    __shared__ uint32_t Xs[128 * 20];
    __shared__ uint32_t Ws[128 * 20];
    const int z = blockIdx.z;
    const float* X    = (z == 0) ? Xq : (z == 1) ? Xk : Xv;
    const float* W    = (z == 0) ? Wq : (z == 1) ? Wk : Wv;
    const float* bias = (z == 0) ? bq : (z == 1) ? bk : bv;
    float* out        = (z == 0) ? oq : (z == 1) ? ok : ov;
    gemm_core<0>(X, W, bias, out, Xs, Ws, blockIdx.y * 128, blockIdx.x * 128);
}

__global__ __launch_bounds__(256, 2) void gemm_out(
    const float* __restrict__ X, const float* __restrict__ W,
    const float* __restrict__ bias, float* __restrict__ out)
{
    __shared__ uint32_t Xs[128 * 20];
    __shared__ uint32_t Ws[128 * 20];
    gemm_core<1>(X, W, bias, out, Xs, Ws, blockIdx.y * 128, blockIdx.x * 128);
}

// ---------------------------------------------------------------------------
// Fused attention (R4 skeleton, fp16 mma, no-max softmax).
// Block = (128 q rows, bh). 8 warps, warp = 16 q rows x 64 k cols.
// Pass 1: rowsum of masked exp(score). Pass 2: recompute, p=exp*inv,
// write probs once, PV mma.
// Smem (half2 words): Qs[128][36] Ks[64][36] Vs[64][36](transposed) Ps[128][36]
// ---------------------------------------------------------------------------
#define FP_ 36
#define Q_OFF 0
#define K_OFF (128 * FP_)
#define V_OFF (K_OFF + 64 * FP_)
#define P_OFF (V_OFF + 64 * FP_)
#define FUSED_SMEM ((P_OFF + 128 * FP_) * 4)

__global__ __launch_bounds__(256, 2) void fused_attn(
    const float* __restrict__ qg, const float* __restrict__ kg,
    const float* __restrict__ vg, const uint32_t* __restrict__ bm,
    float* __restrict__ probs, float* __restrict__ ctx)
{
    extern __shared__ uint32_t sh[];
    uint32_t* Qs = sh + Q_OFF;
    uint32_t* Ks = sh + K_OFF;
    uint32_t* Vs = sh + V_OFF;
    uint32_t* Ps = sh + P_OFF;

    const int tid  = threadIdx.x;
    const int w    = tid >> 5;
    const int lane = tid & 31;
    const int g    = lane >> 2;
    const int t    = lane & 3;
    const int wr   = w * 16;
    const int q0   = blockIdx.x * 128;
    const int bh   = blockIdx.y;
    const int bb   = bh / H_;
    const int h    = bh % H_;
    const float* qbase = qg + (size_t)bh * S_ * D_;
    const float* kbase = kg + (size_t)bh * S_ * D_;
    const float* vbase = vg + (size_t)bh * S_ * D_;

    const int lr0 = wr + g;
    const int lr1 = lr0 + 8;
    const int r0  = q0 + lr0;
    const int r1  = q0 + lr1;
    const uint32_t* bm0 = bm + ((size_t)bb * S_ + r0) * 64;
    const uint32_t* bm1 = bm + ((size_t)bb * S_ + r1) * 64;

    // Q tile 128x64 -> half2 [row][k2], 256 units of (row, 32-float half)
    {
        int r = tid >> 1, j = tid & 1;
        const float* src = qbase + (size_t)(q0 + r) * D_ + 32 * j;
        uint32_t* dst = Qs + r * FP_ + 16 * j;
#pragma unroll
        for (int q = 0; q < 4; q++) {
            float4 v0 = *(const float4*)(src + 8 * q);
            float4 v1 = *(const float4*)(src + 8 * q + 4);
            *(uint4*)(dst + 4 * q) = make_uint4(ph2(v0.x, v0.y), ph2(v0.z, v0.w),
                                                ph2(v1.x, v1.y), ph2(v1.z, v1.w));
        }
    }
    __syncthreads();

    float s0v = 0.f, s1v = 0.f;

    // ---------------- Pass 1: row sums ----------------
    for (int k0 = 0; k0 < S_; k0 += 64) {
        // K tile 64x64 -> half2 [krow][k2]
        {
            int r = tid >> 2, j = tid & 3;
            const float* src = kbase + (size_t)(k0 + r) * D_ + 16 * j;
            float4 v0 = *(const float4*)(src);
            float4 v1 = *(const float4*)(src + 4);
            float4 v2 = *(const float4*)(src + 8);
            float4 v3 = *(const float4*)(src + 12);
            uint32_t* dst = Ks + r * FP_ + 8 * j;
            *(uint4*)(dst)     = make_uint4(ph2(v0.x, v0.y), ph2(v0.z, v0.w),
                                            ph2(v1.x, v1.y), ph2(v1.z, v1.w));
            *(uint4*)(dst + 4) = make_uint4(ph2(v2.x, v2.y), ph2(v2.z, v2.w),
                                            ph2(v3.x, v3.y), ph2(v3.z, v3.w));
        }
        __syncthreads();

        float acc[8][4];
#pragma unroll
        for (int ni = 0; ni < 8; ni++)
#pragma unroll
            for (int r = 0; r < 4; r++) acc[ni][r] = 0.f;

#pragma unroll
        for (int s = 0; s < 4; s++) {       // k16 steps over D=64
            int s8 = s * 8;
            uint32_t a0 = Qs[lr0 * FP_ + s8 + t];
            uint32_t a1 = Qs[lr1 * FP_ + s8 + t];
            uint32_t a2 = Qs[lr0 * FP_ + s8 + t + 4];
            uint32_t a3 = Qs[lr1 * FP_ + s8 + t + 4];
#pragma unroll
            for (int ni = 0; ni < 8; ni++) {
                int nr = 8 * ni + g;
                uint32_t b0 = Ks[nr * FP_ + s8 + t];
                uint32_t b1 = Ks[nr * FP_ + s8 + t + 4];
                mma16(acc[ni], a0, a1, a2, a3, b0, b1);
            }
        }

        uint2 w0 = *(const uint2*)(bm0 + (k0 >> 5));
        uint2 w1 = *(const uint2*)(bm1 + (k0 >> 5));
#pragma unroll
        for (int ni = 0; ni < 8; ni++) {
            uint32_t sel0 = (ni < 4) ? w0.x : w0.y;
            uint32_t sel1 = (ni < 4) ? w1.x : w1.y;
            int bit = (8 * ni + 2 * t) & 31;
            float e00 = ((sel0 >> bit) & 1)       ? 0.f : __expf(acc[ni][0] * SCALE_);
            float e01 = ((sel0 >> (bit + 1)) & 1) ? 0.f : __expf(acc[ni][1] * SCALE_);
            float e10 = ((sel1 >> bit) & 1)       ? 0.f : __expf(acc[ni][2] * SCALE_);
            float e11 = ((sel1 >> (bit + 1)) & 1) ? 0.f : __expf(acc[ni][3] * SCALE_);
            s0v += e00 + e01;
            s1v += e10 + e11;
        }
        __syncthreads();
    }

    // Quad reduce; all lanes get full row sums
    s0v += __shfl_xor_sync(0xffffffffu, s0v, 1);
    s0v += __shfl_xor_sync(0xffffffffu, s0v, 2);
    s1v += __shfl_xor_sync(0xffffffffu, s1v, 1);
    s1v += __shfl_xor_sync(0xffffffffu, s1v, 2);
    const float inv0 = 1.f / s0v;
    const float inv1 = 1.f / s1v;

    float accv[8][4];
#pragma unroll
    for (int ni = 0; ni < 8; ni++)
#pragma unroll
        for (int r = 0; r < 4; r++) accv[ni][r] = 0.f;

    float* pr0 = probs + ((size_t)bh * S_ + r0) * S_;
    float* pr1 = probs + ((size_t)bh * S_ + r1) * S_;

    // ---------------- Pass 2: probs + PV ----------------
    for (int k0 = 0; k0 < S_; k0 += 64) {
        // K tile
        {
            int r = tid >> 2, j = tid & 3;
            const float* src = kbase + (size_t)(k0 + r) * D_ + 16 * j;
            float4 v0 = *(const float4*)(src);
            float4 v1 = *(const float4*)(src + 4);
            float4 v2 = *(const float4*)(src + 8);
            float4 v3 = *(const float4*)(src + 12);
            uint32_t* dst = Ks + r * FP_ + 8 * j;
            *(uint4*)(dst)     = make_uint4(ph2(v0.x, v0.y), ph2(v0.z, v0.w),
                                            ph2(v1.x, v1.y), ph2(v1.z, v1.w));
            *(uint4*)(dst + 4) = make_uint4(ph2(v2.x, v2.y), ph2(v2.z, v2.w),
                                            ph2(v3.x, v3.y), ph2(v3.z, v3.w));
        }
        // V tile 64x64 -> TRANSPOSED half2 [d][k2]: pair = (V[2k2][d], V[2k2+1][d])
        {
            int k2 = tid & 31;            // k-pair index
            int d0 = (tid >> 5) * 8;      // 8 d's per warp
            const float* lo = vbase + (size_t)(k0 + 2 * k2) * D_ + d0;
            const float* hi = lo + D_;
            float4 l0 = *(const float4*)lo;
            float4 l1 = *(const float4*)(lo + 4);
            float4 h0 = *(const float4*)hi;
            float4 h1 = *(const float4*)(hi + 4);
            Vs[(d0 + 0) * FP_ + k2] = ph2(l0.x, h0.x);
            Vs[(d0 + 1) * FP_ + k2] = ph2(l0.y, h0.y);
            Vs[(d0 + 2) * FP_ + k2] = ph2(l0.z, h0.z);
            Vs[(d0 + 3) * FP_ + k2] = ph2(l0.w, h0.w);
            Vs[(d0 + 4) * FP_ + k2] = ph2(l1.x, h1.x);
            Vs[(d0 + 5) * FP_ + k2] = ph2(l1.y, h1.y);
            Vs[(d0 + 6) * FP_ + k2] = ph2(l1.z, h1.z);
            Vs[(d0 + 7) * FP_ + k2] = ph2(l1.w, h1.w);
        }
        __syncthreads();

        float acc[8][4];
#pragma unroll
        for (int ni = 0; ni < 8; ni++)
#pragma unroll
            for (int r = 0; r < 4; r++) acc[ni][r] = 0.f;

#pragma unroll
        for (int s = 0; s < 4; s++) {
            int s8 = s * 8;
            uint32_t a0 = Qs[lr0 * FP_ + s8 + t];
            uint32_t a1 = Qs[lr1 * FP_ + s8 + t];
            uint32_t a2 = Qs[lr0 * FP_ + s8 + t + 4];
            uint32_t a3 = Qs[lr1 * FP_ + s8 + t + 4];
#pragma unroll
            for (int ni = 0; ni < 8; ni++) {
                int nr = 8 * ni + g;
                uint32_t b0 = Ks[nr * FP_ + s8 + t];
                uint32_t b1 = Ks[nr * FP_ + s8 + t + 4];
                mma16(acc[ni], a0, a1, a2, a3, b0, b1);
            }
        }

        uint2 w0 = *(const uint2*)(bm0 + (k0 >> 5));
        uint2 w1 = *(const uint2*)(bm1 + (k0 >> 5));
#pragma unroll
        for (int ni = 0; ni < 8; ni++) {
            uint32_t sel0 = (ni < 4) ? w0.x : w0.y;
            uint32_t sel1 = (ni < 4) ? w1.x : w1.y;
            int bit = (8 * ni + 2 * t) & 31;
            float p00 = ((sel0 >> bit) & 1)       ? 0.f : __expf(acc[ni][0] * SCALE_) * inv0;
            float p01 = ((sel0 >> (bit + 1)) & 1) ? 0.f : __expf(acc[ni][1] * SCALE_) * inv0;
            float p10 = ((sel1 >> bit) & 1)       ? 0.f : __expf(acc[ni][2] * SCALE_) * inv1;
            float p11 = ((sel1 >> (bit + 1)) & 1) ? 0.f : __expf(acc[ni][3] * SCALE_) * inv1;
            int c = k0 + 8 * ni + 2 * t;
            *(float2*)(pr0 + c) = make_float2(p00, p01);
            *(float2*)(pr1 + c) = make_float2(p10, p11);
            int k2 = 4 * ni + t;          // pair (8ni+2t, 8ni+2t+1)
            Ps[lr0 * FP_ + k2] = ph2(p00, p01);
            Ps[lr1 * FP_ + k2] = ph2(p10, p11);
        }
        __syncwarp();

        // PV: A = Ps rows (this warp's 16 rows), B = Vs transposed
#pragma unroll
        for (int s = 0; s < 4; s++) {
            int s8 = s * 8;
            uint32_t a0 = Ps[lr0 * FP_ + s8 + t];
            uint32_t a1 = Ps[lr1 * FP_ + s8 + t];
            uint32_t a2 = Ps[lr0 * FP_ + s8 + t + 4];
            uint32_t a3 = Ps[lr1 * FP_ + s8 + t + 4];
#pragma unroll
            for (int ni = 0; ni < 8; ni++) {
                int nd = 8 * ni + g;
                uint32_t b0 = Vs[nd * FP_ + s8 + t];
                uint32_t b1 = Vs[nd * FP_ + s8 + t + 4];
                mma16(accv[ni], a0, a1, a2, a3, b0, b1);
            }
        }
        __syncthreads();
    }

    // Epilogue
#pragma unroll
    for (int ni = 0; ni < 8; ni++) {
        int col = h * D_ + 8 * ni + 2 * t;
        *(float2*)&ctx[((size_t)(bb * S_ + r0)) * HID_ + col] =
            make_float2(accv[ni][0], accv[ni][1]);
        *(float2*)&ctx[((size_t)(bb * S_ + r1)) * HID_ + col] =
            make_float2(accv[ni][2], accv[ni][3]);
    }
}

// ---------------------------------------------------------------------------
extern "C" void kernel_launch(void* const* d_in, const int* in_sizes, int n_in,
                              void* d_out, int out_size)
{
    (void)in_sizes; (void)n_in; (void)out_size;
    const float* Q  = (const float*)d_in[0];
    const float* K  = (const float*)d_in[1];
    const float* V  = (const float*)d_in[2];
    const int*   mask = (const int*)d_in[3];
    const float* Wq = (const float*)d_in[4];
    const float* bq = (const float*)d_in[5];
    const float* Wk = (const float*)d_in[6];
    const float* bk = (const float*)d_in[7];
    const float* Wv = (const float*)d_in[8];
    const float* bv = (const float*)d_in[9];
    const float* Wo = (const float*)d_in[10];
    const float* bo = (const float*)d_in[11];

    float* out   = (float*)d_out;
    float* probs = out + OUTE;

    float* scratch = nullptr;
    cudaGetSymbolAddress((void**)&scratch, g_scratch);
    uint32_t* bmp = nullptr;
    cudaGetSymbolAddress((void**)&bmp, g_bm);
    float* gq   = scratch;
    float* gk   = scratch + (size_t)OUTE;
    float* gv   = scratch + 2ull * OUTE;
    float* gctx = scratch + 3ull * OUTE;

    cudaFuncSetAttribute(fused_attn, cudaFuncAttributeMaxDynamicSharedMemorySize,
                         FUSED_SMEM);

    build_bitmask<<<2048, 256>>>(mask, bmp);
    gemm_qkv<<<dim3(HID_ / 128, MROWS / 128, 3), 256>>>(
        Q, K, V, Wq, Wk, Wv, bq, bk, bv, gq, gk, gv);
    fused_attn<<<dim3(S_ / 128, BH_), 256, FUSED_SMEM>>>(gq, gk, gv, bmp, probs, gctx);
    gemm_out<<<dim3(HID_ / 128, MROWS / 128), 256>>>(gctx, Wo, bo, out);
}

// round 9
// speedup vs baseline: 1.7055x; 1.2722x over previous
#include <cuda_runtime.h>
#include <cuda_fp16.h>
#include <stdint.h>
#include <stddef.h>

#define B_ 4
#define S_ 2048
#define HID_ 768
#define H_ 12
#define D_ 64
#define BH_ 48
#define MROWS 8192
#define OUTE 6291456
#define SCALE_ 0.125f

// Scratch: q,k,v as half (1.5*OUTE floats) + ctx fp32 (OUTE floats)
__device__ float g_scratch[3ull * 6291456ull];
// Bitmask: [B][S][S/32]
__device__ uint32_t g_bm[524288];

// ---------------------------------------------------------------------------
__device__ __forceinline__ uint32_t f2t(float f) {
    uint32_t r;
    asm("cvt.rna.tf32.f32 %0, %1;" : "=r"(r) : "f"(f));
    return r;
}
__device__ __forceinline__ uint32_t ph2(float a, float b) {
    __half2 h = __floats2half2_rn(a, b);
    return *(uint32_t*)&h;
}
__device__ __forceinline__ uint32_t h2u(__half2 h) { return *(uint32_t*)&h; }

// tf32 m16n8k8
__device__ __forceinline__ void mma8(float* c,
    uint32_t a0, uint32_t a1, uint32_t a2, uint32_t a3,
    uint32_t b0, uint32_t b1)
{
    asm volatile(
        "mma.sync.aligned.m16n8k8.row.col.f32.tf32.tf32.f32 "
        "{%0,%1,%2,%3}, {%4,%5,%6,%7}, {%8,%9}, {%0,%1,%2,%3};"
        : "+f"(c[0]), "+f"(c[1]), "+f"(c[2]), "+f"(c[3])
        : "r"(a0), "r"(a1), "r"(a2), "r"(a3), "r"(b0), "r"(b1));
}
// fp16 m16n8k16
__device__ __forceinline__ void mma16(float* c,
    uint32_t a0, uint32_t a1, uint32_t a2, uint32_t a3,
    uint32_t b0, uint32_t b1)
{
    asm volatile(
        "mma.sync.aligned.m16n8k16.row.col.f32.f16.f16.f32 "
        "{%0,%1,%2,%3}, {%4,%5,%6,%7}, {%8,%9}, {%0,%1,%2,%3};"
        : "+f"(c[0]), "+f"(c[1]), "+f"(c[2]), "+f"(c[3])
        : "r"(a0), "r"(a1), "r"(a2), "r"(a3), "r"(b0), "r"(b1));
}

// ---------------------------------------------------------------------------
// Bitmask builder
// ---------------------------------------------------------------------------
__global__ __launch_bounds__(256) void build_bitmask(
    const int* __restrict__ mask, uint32_t* __restrict__ bm)
{
    int idx = blockIdx.x * 256 + threadIdx.x;
    const int* p = mask + (size_t)idx * 32;
    uint32_t r = 0;
#pragma unroll
    for (int j = 0; j < 8; j++) {
        int4 v = *(const int4*)(p + 4 * j);
        r |= (v.x != 0 ? 1u : 0u) << (4 * j);
        r |= (v.y != 0 ? 1u : 0u) << (4 * j + 1);
        r |= (v.z != 0 ? 1u : 0u) << (4 * j + 2);
        r |= (v.w != 0 ? 1u : 0u) << (4 * j + 3);
    }
    bm[idx] = r;
}

// ---------------------------------------------------------------------------
// Projection GEMMs: R4 tf32 core (proven fastest).
// MODE 0: write __half, scatter to BHSD. MODE 1: write float row-major.
// ---------------------------------------------------------------------------
template <int MODE>
__device__ __forceinline__ void gemm_core(
    const float* __restrict__ X, const float* __restrict__ W,
    const float* __restrict__ bias, void* __restrict__ outp,
    uint32_t (*Xs)[36], uint32_t (*Ws)[136], int m0, int n0)
{
    const int tid  = threadIdx.x;
    const int w    = tid >> 5;
    const int lane = tid & 31;
    const int g    = lane >> 2;
    const int t    = lane & 3;
    const int wm   = (w & 1) * 64;
    const int wn   = (w >> 1) * 32;

    float acc[4][4][4];
#pragma unroll
    for (int mi = 0; mi < 4; mi++)
#pragma unroll
        for (int ni = 0; ni < 4; ni++)
#pragma unroll
            for (int r = 0; r < 4; r++) acc[mi][ni][r] = 0.f;

    for (int k0 = 0; k0 < HID_; k0 += 32) {
#pragma unroll
        for (int i = 0; i < 4; i++) {
            int f = tid + 256 * i;
            int r = f >> 3, q = f & 7;
            float4 v = *(const float4*)(X + (size_t)(m0 + r) * HID_ + k0 + q * 4);
            *(uint4*)&Xs[r][q * 4] = make_uint4(f2t(v.x), f2t(v.y), f2t(v.z), f2t(v.w));
        }
#pragma unroll
        for (int i = 0; i < 4; i++) {
            int f = tid + 256 * i;
            int r = f >> 5, q = f & 31;
            float4 v = *(const float4*)(W + (size_t)(k0 + r) * HID_ + n0 + q * 4);
            *(uint4*)&Ws[r][q * 4] = make_uint4(f2t(v.x), f2t(v.y), f2t(v.z), f2t(v.w));
        }
        __syncthreads();
#pragma unroll
        for (int kk = 0; kk < 32; kk += 8) {
            uint32_t a[4][4], b[4][2];
#pragma unroll
            for (int mi = 0; mi < 4; mi++) {
                int mr = wm + 16 * mi + g;
                a[mi][0] = Xs[mr][kk + t];     a[mi][1] = Xs[mr + 8][kk + t];
                a[mi][2] = Xs[mr][kk + t + 4]; a[mi][3] = Xs[mr + 8][kk + t + 4];
            }
#pragma unroll
            for (int ni = 0; ni < 4; ni++) {
                b[ni][0] = Ws[kk + t][wn + 8 * ni + g];
                b[ni][1] = Ws[kk + t + 4][wn + 8 * ni + g];
            }
#pragma unroll
            for (int mi = 0; mi < 4; mi++)
#pragma unroll
                for (int ni = 0; ni < 4; ni++)
                    mma8(acc[mi][ni], a[mi][0], a[mi][1], a[mi][2], a[mi][3],
                         b[ni][0], b[ni][1]);
        }
        __syncthreads();
    }

#pragma unroll
    for (int mi = 0; mi < 4; mi++) {
        int r0 = m0 + wm + 16 * mi + g;
        int r1 = r0 + 8;
#pragma unroll
        for (int ni = 0; ni < 4; ni++) {
            int col = n0 + wn + 8 * ni + 2 * t;
            float bb0 = bias[col], bb1 = bias[col + 1];
            float c00 = acc[mi][ni][0] + bb0, c01 = acc[mi][ni][1] + bb1;
            float c10 = acc[mi][ni][2] + bb0, c11 = acc[mi][ni][3] + bb1;
            if (MODE == 0) {
                __half* outh = (__half*)outp;
                int h = col >> 6, d = col & 63;
                int b0r = r0 >> 11, s0 = r0 & 2047;
                int b1r = r1 >> 11, s1 = r1 & 2047;
                *(uint32_t*)&outh[(((size_t)(b0r * H_ + h) * S_ + s0) << 6) + d] = ph2(c00, c01);
                *(uint32_t*)&outh[(((size_t)(b1r * H_ + h) * S_ + s1) << 6) + d] = ph2(c10, c11);
            } else {
                float* outf = (float*)outp;
                *(float2*)&outf[(size_t)r0 * HID_ + col] = make_float2(c00, c01);
                *(float2*)&outf[(size_t)r1 * HID_ + col] = make_float2(c10, c11);
            }
        }
    }
}

__global__ __launch_bounds__(256, 2) void gemm_qkv(
    const float* __restrict__ Xq, const float* __restrict__ Xk, const float* __restrict__ Xv,
    const float* __restrict__ Wq, const float* __restrict__ Wk, const float* __restrict__ Wv,
    const float* __restrict__ bq, const float* __restrict__ bk, const float* __restrict__ bv,
    __half* __restrict__ oq, __half* __restrict__ ok, __half* __restrict__ ov)
{
    __shared__ uint32_t Xs[128][36];
    __shared__ uint32_t Ws[32][136];
    const int z = blockIdx.z;
    const float* X    = (z == 0) ? Xq : (z == 1) ? Xk : Xv;
    const float* W    = (z == 0) ? Wq : (z == 1) ? Wk : Wv;
    const float* bias = (z == 0) ? bq : (z == 1) ? bk : bv;
    __half* out       = (z == 0) ? oq : (z == 1) ? ok : ov;
    gemm_core<0>(X, W, bias, out, Xs, Ws, blockIdx.y * 128, blockIdx.x * 128);
}

__global__ __launch_bounds__(256, 2) void gemm_out(
    const float* __restrict__ X, const float* __restrict__ W,
    const float* __restrict__ bias, float* __restrict__ out)
{
    __shared__ uint32_t Xs[128][36];
    __shared__ uint32_t Ws[32][136];
    gemm_core<1>(X, W, bias, out, Xs, Ws, blockIdx.y * 128, blockIdx.x * 128);
}

// ---------------------------------------------------------------------------
// Fused attention (R8 structure): fp16 inputs, fp16 mma, no-max softmax.
// Smem (words): Qs[128][36] Ks[64][36] Vs[64][36](transposed) Ps[128][36]
// ---------------------------------------------------------------------------
#define FP_ 36
#define Q_OFF 0
#define K_OFF (128 * FP_)
#define V_OFF (K_OFF + 64 * FP_)
#define P_OFF (V_OFF + 64 * FP_)
#define FUSED_SMEM ((P_OFF + 128 * FP_) * 4)

__global__ __launch_bounds__(256, 2) void fused_attn(
    const __half* __restrict__ qg, const __half* __restrict__ kg,
    const __half* __restrict__ vg, const uint32_t* __restrict__ bm,
    float* __restrict__ probs, float* __restrict__ ctx)
{
    extern __shared__ uint32_t sh[];
    uint32_t* Qs = sh + Q_OFF;
    uint32_t* Ks = sh + K_OFF;
    uint32_t* Vs = sh + V_OFF;
    uint32_t* Ps = sh + P_OFF;

    const int tid  = threadIdx.x;
    const int w    = tid >> 5;
    const int lane = tid & 31;
    const int g    = lane >> 2;
    const int t    = lane & 3;
    const int wr   = w * 16;
    const int q0   = blockIdx.x * 128;
    const int bh   = blockIdx.y;
    const int bb   = bh / H_;
    const int h    = bh % H_;
    const __half* qbase = qg + (size_t)bh * S_ * D_;
    const __half* kbase = kg + (size_t)bh * S_ * D_;
    const __half* vbase = vg + (size_t)bh * S_ * D_;

    const int lr0 = wr + g;
    const int lr1 = lr0 + 8;
    const int r0  = q0 + lr0;
    const int r1  = q0 + lr1;
    const uint32_t* bm0 = bm + ((size_t)bb * S_ + r0) * 64;
    const uint32_t* bm1 = bm + ((size_t)bb * S_ + r1) * 64;

    // Q tile 128 rows x 64 halves: 1024 16B-chunks, 4/thread.
#pragma unroll
    for (int i = 0; i < 4; i++) {
        int u = tid + 256 * i;
        int r = u >> 3, c = u & 7;          // 8 chunks per row
        uint4 v = *(const uint4*)(qbase + (size_t)(q0 + r) * D_ + c * 8);
        *(uint4*)&Qs[r * FP_ + c * 4] = v;
    }
    __syncthreads();

    float s0v = 0.f, s1v = 0.f;

    // ---------------- Pass 1: row sums ----------------
    for (int k0 = 0; k0 < S_; k0 += 64) {
        // K tile 64x64 halves: 512 chunks, 2/thread
#pragma unroll
        for (int i = 0; i < 2; i++) {
            int u = tid + 256 * i;
            int r = u >> 3, c = u & 7;
            uint4 v = *(const uint4*)(kbase + (size_t)(k0 + r) * D_ + c * 8);
            *(uint4*)&Ks[r * FP_ + c * 4] = v;
        }
        __syncthreads();

        float acc[8][4];
#pragma unroll
        for (int ni = 0; ni < 8; ni++)
#pragma unroll
            for (int r = 0; r < 4; r++) acc[ni][r] = 0.f;

#pragma unroll
        for (int s = 0; s < 4; s++) {
            int s8 = s * 8;
            uint32_t a0 = Qs[lr0 * FP_ + s8 + t];
            uint32_t a1 = Qs[lr1 * FP_ + s8 + t];
            uint32_t a2 = Qs[lr0 * FP_ + s8 + t + 4];
            uint32_t a3 = Qs[lr1 * FP_ + s8 + t + 4];
#pragma unroll
            for (int ni = 0; ni < 8; ni++) {
                int nr = 8 * ni + g;
                uint32_t b0 = Ks[nr * FP_ + s8 + t];
                uint32_t b1 = Ks[nr * FP_ + s8 + t + 4];
                mma16(acc[ni], a0, a1, a2, a3, b0, b1);
            }
        }

        uint2 w0 = *(const uint2*)(bm0 + (k0 >> 5));
        uint2 w1 = *(const uint2*)(bm1 + (k0 >> 5));
#pragma unroll
        for (int ni = 0; ni < 8; ni++) {
            uint32_t sel0 = (ni < 4) ? w0.x : w0.y;
            uint32_t sel1 = (ni < 4) ? w1.x : w1.y;
            int bit = (8 * ni + 2 * t) & 31;
            float e00 = ((sel0 >> bit) & 1)       ? 0.f : __expf(acc[ni][0] * SCALE_);
            float e01 = ((sel0 >> (bit + 1)) & 1) ? 0.f : __expf(acc[ni][1] * SCALE_);
            float e10 = ((sel1 >> bit) & 1)       ? 0.f : __expf(acc[ni][2] * SCALE_);
            float e11 = ((sel1 >> (bit + 1)) & 1) ? 0.f : __expf(acc[ni][3] * SCALE_);
            s0v += e00 + e01;
            s1v += e10 + e11;
        }
        __syncthreads();
    }

    s0v += __shfl_xor_sync(0xffffffffu, s0v, 1);
    s0v += __shfl_xor_sync(0xffffffffu, s0v, 2);
    s1v += __shfl_xor_sync(0xffffffffu, s1v, 1);
    s1v += __shfl_xor_sync(0xffffffffu, s1v, 2);
    const float inv0 = 1.f / s0v;
    const float inv1 = 1.f / s1v;

    float accv[8][4];
#pragma unroll
    for (int ni = 0; ni < 8; ni++)
#pragma unroll
        for (int r = 0; r < 4; r++) accv[ni][r] = 0.f;

    float* pr0 = probs + ((size_t)bh * S_ + r0) * S_;
    float* pr1 = probs + ((size_t)bh * S_ + r1) * S_;

    // ---------------- Pass 2: probs + PV ----------------
    for (int k0 = 0; k0 < S_; k0 += 64) {
#pragma unroll
        for (int i = 0; i < 2; i++) {
            int u = tid + 256 * i;
            int r = u >> 3, c = u & 7;
            uint4 v = *(const uint4*)(kbase + (size_t)(k0 + r) * D_ + c * 8);
            *(uint4*)&Ks[r * FP_ + c * 4] = v;
        }
        // V tile 64x64 -> transposed [d][k2] via half-interleave (no cvt)
        {
            int k2 = tid & 31;
            int d0 = (tid >> 5) * 8;
            const __half* lo = vbase + (size_t)(k0 + 2 * k2) * D_ + d0;
            const __half* hi = lo + D_;
            __half2 l[4], h[4];
            *(uint4*)l = *(const uint4*)lo;
            *(uint4*)h = *(const uint4*)hi;
#pragma unroll
            for (int j = 0; j < 4; j++) {
                Vs[(d0 + 2 * j) * FP_ + k2]     = h2u(__lows2half2(l[j], h[j]));
                Vs[(d0 + 2 * j + 1) * FP_ + k2] = h2u(__highs2half2(l[j], h[j]));
            }
        }
        __syncthreads();

        float acc[8][4];
#pragma unroll
        for (int ni = 0; ni < 8; ni++)
#pragma unroll
            for (int r = 0; r < 4; r++) acc[ni][r] = 0.f;

#pragma unroll
        for (int s = 0; s < 4; s++) {
            int s8 = s * 8;
            uint32_t a0 = Qs[lr0 * FP_ + s8 + t];
            uint32_t a1 = Qs[lr1 * FP_ + s8 + t];
            uint32_t a2 = Qs[lr0 * FP_ + s8 + t + 4];
            uint32_t a3 = Qs[lr1 * FP_ + s8 + t + 4];
#pragma unroll
            for (int ni = 0; ni < 8; ni++) {
                int nr = 8 * ni + g;
                uint32_t b0 = Ks[nr * FP_ + s8 + t];
                uint32_t b1 = Ks[nr * FP_ + s8 + t + 4];
                mma16(acc[ni], a0, a1, a2, a3, b0, b1);
            }
        }

        uint2 w0 = *(const uint2*)(bm0 + (k0 >> 5));
        uint2 w1 = *(const uint2*)(bm1 + (k0 >> 5));
#pragma unroll
        for (int ni = 0; ni < 8; ni++) {
            uint32_t sel0 = (ni < 4) ? w0.x : w0.y;
            uint32_t sel1 = (ni < 4) ? w1.x : w1.y;
            int bit = (8 * ni + 2 * t) & 31;
            float p00 = ((sel0 >> bit) & 1)       ? 0.f : __expf(acc[ni][0] * SCALE_) * inv0;
            float p01 = ((sel0 >> (bit + 1)) & 1) ? 0.f : __expf(acc[ni][1] * SCALE_) * inv0;
            float p10 = ((sel1 >> bit) & 1)       ? 0.f : __expf(acc[ni][2] * SCALE_) * inv1;
            float p11 = ((sel1 >> (bit + 1)) & 1) ? 0.f : __expf(acc[ni][3] * SCALE_) * inv1;
            int c = k0 + 8 * ni + 2 * t;
            *(float2*)(pr0 + c) = make_float2(p00, p01);
            *(float2*)(pr1 + c) = make_float2(p10, p11);
            int k2 = 4 * ni + t;
            Ps[lr0 * FP_ + k2] = ph2(p00, p01);
            Ps[lr1 * FP_ + k2] = ph2(p10, p11);
        }
        __syncwarp();

#pragma unroll
        for (int s = 0; s < 4; s++) {
            int s8 = s * 8;
            uint32_t a0 = Ps[lr0 * FP_ + s8 + t];
            uint32_t a1 = Ps[lr1 * FP_ + s8 + t];
            uint32_t a2 = Ps[lr0 * FP_ + s8 + t + 4];
            uint32_t a3 = Ps[lr1 * FP_ + s8 + t + 4];
#pragma unroll
            for (int ni = 0; ni < 8; ni++) {
                int nd = 8 * ni + g;
                uint32_t b0 = Vs[nd * FP_ + s8 + t];
                uint32_t b1 = Vs[nd * FP_ + s8 + t + 4];
                mma16(accv[ni], a0, a1, a2, a3, b0, b1);
            }
        }
        __syncthreads();
    }

#pragma unroll
    for (int ni = 0; ni < 8; ni++) {
        int col = h * D_ + 8 * ni + 2 * t;
        *(float2*)&ctx[((size_t)(bb * S_ + r0)) * HID_ + col] =
            make_float2(accv[ni][0], accv[ni][1]);
        *(float2*)&ctx[((size_t)(bb * S_ + r1)) * HID_ + col] =
            make_float2(accv[ni][2], accv[ni][3]);
    }
}

// ---------------------------------------------------------------------------
extern "C" void kernel_launch(void* const* d_in, const int* in_sizes, int n_in,
                              void* d_out, int out_size)
{
    (void)in_sizes; (void)n_in; (void)out_size;
    const float* Q  = (const float*)d_in[0];
    const float* K  = (const float*)d_in[1];
    const float* V  = (const float*)d_in[2];
    const int*   mask = (const int*)d_in[3];
    const float* Wq = (const float*)d_in[4];
    const float* bq = (const float*)d_in[5];
    const float* Wk = (const float*)d_in[6];
    const float* bk = (const float*)d_in[7];
    const float* Wv = (const float*)d_in[8];
    const float* bv = (const float*)d_in[9];
    const float* Wo = (const float*)d_in[10];
    const float* bo = (const float*)d_in[11];

    float* out   = (float*)d_out;
    float* probs = out + OUTE;

    float* scratch = nullptr;
    cudaGetSymbolAddress((void**)&scratch, g_scratch);
    uint32_t* bmp = nullptr;
    cudaGetSymbolAddress((void**)&bmp, g_bm);

    __half* gq = (__half*)scratch;            // OUTE halves
    __half* gk = gq + (size_t)OUTE;
    __half* gv = gk + (size_t)OUTE;           // ends at 1.5*OUTE floats
    float* gctx = scratch + 2ull * OUTE;      // fp32 context

    cudaFuncSetAttribute(fused_attn, cudaFuncAttributeMaxDynamicSharedMemorySize,
                         FUSED_SMEM);

    build_bitmask<<<2048, 256>>>(mask, bmp);
    gemm_qkv<<<dim3(HID_ / 128, MROWS / 128, 3), 256>>>(
        Q, K, V, Wq, Wk, Wv, bq, bk, bv, gq, gk, gv);
    fused_attn<<<dim3(S_ / 128, BH_), 256, FUSED_SMEM>>>(gq, gk, gv, bmp, probs, gctx);
    gemm_out<<<dim3(HID_ / 128, MROWS / 128), 256>>>(gctx, Wo, bo, out);
}

// round 10
// speedup vs baseline: 1.7552x; 1.0291x over previous
#include <cuda_runtime.h>
#include <cuda_fp16.h>
#include <stdint.h>
#include <stddef.h>

#define B_ 4
#define S_ 2048
#define HID_ 768
#define H_ 12
#define D_ 64
#define BH_ 48
#define MROWS 8192
#define OUTE 6291456
#define SCALE_ 0.125f

// Scratch: q,k,v as half (1.5*OUTE floats) + ctx fp32 (OUTE floats)
__device__ float g_scratch[3ull * 6291456ull];
// Bitmask: [B][S][S/32]
__device__ uint32_t g_bm[524288];

// ---------------------------------------------------------------------------
__device__ __forceinline__ uint32_t f2t(float f) {
    uint32_t r;
    asm("cvt.rna.tf32.f32 %0, %1;" : "=r"(r) : "f"(f));
    return r;
}
__device__ __forceinline__ uint32_t ph2(float a, float b) {
    __half2 h = __floats2half2_rn(a, b);
    return *(uint32_t*)&h;
}
__device__ __forceinline__ uint32_t h2u(__half2 h) { return *(uint32_t*)&h; }

// tf32 m16n8k8
__device__ __forceinline__ void mma8(float* c,
    uint32_t a0, uint32_t a1, uint32_t a2, uint32_t a3,
    uint32_t b0, uint32_t b1)
{
    asm volatile(
        "mma.sync.aligned.m16n8k8.row.col.f32.tf32.tf32.f32 "
        "{%0,%1,%2,%3}, {%4,%5,%6,%7}, {%8,%9}, {%0,%1,%2,%3};"
        : "+f"(c[0]), "+f"(c[1]), "+f"(c[2]), "+f"(c[3])
        : "r"(a0), "r"(a1), "r"(a2), "r"(a3), "r"(b0), "r"(b1));
}
// fp16 m16n8k16
__device__ __forceinline__ void mma16(float* c,
    uint32_t a0, uint32_t a1, uint32_t a2, uint32_t a3,
    uint32_t b0, uint32_t b1)
{
    asm volatile(
        "mma.sync.aligned.m16n8k16.row.col.f32.f16.f16.f32 "
        "{%0,%1,%2,%3}, {%4,%5,%6,%7}, {%8,%9}, {%0,%1,%2,%3};"
        : "+f"(c[0]), "+f"(c[1]), "+f"(c[2]), "+f"(c[3])
        : "r"(a0), "r"(a1), "r"(a2), "r"(a3), "r"(b0), "r"(b1));
}
// ldmatrix x4
__device__ __forceinline__ void ldsm4(uint32_t& r0, uint32_t& r1,
                                      uint32_t& r2, uint32_t& r3, uint32_t saddr)
{
    asm volatile("ldmatrix.sync.aligned.m8n8.x4.shared.b16 {%0,%1,%2,%3}, [%4];"
        : "=r"(r0), "=r"(r1), "=r"(r2), "=r"(r3) : "r"(saddr));
}

// ---------------------------------------------------------------------------
// Bitmask builder
// ---------------------------------------------------------------------------
__global__ __launch_bounds__(256) void build_bitmask(
    const int* __restrict__ mask, uint32_t* __restrict__ bm)
{
    int idx = blockIdx.x * 256 + threadIdx.x;
    const int* p = mask + (size_t)idx * 32;
    uint32_t r = 0;
#pragma unroll
    for (int j = 0; j < 8; j++) {
        int4 v = *(const int4*)(p + 4 * j);
        r |= (v.x != 0 ? 1u : 0u) << (4 * j);
        r |= (v.y != 0 ? 1u : 0u) << (4 * j + 1);
        r |= (v.z != 0 ? 1u : 0u) << (4 * j + 2);
        r |= (v.w != 0 ? 1u : 0u) << (4 * j + 3);
    }
    bm[idx] = r;
}

// ---------------------------------------------------------------------------
// Projection GEMMs: R4 tf32 core.
// MODE 0: write __half, scatter to BHSD. MODE 1: write float row-major.
// ---------------------------------------------------------------------------
template <int MODE>
__device__ __forceinline__ void gemm_core(
    const float* __restrict__ X, const float* __restrict__ W,
    const float* __restrict__ bias, void* __restrict__ outp,
    uint32_t (*Xs)[36], uint32_t (*Ws)[136], int m0, int n0)
{
    const int tid  = threadIdx.x;
    const int w    = tid >> 5;
    const int lane = tid & 31;
    const int g    = lane >> 2;
    const int t    = lane & 3;
    const int wm   = (w & 1) * 64;
    const int wn   = (w >> 1) * 32;

    float acc[4][4][4];
#pragma unroll
    for (int mi = 0; mi < 4; mi++)
#pragma unroll
        for (int ni = 0; ni < 4; ni++)
#pragma unroll
            for (int r = 0; r < 4; r++) acc[mi][ni][r] = 0.f;

    for (int k0 = 0; k0 < HID_; k0 += 32) {
#pragma unroll
        for (int i = 0; i < 4; i++) {
            int f = tid + 256 * i;
            int r = f >> 3, q = f & 7;
            float4 v = *(const float4*)(X + (size_t)(m0 + r) * HID_ + k0 + q * 4);
            *(uint4*)&Xs[r][q * 4] = make_uint4(f2t(v.x), f2t(v.y), f2t(v.z), f2t(v.w));
        }
#pragma unroll
        for (int i = 0; i < 4; i++) {
            int f = tid + 256 * i;
            int r = f >> 5, q = f & 31;
            float4 v = *(const float4*)(W + (size_t)(k0 + r) * HID_ + n0 + q * 4);
            *(uint4*)&Ws[r][q * 4] = make_uint4(f2t(v.x), f2t(v.y), f2t(v.z), f2t(v.w));
        }
        __syncthreads();
#pragma unroll
        for (int kk = 0; kk < 32; kk += 8) {
            uint32_t a[4][4], b[4][2];
#pragma unroll
            for (int mi = 0; mi < 4; mi++) {
                int mr = wm + 16 * mi + g;
                a[mi][0] = Xs[mr][kk + t];     a[mi][1] = Xs[mr + 8][kk + t];
                a[mi][2] = Xs[mr][kk + t + 4]; a[mi][3] = Xs[mr + 8][kk + t + 4];
            }
#pragma unroll
            for (int ni = 0; ni < 4; ni++) {
                b[ni][0] = Ws[kk + t][wn + 8 * ni + g];
                b[ni][1] = Ws[kk + t + 4][wn + 8 * ni + g];
            }
#pragma unroll
            for (int mi = 0; mi < 4; mi++)
#pragma unroll
                for (int ni = 0; ni < 4; ni++)
                    mma8(acc[mi][ni], a[mi][0], a[mi][1], a[mi][2], a[mi][3],
                         b[ni][0], b[ni][1]);
        }
        __syncthreads();
    }

#pragma unroll
    for (int mi = 0; mi < 4; mi++) {
        int r0 = m0 + wm + 16 * mi + g;
        int r1 = r0 + 8;
#pragma unroll
        for (int ni = 0; ni < 4; ni++) {
            int col = n0 + wn + 8 * ni + 2 * t;
            float bb0 = bias[col], bb1 = bias[col + 1];
            float c00 = acc[mi][ni][0] + bb0, c01 = acc[mi][ni][1] + bb1;
            float c10 = acc[mi][ni][2] + bb0, c11 = acc[mi][ni][3] + bb1;
            if (MODE == 0) {
                __half* outh = (__half*)outp;
                int h = col >> 6, d = col & 63;
                int b0r = r0 >> 11, s0 = r0 & 2047;
                int b1r = r1 >> 11, s1 = r1 & 2047;
                *(uint32_t*)&outh[(((size_t)(b0r * H_ + h) * S_ + s0) << 6) + d] = ph2(c00, c01);
                *(uint32_t*)&outh[(((size_t)(b1r * H_ + h) * S_ + s1) << 6) + d] = ph2(c10, c11);
            } else {
                float* outf = (float*)outp;
                *(float2*)&outf[(size_t)r0 * HID_ + col] = make_float2(c00, c01);
                *(float2*)&outf[(size_t)r1 * HID_ + col] = make_float2(c10, c11);
            }
        }
    }
}

__global__ __launch_bounds__(256, 2) void gemm_qkv(
    const float* __restrict__ Xq, const float* __restrict__ Xk, const float* __restrict__ Xv,
    const float* __restrict__ Wq, const float* __restrict__ Wk, const float* __restrict__ Wv,
    const float* __restrict__ bq, const float* __restrict__ bk, const float* __restrict__ bv,
    __half* __restrict__ oq, __half* __restrict__ ok, __half* __restrict__ ov)
{
    __shared__ uint32_t Xs[128][36];
    __shared__ uint32_t Ws[32][136];
    const int z = blockIdx.z;
    const float* X    = (z == 0) ? Xq : (z == 1) ? Xk : Xv;
    const float* W    = (z == 0) ? Wq : (z == 1) ? Wk : Wv;
    const float* bias = (z == 0) ? bq : (z == 1) ? bk : bv;
    __half* out       = (z == 0) ? oq : (z == 1) ? ok : ov;
    gemm_core<0>(X, W, bias, out, Xs, Ws, blockIdx.y * 128, blockIdx.x * 128);
}

__global__ __launch_bounds__(256, 2) void gemm_out(
    const float* __restrict__ X, const float* __restrict__ W,
    const float* __restrict__ bias, float* __restrict__ out)
{
    __shared__ uint32_t Xs[128][36];
    __shared__ uint32_t Ws[32][136];
    gemm_core<1>(X, W, bias, out, Xs, Ws, blockIdx.y * 128, blockIdx.x * 128);
}

// ---------------------------------------------------------------------------
// Fused attention: fp16 inputs/mma, no-max softmax, ldmatrix fragments,
// Q A-fragments hoisted to registers for the whole kernel.
// Smem (words): Qs[128][36] Ks[64][36] Vs[64][36](transposed) Ps[128][36]
// ---------------------------------------------------------------------------
#define FP_ 36
#define Q_OFF 0
#define K_OFF (128 * FP_)
#define V_OFF (K_OFF + 64 * FP_)
#define P_OFF (V_OFF + 64 * FP_)
#define FUSED_SMEM ((P_OFF + 128 * FP_) * 4)

__global__ __launch_bounds__(256, 2) void fused_attn(
    const __half* __restrict__ qg, const __half* __restrict__ kg,
    const __half* __restrict__ vg, const uint32_t* __restrict__ bm,
    float* __restrict__ probs, float* __restrict__ ctx)
{
    extern __shared__ uint32_t sh[];
    uint32_t* Qs = sh + Q_OFF;
    uint32_t* Ks = sh + K_OFF;
    uint32_t* Vs = sh + V_OFF;
    uint32_t* Ps = sh + P_OFF;

    uint32_t sbase;
    asm("{ .reg .u64 t0; cvta.to.shared.u64 t0, %1; cvt.u32.u64 %0, t0; }"
        : "=r"(sbase) : "l"(sh));

    const int tid  = threadIdx.x;
    const int w    = tid >> 5;
    const int lane = tid & 31;
    const int g    = lane >> 2;
    const int t    = lane & 3;
    const int wr   = w * 16;
    const int q0   = blockIdx.x * 128;
    const int bh   = blockIdx.y;
    const int bb   = bh / H_;
    const int h    = bh % H_;
    const __half* qbase = qg + (size_t)bh * S_ * D_;
    const __half* kbase = kg + (size_t)bh * S_ * D_;
    const __half* vbase = vg + (size_t)bh * S_ * D_;

    const int lr0 = wr + g;
    const int lr1 = lr0 + 8;
    const int r0  = q0 + lr0;
    const int r1  = q0 + lr1;
    const uint32_t* bm0 = bm + ((size_t)bb * S_ + r0) * 64;
    const uint32_t* bm1 = bm + ((size_t)bb * S_ + r1) * 64;

    // ldmatrix lane address components
    const int arow = wr + (lane & 15);               // A-pattern row
    const int ahi  = (lane >> 4) * 4;                // A-pattern k-offset (words)
    const int brow = (lane & 7) + ((lane >> 1) & 8); // B-pattern row (0..15)
    const int bhi  = ((lane >> 3) & 1) * 4;          // B-pattern k-offset (words)
    const uint32_t qaddr = sbase + (uint32_t)(Q_OFF + arow * FP_ + ahi) * 4;
    const uint32_t paddr = sbase + (uint32_t)(P_OFF + arow * FP_ + ahi) * 4;
    const uint32_t kaddr = sbase + (uint32_t)(K_OFF + brow * FP_ + bhi) * 4;
    const uint32_t vaddr = sbase + (uint32_t)(V_OFF + brow * FP_ + bhi) * 4;

    // Q tile 128 rows x 64 halves: 1024 16B-chunks, 4/thread.
#pragma unroll
    for (int i = 0; i < 4; i++) {
        int u = tid + 256 * i;
        int r = u >> 3, c = u & 7;
        uint4 v = *(const uint4*)(qbase + (size_t)(q0 + r) * D_ + c * 8);
        *(uint4*)&Qs[r * FP_ + c * 4] = v;
    }
    __syncthreads();

    // Hoist Q A-fragments: 4 k16-steps x 4 regs, valid for entire kernel.
    uint32_t qa[4][4];
#pragma unroll
    for (int s = 0; s < 4; s++)
        ldsm4(qa[s][0], qa[s][1], qa[s][2], qa[s][3], qaddr + s * 32);

    float s0v = 0.f, s1v = 0.f;

    // ---------------- Pass 1: row sums ----------------
    for (int k0 = 0; k0 < S_; k0 += 64) {
#pragma unroll
        for (int i = 0; i < 2; i++) {
            int u = tid + 256 * i;
            int r = u >> 3, c = u & 7;
            uint4 v = *(const uint4*)(kbase + (size_t)(k0 + r) * D_ + c * 8);
            *(uint4*)&Ks[r * FP_ + c * 4] = v;
        }
        __syncthreads();

        float acc[8][4];
#pragma unroll
        for (int ni = 0; ni < 8; ni++)
#pragma unroll
            for (int r = 0; r < 4; r++) acc[ni][r] = 0.f;

#pragma unroll
        for (int s = 0; s < 4; s++) {
            uint32_t kb[16];
#pragma unroll
            for (int j = 0; j < 4; j++)
                ldsm4(kb[4 * j], kb[4 * j + 1], kb[4 * j + 2], kb[4 * j + 3],
                      kaddr + (uint32_t)(16 * j * FP_ + s * 8) * 4);
#pragma unroll
            for (int ni = 0; ni < 8; ni++)
                mma16(acc[ni], qa[s][0], qa[s][1], qa[s][2], qa[s][3],
                      kb[2 * ni], kb[2 * ni + 1]);
        }

        uint2 w0 = *(const uint2*)(bm0 + (k0 >> 5));
        uint2 w1 = *(const uint2*)(bm1 + (k0 >> 5));
#pragma unroll
        for (int ni = 0; ni < 8; ni++) {
            uint32_t sel0 = (ni < 4) ? w0.x : w0.y;
            uint32_t sel1 = (ni < 4) ? w1.x : w1.y;
            int bit = (8 * ni + 2 * t) & 31;
            float e00 = ((sel0 >> bit) & 1)       ? 0.f : __expf(acc[ni][0] * SCALE_);
            float e01 = ((sel0 >> (bit + 1)) & 1) ? 0.f : __expf(acc[ni][1] * SCALE_);
            float e10 = ((sel1 >> bit) & 1)       ? 0.f : __expf(acc[ni][2] * SCALE_);
            float e11 = ((sel1 >> (bit + 1)) & 1) ? 0.f : __expf(acc[ni][3] * SCALE_);
            s0v += e00 + e01;
            s1v += e10 + e11;
        }
        __syncthreads();
    }

    s0v += __shfl_xor_sync(0xffffffffu, s0v, 1);
    s0v += __shfl_xor_sync(0xffffffffu, s0v, 2);
    s1v += __shfl_xor_sync(0xffffffffu, s1v, 1);
    s1v += __shfl_xor_sync(0xffffffffu, s1v, 2);
    const float inv0 = 1.f / s0v;
    const float inv1 = 1.f / s1v;

    float accv[8][4];
#pragma unroll
    for (int ni = 0; ni < 8; ni++)
#pragma unroll
        for (int r = 0; r < 4; r++) accv[ni][r] = 0.f;

    float* pr0 = probs + ((size_t)bh * S_ + r0) * S_;
    float* pr1 = probs + ((size_t)bh * S_ + r1) * S_;

    // ---------------- Pass 2: probs + PV ----------------
    for (int k0 = 0; k0 < S_; k0 += 64) {
#pragma unroll
        for (int i = 0; i < 2; i++) {
            int u = tid + 256 * i;
            int r = u >> 3, c = u & 7;
            uint4 v = *(const uint4*)(kbase + (size_t)(k0 + r) * D_ + c * 8);
            *(uint4*)&Ks[r * FP_ + c * 4] = v;
        }
        // V tile 64x64 -> transposed [d][k2] via half interleave
        {
            int k2 = tid & 31;
            int d0 = (tid >> 5) * 8;
            const __half* lo = vbase + (size_t)(k0 + 2 * k2) * D_ + d0;
            const __half* hi = lo + D_;
            __half2 l[4], hh[4];
            *(uint4*)l  = *(const uint4*)lo;
            *(uint4*)hh = *(const uint4*)hi;
#pragma unroll
            for (int j = 0; j < 4; j++) {
                Vs[(d0 + 2 * j) * FP_ + k2]     = h2u(__lows2half2(l[j], hh[j]));
                Vs[(d0 + 2 * j + 1) * FP_ + k2] = h2u(__highs2half2(l[j], hh[j]));
            }
        }
        __syncthreads();

        float acc[8][4];
#pragma unroll
        for (int ni = 0; ni < 8; ni++)
#pragma unroll
            for (int r = 0; r < 4; r++) acc[ni][r] = 0.f;

#pragma unroll
        for (int s = 0; s < 4; s++) {
            uint32_t kb[16];
#pragma unroll
            for (int j = 0; j < 4; j++)
                ldsm4(kb[4 * j], kb[4 * j + 1], kb[4 * j + 2], kb[4 * j + 3],
                      kaddr + (uint32_t)(16 * j * FP_ + s * 8) * 4);
#pragma unroll
            for (int ni = 0; ni < 8; ni++)
                mma16(acc[ni], qa[s][0], qa[s][1], qa[s][2], qa[s][3],
                      kb[2 * ni], kb[2 * ni + 1]);
        }

        uint2 w0 = *(const uint2*)(bm0 + (k0 >> 5));
        uint2 w1 = *(const uint2*)(bm1 + (k0 >> 5));
#pragma unroll
        for (int ni = 0; ni < 8; ni++) {
            uint32_t sel0 = (ni < 4) ? w0.x : w0.y;
            uint32_t sel1 = (ni < 4) ? w1.x : w1.y;
            int bit = (8 * ni + 2 * t) & 31;
            float p00 = ((sel0 >> bit) & 1)       ? 0.f : __expf(acc[ni][0] * SCALE_) * inv0;
            float p01 = ((sel0 >> (bit + 1)) & 1) ? 0.f : __expf(acc[ni][1] * SCALE_) * inv0;
            float p10 = ((sel1 >> bit) & 1)       ? 0.f : __expf(acc[ni][2] * SCALE_) * inv1;
            float p11 = ((sel1 >> (bit + 1)) & 1) ? 0.f : __expf(acc[ni][3] * SCALE_) * inv1;
            int c = k0 + 8 * ni + 2 * t;
            *(float2*)(pr0 + c) = make_float2(p00, p01);
            *(float2*)(pr1 + c) = make_float2(p10, p11);
            int k2 = 4 * ni + t;
            Ps[lr0 * FP_ + k2] = ph2(p00, p01);
            Ps[lr1 * FP_ + k2] = ph2(p10, p11);
        }
        __syncwarp();

#pragma unroll
        for (int s = 0; s < 4; s++) {
            uint32_t pa[4];
            ldsm4(pa[0], pa[1], pa[2], pa[3], paddr + s * 32);
            uint32_t vb[16];
#pragma unroll
            for (int j = 0; j < 4; j++)
                ldsm4(vb[4 * j], vb[4 * j + 1], vb[4 * j + 2], vb[4 * j + 3],
                      vaddr + (uint32_t)(16 * j * FP_ + s * 8) * 4);
#pragma unroll
            for (int ni = 0; ni < 8; ni++)
                mma16(accv[ni], pa[0], pa[1], pa[2], pa[3],
                      vb[2 * ni], vb[2 * ni + 1]);
        }
        __syncthreads();
    }

#pragma unroll
    for (int ni = 0; ni < 8; ni++) {
        int col = h * D_ + 8 * ni + 2 * t;
        *(float2*)&ctx[((size_t)(bb * S_ + r0)) * HID_ + col] =
            make_float2(accv[ni][0], accv[ni][1]);
        *(float2*)&ctx[((size_t)(bb * S_ + r1)) * HID_ + col] =
            make_float2(accv[ni][2], accv[ni][3]);
    }
}

// ---------------------------------------------------------------------------
extern "C" void kernel_launch(void* const* d_in, const int* in_sizes, int n_in,
                              void* d_out, int out_size)
{
    (void)in_sizes; (void)n_in; (void)out_size;
    const float* Q  = (const float*)d_in[0];
    const float* K  = (const float*)d_in[1];
    const float* V  = (const float*)d_in[2];
    const int*   mask = (const int*)d_in[3];
    const float* Wq = (const float*)d_in[4];
    const float* bq = (const float*)d_in[5];
    const float* Wk = (const float*)d_in[6];
    const float* bk = (const float*)d_in[7];
    const float* Wv = (const float*)d_in[8];
    const float* bv = (const float*)d_in[9];
    const float* Wo = (const float*)d_in[10];
    const float* bo = (const float*)d_in[11];

    float* out   = (float*)d_out;
    float* probs = out + OUTE;

    float* scratch = nullptr;
    cudaGetSymbolAddress((void**)&scratch, g_scratch);
    uint32_t* bmp = nullptr;
    cudaGetSymbolAddress((void**)&bmp, g_bm);

    __half* gq = (__half*)scratch;
    __half* gk = gq + (size_t)OUTE;
    __half* gv = gk + (size_t)OUTE;
    float* gctx = scratch + 2ull * OUTE;

    cudaFuncSetAttribute(fused_attn, cudaFuncAttributeMaxDynamicSharedMemorySize,
                         FUSED_SMEM);

    build_bitmask<<<2048, 256>>>(mask, bmp);
    gemm_qkv<<<dim3(HID_ / 128, MROWS / 128, 3), 256>>>(
        Q, K, V, Wq, Wk, Wv, bq, bk, bv, gq, gk, gv);
    fused_attn<<<dim3(S_ / 128, BH_), 256, FUSED_SMEM>>>(gq, gk, gv, bmp, probs, gctx);
    gemm_out<<<dim3(HID_ / 128, MROWS / 128), 256>>>(gctx, Wo, bo, out);
}

// round 12
// speedup vs baseline: 1.8902x; 1.0770x over previous
#include <cuda_runtime.h>
#include <cuda_fp16.h>
#include <stdint.h>
#include <stddef.h>

#define B_ 4
#define S_ 2048
#define HID_ 768
#define H_ 12
#define D_ 64
#define BH_ 48
#define MROWS 8192
#define OUTE 6291456
#define SCALE_ 0.125f

// Scratch: q,k,v as half (1.5*OUTE floats) + ctx fp32 (OUTE floats)
__device__ float g_scratch[3ull * 6291456ull];
// Bitmask: [B][S][S/32]
__device__ uint32_t g_bm[524288];

// ---------------------------------------------------------------------------
__device__ __forceinline__ uint32_t f2t(float f) {
    uint32_t r;
    asm("cvt.rna.tf32.f32 %0, %1;" : "=r"(r) : "f"(f));
    return r;
}
__device__ __forceinline__ uint32_t ph2(float a, float b) {
    __half2 h = __floats2half2_rn(a, b);
    return *(uint32_t*)&h;
}

// tf32 m16n8k8
__device__ __forceinline__ void mma8(float* c,
    uint32_t a0, uint32_t a1, uint32_t a2, uint32_t a3,
    uint32_t b0, uint32_t b1)
{
    asm volatile(
        "mma.sync.aligned.m16n8k8.row.col.f32.tf32.tf32.f32 "
        "{%0,%1,%2,%3}, {%4,%5,%6,%7}, {%8,%9}, {%0,%1,%2,%3};"
        : "+f"(c[0]), "+f"(c[1]), "+f"(c[2]), "+f"(c[3])
        : "r"(a0), "r"(a1), "r"(a2), "r"(a3), "r"(b0), "r"(b1));
}
// fp16 m16n8k16
__device__ __forceinline__ void mma16(float* c,
    uint32_t a0, uint32_t a1, uint32_t a2, uint32_t a3,
    uint32_t b0, uint32_t b1)
{
    asm volatile(
        "mma.sync.aligned.m16n8k16.row.col.f32.f16.f16.f32 "
        "{%0,%1,%2,%3}, {%4,%5,%6,%7}, {%8,%9}, {%0,%1,%2,%3};"
        : "+f"(c[0]), "+f"(c[1]), "+f"(c[2]), "+f"(c[3])
        : "r"(a0), "r"(a1), "r"(a2), "r"(a3), "r"(b0), "r"(b1));
}
__device__ __forceinline__ void ldsm4(uint32_t& r0, uint32_t& r1,
                                      uint32_t& r2, uint32_t& r3, uint32_t saddr)
{
    asm volatile("ldmatrix.sync.aligned.m8n8.x4.shared.b16 {%0,%1,%2,%3}, [%4];"
        : "=r"(r0), "=r"(r1), "=r"(r2), "=r"(r3) : "r"(saddr));
}
__device__ __forceinline__ void ldsm4t(uint32_t& r0, uint32_t& r1,
                                       uint32_t& r2, uint32_t& r3, uint32_t saddr)
{
    asm volatile("ldmatrix.sync.aligned.m8n8.x4.trans.shared.b16 {%0,%1,%2,%3}, [%4];"
        : "=r"(r0), "=r"(r1), "=r"(r2), "=r"(r3) : "r"(saddr));
}
__device__ __forceinline__ void cpa16(uint32_t saddr, const void* g) {
    asm volatile("cp.async.cg.shared.global [%0], [%1], 16;"
        :: "r"(saddr), "l"(g));
}
#define CP_COMMIT() asm volatile("cp.async.commit_group;" ::: "memory")
#define CP_WAIT0()  asm volatile("cp.async.wait_group 0;" ::: "memory")

// ---------------------------------------------------------------------------
// Bitmask builder
// ---------------------------------------------------------------------------
__global__ __launch_bounds__(256) void build_bitmask(
    const int* __restrict__ mask, uint32_t* __restrict__ bm)
{
    int idx = blockIdx.x * 256 + threadIdx.x;
    const int* p = mask + (size_t)idx * 32;
    uint32_t r = 0;
#pragma unroll
    for (int j = 0; j < 8; j++) {
        int4 v = *(const int4*)(p + 4 * j);
        r |= (v.x != 0 ? 1u : 0u) << (4 * j);
        r |= (v.y != 0 ? 1u : 0u) << (4 * j + 1);
        r |= (v.z != 0 ? 1u : 0u) << (4 * j + 2);
        r |= (v.w != 0 ? 1u : 0u) << (4 * j + 3);
    }
    bm[idx] = r;
}

// ---------------------------------------------------------------------------
// Projection GEMMs: R4 tf32 core (unchanged; proven).
// MODE 0: write __half, scatter to BHSD. MODE 1: write float row-major.
// ---------------------------------------------------------------------------
template <int MODE>
__device__ __forceinline__ void gemm_core(
    const float* __restrict__ X, const float* __restrict__ W,
    const float* __restrict__ bias, void* __restrict__ outp,
    uint32_t (*Xs)[36], uint32_t (*Ws)[136], int m0, int n0)
{
    const int tid  = threadIdx.x;
    const int w    = tid >> 5;
    const int lane = tid & 31;
    const int g    = lane >> 2;
    const int t    = lane & 3;
    const int wm   = (w & 1) * 64;
    const int wn   = (w >> 1) * 32;

    float acc[4][4][4];
#pragma unroll
    for (int mi = 0; mi < 4; mi++)
#pragma unroll
        for (int ni = 0; ni < 4; ni++)
#pragma unroll
            for (int r = 0; r < 4; r++) acc[mi][ni][r] = 0.f;

    for (int k0 = 0; k0 < HID_; k0 += 32) {
#pragma unroll
        for (int i = 0; i < 4; i++) {
            int f = tid + 256 * i;
            int r = f >> 3, q = f & 7;
            float4 v = *(const float4*)(X + (size_t)(m0 + r) * HID_ + k0 + q * 4);
            *(uint4*)&Xs[r][q * 4] = make_uint4(f2t(v.x), f2t(v.y), f2t(v.z), f2t(v.w));
        }
#pragma unroll
        for (int i = 0; i < 4; i++) {
            int f = tid + 256 * i;
            int r = f >> 5, q = f & 31;
            float4 v = *(const float4*)(W + (size_t)(k0 + r) * HID_ + n0 + q * 4);
            *(uint4*)&Ws[r][q * 4] = make_uint4(f2t(v.x), f2t(v.y), f2t(v.z), f2t(v.w));
        }
        __syncthreads();
#pragma unroll
        for (int kk = 0; kk < 32; kk += 8) {
            uint32_t a[4][4], b[4][2];
#pragma unroll
            for (int mi = 0; mi < 4; mi++) {
                int mr = wm + 16 * mi + g;
                a[mi][0] = Xs[mr][kk + t];     a[mi][1] = Xs[mr + 8][kk + t];
                a[mi][2] = Xs[mr][kk + t + 4]; a[mi][3] = Xs[mr + 8][kk + t + 4];
            }
#pragma unroll
            for (int ni = 0; ni < 4; ni++) {
                b[ni][0] = Ws[kk + t][wn + 8 * ni + g];
                b[ni][1] = Ws[kk + t + 4][wn + 8 * ni + g];
            }
#pragma unroll
            for (int mi = 0; mi < 4; mi++)
#pragma unroll
                for (int ni = 0; ni < 4; ni++)
                    mma8(acc[mi][ni], a[mi][0], a[mi][1], a[mi][2], a[mi][3],
                         b[ni][0], b[ni][1]);
        }
        __syncthreads();
    }

#pragma unroll
    for (int mi = 0; mi < 4; mi++) {
        int r0 = m0 + wm + 16 * mi + g;
        int r1 = r0 + 8;
#pragma unroll
        for (int ni = 0; ni < 4; ni++) {
            int col = n0 + wn + 8 * ni + 2 * t;
            float bb0 = bias[col], bb1 = bias[col + 1];
            float c00 = acc[mi][ni][0] + bb0, c01 = acc[mi][ni][1] + bb1;
            float c10 = acc[mi][ni][2] + bb0, c11 = acc[mi][ni][3] + bb1;
            if (MODE == 0) {
                __half* outh = (__half*)outp;
                int h = col >> 6, d = col & 63;
                int b0r = r0 >> 11, s0 = r0 & 2047;
                int b1r = r1 >> 11, s1 = r1 & 2047;
                *(uint32_t*)&outh[(((size_t)(b0r * H_ + h) * S_ + s0) << 6) + d] = ph2(c00, c01);
                *(uint32_t*)&outh[(((size_t)(b1r * H_ + h) * S_ + s1) << 6) + d] = ph2(c10, c11);
            } else {
                float* outf = (float*)outp;
                *(float2*)&outf[(size_t)r0 * HID_ + col] = make_float2(c00, c01);
                *(float2*)&outf[(size_t)r1 * HID_ + col] = make_float2(c10, c11);
            }
        }
    }
}

__global__ __launch_bounds__(256, 2) void gemm_qkv(
    const float* __restrict__ Xq, const float* __restrict__ Xk, const float* __restrict__ Xv,
    const float* __restrict__ Wq, const float* __restrict__ Wk, const float* __restrict__ Wv,
    const float* __restrict__ bq, const float* __restrict__ bk, const float* __restrict__ bv,
    __half* __restrict__ oq, __half* __restrict__ ok, __half* __restrict__ ov)
{
    __shared__ uint32_t Xs[128][36];
    __shared__ uint32_t Ws[32][136];
    const int z = blockIdx.z;
    const float* X    = (z == 0) ? Xq : (z == 1) ? Xk : Xv;
    const float* W    = (z == 0) ? Wq : (z == 1) ? Wk : Wv;
    const float* bias = (z == 0) ? bq : (z == 1) ? bk : bv;
    __half* out       = (z == 0) ? oq : (z == 1) ? ok : ov;
    gemm_core<0>(X, W, bias, out, Xs, Ws, blockIdx.y * 128, blockIdx.x * 128);
}

__global__ __launch_bounds__(256, 2) void gemm_out(
    const float* __restrict__ X, const float* __restrict__ W,
    const float* __restrict__ bias, float* __restrict__ out)
{
    __shared__ uint32_t Xs[128][36];
    __shared__ uint32_t Ws[32][136];
    gemm_core<1>(X, W, bias, out, Xs, Ws, blockIdx.y * 128, blockIdx.x * 128);
}

// ---------------------------------------------------------------------------
// Fused attention: fp16 inputs/mma, no-max softmax, ldmatrix fragments,
// Q A-fragments hoisted, cp.async double-buffered K (both passes) and V
// (pass 2, raw [k][d] layout + ldmatrix.trans for B-fragments).
// Smem words: Qs[128][36] Kb[2][64][36] Vb[2][64][36] Ps[128][36]
// ---------------------------------------------------------------------------
#define FP_ 36
#define KBUFW (64 * FP_)
#define Q_OFF 0
#define K_OFF (128 * FP_)
#define V_OFF (K_OFF + 2 * KBUFW)
#define P_OFF (V_OFF + 2 * KBUFW)
#define FUSED_SMEM ((P_OFF + 128 * FP_) * 4)

__global__ __launch_bounds__(256, 2) void fused_attn(
    const __half* __restrict__ qg, const __half* __restrict__ kg,
    const __half* __restrict__ vg, const uint32_t* __restrict__ bm,
    float* __restrict__ probs, float* __restrict__ ctx)
{
    extern __shared__ uint32_t sh[];
    uint32_t* Ps = sh + P_OFF;

    uint32_t sbase;
    asm("{ .reg .u64 t0; cvta.to.shared.u64 t0, %1; cvt.u32.u64 %0, t0; }"
        : "=r"(sbase) : "l"(sh));

    const int tid  = threadIdx.x;
    const int w    = tid >> 5;
    const int lane = tid & 31;
    const int g    = lane >> 2;
    const int t    = lane & 3;
    const int wr   = w * 16;
    const int q0   = blockIdx.x * 128;
    const int bh   = blockIdx.y;
    const int bb   = bh / H_;
    const int h    = bh % H_;
    const __half* qbase = qg + (size_t)bh * S_ * D_;
    const __half* kbase = kg + (size_t)bh * S_ * D_;
    const __half* vbase = vg + (size_t)bh * S_ * D_;

    const int lr0 = wr + g;
    const int lr1 = lr0 + 8;
    const int r0  = q0 + lr0;
    const int r1  = q0 + lr1;
    const uint32_t* bm0 = bm + ((size_t)bb * S_ + r0) * 64;
    const uint32_t* bm1 = bm + ((size_t)bb * S_ + r1) * 64;

    // ldmatrix lane components
    const int arow = wr + (lane & 15);               // A-pattern row
    const int ahi  = (lane >> 4) * 4;                // A k-offset (words)
    const int brow = (lane & 7) + ((lane >> 1) & 8); // normal-B row ([n][k2] layout)
    const int bhi  = ((lane >> 3) & 1) * 4;          // normal-B k-offset
    const int vrow = lane & 15;                      // trans-B: k row within 16
    const int vhi  = (lane >> 4) * 4;                // trans-B: d col-group (words)
    const uint32_t qaddr  = sbase + (uint32_t)(Q_OFF + arow * FP_ + ahi) * 4;
    const uint32_t paddr  = sbase + (uint32_t)(P_OFF + arow * FP_ + ahi) * 4;
    const uint32_t kaddr0 = sbase + (uint32_t)(K_OFF + brow * FP_ + bhi) * 4;
    const uint32_t vaddr0 = sbase + (uint32_t)(V_OFF + vrow * FP_ + vhi) * 4;

    // cp.async staging indices: 512 chunks per 64x64 half tile, 2/thread
    const int cr0 = tid >> 2, cc0 = (tid & 3) * 2;   // chunk (row, col16) x2

    // Q tile 128x64 halves: 1024 chunks, 4/thread
#pragma unroll
    for (int i = 0; i < 4; i++) {
        int u = tid + 256 * i;
        int r = u >> 3, c = u & 7;
        cpa16(sbase + (uint32_t)(Q_OFF + r * FP_ + c * 4) * 4,
              qbase + (size_t)(q0 + r) * D_ + c * 8);
    }
    // K tile 0 -> buf 0
#pragma unroll
    for (int i = 0; i < 2; i++)
        cpa16(sbase + (uint32_t)(K_OFF + cr0 * FP_ + (cc0 + i) * 4) * 4,
              kbase + (size_t)cr0 * D_ + (cc0 + i) * 8);
    CP_COMMIT();
    CP_WAIT0();
    __syncthreads();

    // Hoist Q A-fragments
    uint32_t qa[4][4];
#pragma unroll
    for (int s = 0; s < 4; s++)
        ldsm4(qa[s][0], qa[s][1], qa[s][2], qa[s][3], qaddr + s * 32);

    float s0v = 0.f, s1v = 0.f;
    int buf = 0;

    // ---------------- Pass 1: row sums ----------------
    for (int kt = 0; kt < 32; kt++) {
        if (kt < 31) {
            const __half* src = kbase + (size_t)(kt + 1) * 64 * D_;
            uint32_t dst = sbase + (uint32_t)(K_OFF + (buf ^ 1) * KBUFW) * 4;
#pragma unroll
            for (int i = 0; i < 2; i++)
                cpa16(dst + (uint32_t)(cr0 * FP_ + (cc0 + i) * 4) * 4,
                      src + (size_t)cr0 * D_ + (cc0 + i) * 8);
            CP_COMMIT();
        }

        float acc[8][4];
#pragma unroll
        for (int ni = 0; ni < 8; ni++)
#pragma unroll
            for (int r = 0; r < 4; r++) acc[ni][r] = 0.f;

        uint32_t ka = kaddr0 + (uint32_t)(buf * KBUFW) * 4;
#pragma unroll
        for (int s = 0; s < 4; s++) {
            uint32_t kb[16];
#pragma unroll
            for (int j = 0; j < 4; j++)
                ldsm4(kb[4 * j], kb[4 * j + 1], kb[4 * j + 2], kb[4 * j + 3],
                      ka + (uint32_t)(16 * j * FP_ + s * 8) * 4);
#pragma unroll
            for (int ni = 0; ni < 8; ni++)
                mma16(acc[ni], qa[s][0], qa[s][1], qa[s][2], qa[s][3],
                      kb[2 * ni], kb[2 * ni + 1]);
        }

        int k0 = kt * 64;
        uint2 w0 = *(const uint2*)(bm0 + (k0 >> 5));
        uint2 w1 = *(const uint2*)(bm1 + (k0 >> 5));
#pragma unroll
        for (int ni = 0; ni < 8; ni++) {
            uint32_t sel0 = (ni < 4) ? w0.x : w0.y;
            uint32_t sel1 = (ni < 4) ? w1.x : w1.y;
            int bit = (8 * ni + 2 * t) & 31;
            float e00 = ((sel0 >> bit) & 1)       ? 0.f : __expf(acc[ni][0] * SCALE_);
            float e01 = ((sel0 >> (bit + 1)) & 1) ? 0.f : __expf(acc[ni][1] * SCALE_);
            float e10 = ((sel1 >> bit) & 1)       ? 0.f : __expf(acc[ni][2] * SCALE_);
            float e11 = ((sel1 >> (bit + 1)) & 1) ? 0.f : __expf(acc[ni][3] * SCALE_);
            s0v += e00 + e01;
            s1v += e10 + e11;
        }

        if (kt < 31) CP_WAIT0();
        __syncthreads();
        buf ^= 1;
    }

    s0v += __shfl_xor_sync(0xffffffffu, s0v, 1);
    s0v += __shfl_xor_sync(0xffffffffu, s0v, 2);
    s1v += __shfl_xor_sync(0xffffffffu, s1v, 1);
    s1v += __shfl_xor_sync(0xffffffffu, s1v, 2);
    const float inv0 = 1.f / s0v;
    const float inv1 = 1.f / s1v;

    float accv[8][4];
#pragma unroll
    for (int ni = 0; ni < 8; ni++)
#pragma unroll
        for (int r = 0; r < 4; r++) accv[ni][r] = 0.f;

    float* pr0 = probs + ((size_t)bh * S_ + r0) * S_;
    float* pr1 = probs + ((size_t)bh * S_ + r1) * S_;

    // Preload K+V tile 0 into buf 0
    buf = 0;
#pragma unroll
    for (int i = 0; i < 2; i++) {
        cpa16(sbase + (uint32_t)(K_OFF + cr0 * FP_ + (cc0 + i) * 4) * 4,
              kbase + (size_t)cr0 * D_ + (cc0 + i) * 8);
        cpa16(sbase + (uint32_t)(V_OFF + cr0 * FP_ + (cc0 + i) * 4) * 4,
              vbase + (size_t)cr0 * D_ + (cc0 + i) * 8);
    }
    CP_COMMIT();
    CP_WAIT0();
    __syncthreads();

    // ---------------- Pass 2: probs + PV ----------------
    for (int kt = 0; kt < 32; kt++) {
        if (kt < 31) {
            const __half* ksrc = kbase + (size_t)(kt + 1) * 64 * D_;
            const __half* vsrc = vbase + (size_t)(kt + 1) * 64 * D_;
            uint32_t kdst = sbase + (uint32_t)(K_OFF + (buf ^ 1) * KBUFW) * 4;
            uint32_t vdst = sbase + (uint32_t)(V_OFF + (buf ^ 1) * KBUFW) * 4;
#pragma unroll
            for (int i = 0; i < 2; i++) {
                cpa16(kdst + (uint32_t)(cr0 * FP_ + (cc0 + i) * 4) * 4,
                      ksrc + (size_t)cr0 * D_ + (cc0 + i) * 8);
                cpa16(vdst + (uint32_t)(cr0 * FP_ + (cc0 + i) * 4) * 4,
                      vsrc + (size_t)cr0 * D_ + (cc0 + i) * 8);
            }
            CP_COMMIT();
        }

        float acc[8][4];
#pragma unroll
        for (int ni = 0; ni < 8; ni++)
#pragma unroll
            for (int r = 0; r < 4; r++) acc[ni][r] = 0.f;

        uint32_t ka = kaddr0 + (uint32_t)(buf * KBUFW) * 4;
#pragma unroll
        for (int s = 0; s < 4; s++) {
            uint32_t kb[16];
#pragma unroll
            for (int j = 0; j < 4; j++)
                ldsm4(kb[4 * j], kb[4 * j + 1], kb[4 * j + 2], kb[4 * j + 3],
                      ka + (uint32_t)(16 * j * FP_ + s * 8) * 4);
#pragma unroll
            for (int ni = 0; ni < 8; ni++)
                mma16(acc[ni], qa[s][0], qa[s][1], qa[s][2], qa[s][3],
                      kb[2 * ni], kb[2 * ni + 1]);
        }

        int k0 = kt * 64;
        uint2 w0 = *(const uint2*)(bm0 + (k0 >> 5));
        uint2 w1 = *(const uint2*)(bm1 + (k0 >> 5));
#pragma unroll
        for (int ni = 0; ni < 8; ni++) {
            uint32_t sel0 = (ni < 4) ? w0.x : w0.y;
            uint32_t sel1 = (ni < 4) ? w1.x : w1.y;
            int bit = (8 * ni + 2 * t) & 31;
            float p00 = ((sel0 >> bit) & 1)       ? 0.f : __expf(acc[ni][0] * SCALE_) * inv0;
            float p01 = ((sel0 >> (bit + 1)) & 1) ? 0.f : __expf(acc[ni][1] * SCALE_) * inv0;
            float p10 = ((sel1 >> bit) & 1)       ? 0.f : __expf(acc[ni][2] * SCALE_) * inv1;
            float p11 = ((sel1 >> (bit + 1)) & 1) ? 0.f : __expf(acc[ni][3] * SCALE_) * inv1;
            int c = k0 + 8 * ni + 2 * t;
            *(float2*)(pr0 + c) = make_float2(p00, p01);
            *(float2*)(pr1 + c) = make_float2(p10, p11);
            int k2 = 4 * ni + t;
            Ps[lr0 * FP_ + k2] = ph2(p00, p01);
            Ps[lr1 * FP_ + k2] = ph2(p10, p11);
        }
        __syncwarp();

        // PV: A from Ps (warp-local rows), B from V via ldmatrix.trans.
        // Matrix i lanes: 0-15 -> k rows 16s+0..15 col-group vhi, 16-31 -> +8 cols.
        uint32_t va = vaddr0 + (uint32_t)(buf * KBUFW) * 4;
#pragma unroll
        for (int s = 0; s < 4; s++) {
            uint32_t pa[4];
            ldsm4(pa[0], pa[1], pa[2], pa[3], paddr + s * 32);
#pragma unroll
            for (int j = 0; j < 4; j++) {
                uint32_t vb0, vb1, vb2, vb3;
                ldsm4t(vb0, vb1, vb2, vb3,
                       va + (uint32_t)(16 * s * FP_ + 8 * j) * 4);
                mma16(accv[2 * j],     pa[0], pa[1], pa[2], pa[3], vb0, vb1);
                mma16(accv[2 * j + 1], pa[0], pa[1], pa[2], pa[3], vb2, vb3);
            }
        }

        if (kt < 31) CP_WAIT0();
        __syncthreads();
        buf ^= 1;
    }

#pragma unroll
    for (int ni = 0; ni < 8; ni++) {
        int col = h * D_ + 8 * ni + 2 * t;
        *(float2*)&ctx[((size_t)(bb * S_ + r0)) * HID_ + col] =
            make_float2(accv[ni][0], accv[ni][1]);
        *(float2*)&ctx[((size_t)(bb * S_ + r1)) * HID_ + col] =
            make_float2(accv[ni][2], accv[ni][3]);
    }
}

// ---------------------------------------------------------------------------
extern "C" void kernel_launch(void* const* d_in, const int* in_sizes, int n_in,
                              void* d_out, int out_size)
{
    (void)in_sizes; (void)n_in; (void)out_size;
    const float* Q  = (const float*)d_in[0];
    const float* K  = (const float*)d_in[1];
    const float* V  = (const float*)d_in[2];
    const int*   mask = (const int*)d_in[3];
    const float* Wq = (const float*)d_in[4];
    const float* bq = (const float*)d_in[5];
    const float* Wk = (const float*)d_in[6];
    const float* bk = (const float*)d_in[7];
    const float* Wv = (const float*)d_in[8];
    const float* bv = (const float*)d_in[9];
    const float* Wo = (const float*)d_in[10];
    const float* bo = (const float*)d_in[11];

    float* out   = (float*)d_out;
    float* probs = out + OUTE;

    float* scratch = nullptr;
    cudaGetSymbolAddress((void**)&scratch, g_scratch);
    uint32_t* bmp = nullptr;
    cudaGetSymbolAddress((void**)&bmp, g_bm);

    __half* gq = (__half*)scratch;
    __half* gk = gq + (size_t)OUTE;
    __half* gv = gk + (size_t)OUTE;
    float* gctx = scratch + 2ull * OUTE;

    cudaFuncSetAttribute(fused_attn, cudaFuncAttributeMaxDynamicSharedMemorySize,
                         FUSED_SMEM);

    build_bitmask<<<2048, 256>>>(mask, bmp);
    gemm_qkv<<<dim3(HID_ / 128, MROWS / 128, 3), 256>>>(
        Q, K, V, Wq, Wk, Wv, bq, bk, bv, gq, gk, gv);
    fused_attn<<<dim3(S_ / 128, BH_), 256, FUSED_SMEM>>>(gq, gk, gv, bmp, probs, gctx);
    gemm_out<<<dim3(HID_ / 128, MROWS / 128), 256>>>(gctx, Wo, bo, out);
}

// round 13
// speedup vs baseline: 1.9878x; 1.0516x over previous
#include <cuda_runtime.h>
#include <cuda_fp16.h>
#include <stdint.h>
#include <stddef.h>

#define B_ 4
#define S_ 2048
#define HID_ 768
#define H_ 12
#define D_ 64
#define BH_ 48
#define MROWS 8192
#define OUTE 6291456
#define WE 589824
#define SCALE_ 0.125f

// Scratch: rounded Xq/Xk/Xv (3*OUTE f32) + rounded W's (4*WE f32)
//        + q/k/v half (1.5*OUTE f32) + ctx f32 (OUTE)
__device__ float g_scratch[36962304ull];
// Bitmask: [B][S][S/32]
__device__ uint32_t g_bm[524288];

// ---------------------------------------------------------------------------
__device__ __forceinline__ uint32_t f2t(float f) {
    uint32_t r;
    asm("cvt.rna.tf32.f32 %0, %1;" : "=r"(r) : "f"(f));
    return r;
}
__device__ __forceinline__ uint32_t ph2(float a, float b) {
    __half2 h = __floats2half2_rn(a, b);
    return *(uint32_t*)&h;
}

// tf32 m16n8k8
__device__ __forceinline__ void mma8(float* c,
    uint32_t a0, uint32_t a1, uint32_t a2, uint32_t a3,
    uint32_t b0, uint32_t b1)
{
    asm volatile(
        "mma.sync.aligned.m16n8k8.row.col.f32.tf32.tf32.f32 "
        "{%0,%1,%2,%3}, {%4,%5,%6,%7}, {%8,%9}, {%0,%1,%2,%3};"
        : "+f"(c[0]), "+f"(c[1]), "+f"(c[2]), "+f"(c[3])
        : "r"(a0), "r"(a1), "r"(a2), "r"(a3), "r"(b0), "r"(b1));
}
// fp16 m16n8k16
__device__ __forceinline__ void mma16(float* c,
    uint32_t a0, uint32_t a1, uint32_t a2, uint32_t a3,
    uint32_t b0, uint32_t b1)
{
    asm volatile(
        "mma.sync.aligned.m16n8k16.row.col.f32.f16.f16.f32 "
        "{%0,%1,%2,%3}, {%4,%5,%6,%7}, {%8,%9}, {%0,%1,%2,%3};"
        : "+f"(c[0]), "+f"(c[1]), "+f"(c[2]), "+f"(c[3])
        : "r"(a0), "r"(a1), "r"(a2), "r"(a3), "r"(b0), "r"(b1));
}
__device__ __forceinline__ void ldsm4(uint32_t& r0, uint32_t& r1,
                                      uint32_t& r2, uint32_t& r3, uint32_t saddr)
{
    asm volatile("ldmatrix.sync.aligned.m8n8.x4.shared.b16 {%0,%1,%2,%3}, [%4];"
        : "=r"(r0), "=r"(r1), "=r"(r2), "=r"(r3) : "r"(saddr));
}
__device__ __forceinline__ void ldsm4t(uint32_t& r0, uint32_t& r1,
                                       uint32_t& r2, uint32_t& r3, uint32_t saddr)
{
    asm volatile("ldmatrix.sync.aligned.m8n8.x4.trans.shared.b16 {%0,%1,%2,%3}, [%4];"
        : "=r"(r0), "=r"(r1), "=r"(r2), "=r"(r3) : "r"(saddr));
}
__device__ __forceinline__ void cpa16(uint32_t saddr, const void* g) {
    asm volatile("cp.async.cg.shared.global [%0], [%1], 16;"
        :: "r"(saddr), "l"(g));
}
#define CP_COMMIT() asm volatile("cp.async.commit_group;" ::: "memory")
#define CP_WAIT0()  asm volatile("cp.async.wait_group 0;" ::: "memory")

// ---------------------------------------------------------------------------
// Pre-round fp32 -> tf32 bit pattern (rna). n4 float4's, one per thread.
// ---------------------------------------------------------------------------
__global__ __launch_bounds__(256) void round_tf32(
    const float* __restrict__ src, float* __restrict__ dst)
{
    size_t i = (size_t)blockIdx.x * 256 + threadIdx.x;
    float4 v = ((const float4*)src)[i];
    uint4 u = make_uint4(f2t(v.x), f2t(v.y), f2t(v.z), f2t(v.w));
    ((uint4*)dst)[i] = u;
}

// ---------------------------------------------------------------------------
// Bitmask builder
// ---------------------------------------------------------------------------
__global__ __launch_bounds__(256) void build_bitmask(
    const int* __restrict__ mask, uint32_t* __restrict__ bm)
{
    int idx = blockIdx.x * 256 + threadIdx.x;
    const int* p = mask + (size_t)idx * 32;
    uint32_t r = 0;
#pragma unroll
    for (int j = 0; j < 8; j++) {
        int4 v = *(const int4*)(p + 4 * j);
        r |= (v.x != 0 ? 1u : 0u) << (4 * j);
        r |= (v.y != 0 ? 1u : 0u) << (4 * j + 1);
        r |= (v.z != 0 ? 1u : 0u) << (4 * j + 2);
        r |= (v.w != 0 ? 1u : 0u) << (4 * j + 3);
    }
    bm[idx] = r;
}

// ---------------------------------------------------------------------------
// Projection GEMMs: tf32 mma, cp.async double-buffered tiles of pre-rounded
// fp32. Block 128x128, BK=32, warp tile 64x32.
// Smem words: Xs[2][128][36] + Ws[2][32][136] = 17920 words (71680 B)
// ---------------------------------------------------------------------------
#define XBUF 4608
#define WBUF 4352
#define WOFF (2 * XBUF)
#define GEMM_SMEM ((2 * XBUF + 2 * WBUF) * 4)

template <int MODE>
__device__ __forceinline__ void gemm_core_ca(
    const float* __restrict__ X, const float* __restrict__ W,
    const float* __restrict__ bias, void* __restrict__ outp,
    uint32_t* sh, int m0, int n0)
{
    uint32_t sbase;
    asm("{ .reg .u64 t0; cvta.to.shared.u64 t0, %1; cvt.u32.u64 %0, t0; }"
        : "=r"(sbase) : "l"(sh));

    const int tid  = threadIdx.x;
    const int w    = tid >> 5;
    const int lane = tid & 31;
    const int g    = lane >> 2;
    const int t    = lane & 3;
    const int wm   = (w & 1) * 64;
    const int wn   = (w >> 1) * 32;

    // chunk indices
    const int xr = tid >> 1, xc = (tid & 1) * 4;   // X: 128 rows x 8 chunks, 2/thread base
    const int wr2 = tid >> 5, wc2 = lane;          // W: 32 rows x 32 chunks, 4/thread base

    float acc[4][4][4];
#pragma unroll
    for (int mi = 0; mi < 4; mi++)
#pragma unroll
        for (int ni = 0; ni < 4; ni++)
#pragma unroll
            for (int r = 0; r < 4; r++) acc[mi][ni][r] = 0.f;

    // stage helpers: X tile 128x32 = 1024 chunks (4/thread), W 32x128 = 1024 (4/thread)
    auto stage = [&](int k0, int buf) {
#pragma unroll
        for (int i = 0; i < 4; i++) {
            int u = tid + 256 * i;
            int r = u >> 3, c = u & 7;
            cpa16(sbase + (uint32_t)(buf * XBUF + r * 36 + c * 4) * 4,
                  X + (size_t)(m0 + r) * HID_ + k0 + c * 4);
        }
#pragma unroll
        for (int i = 0; i < 4; i++) {
            int u = tid + 256 * i;
            int r = u >> 5, c = u & 31;
            cpa16(sbase + (uint32_t)(WOFF + buf * WBUF + r * 136 + c * 4) * 4,
                  W + (size_t)(k0 + r) * HID_ + n0 + c * 4);
        }
    };

    stage(0, 0);
    CP_COMMIT(); CP_WAIT0();
    __syncthreads();

    int buf = 0;
    for (int kt = 0; kt < 24; kt++) {
        if (kt < 23) { stage((kt + 1) * 32, buf ^ 1); CP_COMMIT(); }

        const uint32_t* Xs = sh + buf * XBUF;
        const uint32_t* Ws = sh + WOFF + buf * WBUF;
#pragma unroll
        for (int kk = 0; kk < 32; kk += 8) {
            uint32_t a[4][4], b[4][2];
#pragma unroll
            for (int mi = 0; mi < 4; mi++) {
                int mr = wm + 16 * mi + g;
                a[mi][0] = Xs[mr * 36 + kk + t];
                a[mi][1] = Xs[(mr + 8) * 36 + kk + t];
                a[mi][2] = Xs[mr * 36 + kk + t + 4];
                a[mi][3] = Xs[(mr + 8) * 36 + kk + t + 4];
            }
#pragma unroll
            for (int ni = 0; ni < 4; ni++) {
                b[ni][0] = Ws[(kk + t) * 136 + wn + 8 * ni + g];
                b[ni][1] = Ws[(kk + t + 4) * 136 + wn + 8 * ni + g];
            }
#pragma unroll
            for (int mi = 0; mi < 4; mi++)
#pragma unroll
                for (int ni = 0; ni < 4; ni++)
                    mma8(acc[mi][ni], a[mi][0], a[mi][1], a[mi][2], a[mi][3],
                         b[ni][0], b[ni][1]);
        }

        if (kt < 23) CP_WAIT0();
        __syncthreads();
        buf ^= 1;
    }

#pragma unroll
    for (int mi = 0; mi < 4; mi++) {
        int r0 = m0 + wm + 16 * mi + g;
        int r1 = r0 + 8;
#pragma unroll
        for (int ni = 0; ni < 4; ni++) {
            int col = n0 + wn + 8 * ni + 2 * t;
            float bb0 = bias[col], bb1 = bias[col + 1];
            float c00 = acc[mi][ni][0] + bb0, c01 = acc[mi][ni][1] + bb1;
            float c10 = acc[mi][ni][2] + bb0, c11 = acc[mi][ni][3] + bb1;
            if (MODE == 0) {
                __half* outh = (__half*)outp;
                int h = col >> 6, d = col & 63;
                int b0r = r0 >> 11, s0 = r0 & 2047;
                int b1r = r1 >> 11, s1 = r1 & 2047;
                *(uint32_t*)&outh[(((size_t)(b0r * H_ + h) * S_ + s0) << 6) + d] = ph2(c00, c01);
                *(uint32_t*)&outh[(((size_t)(b1r * H_ + h) * S_ + s1) << 6) + d] = ph2(c10, c11);
            } else {
                float* outf = (float*)outp;
                *(float2*)&outf[(size_t)r0 * HID_ + col] = make_float2(c00, c01);
                *(float2*)&outf[(size_t)r1 * HID_ + col] = make_float2(c10, c11);
            }
        }
    }
    (void)xr; (void)xc; (void)wr2; (void)wc2;
}

__global__ __launch_bounds__(256, 2) void gemm_qkv(
    const float* __restrict__ Xq, const float* __restrict__ Xk, const float* __restrict__ Xv,
    const float* __restrict__ Wq, const float* __restrict__ Wk, const float* __restrict__ Wv,
    const float* __restrict__ bq, const float* __restrict__ bk, const float* __restrict__ bv,
    __half* __restrict__ oq, __half* __restrict__ ok, __half* __restrict__ ov)
{
    extern __shared__ uint32_t gsh[];
    const int z = blockIdx.z;
    const float* X    = (z == 0) ? Xq : (z == 1) ? Xk : Xv;
    const float* W    = (z == 0) ? Wq : (z == 1) ? Wk : Wv;
    const float* bias = (z == 0) ? bq : (z == 1) ? bk : bv;
    __half* out       = (z == 0) ? oq : (z == 1) ? ok : ov;
    gemm_core_ca<0>(X, W, bias, out, gsh, blockIdx.y * 128, blockIdx.x * 128);
}

__global__ __launch_bounds__(256, 2) void gemm_out(
    const float* __restrict__ X, const float* __restrict__ W,
    const float* __restrict__ bias, float* __restrict__ out)
{
    extern __shared__ uint32_t gsh[];
    gemm_core_ca<1>(X, W, bias, out, gsh, blockIdx.y * 128, blockIdx.x * 128);
}

// ---------------------------------------------------------------------------
// Fused attention (R12, unchanged except ctx written pre-rounded to tf32).
// Smem words: Qs[128][36] Kb[2][64][36] Vb[2][64][36] Ps[128][36]
// ---------------------------------------------------------------------------
#define FP_ 36
#define KBUFW (64 * FP_)
#define Q_OFF 0
#define K_OFF (128 * FP_)
#define V_OFF (K_OFF + 2 * KBUFW)
#define P_OFF (V_OFF + 2 * KBUFW)
#define FUSED_SMEM ((P_OFF + 128 * FP_) * 4)

__global__ __launch_bounds__(256, 2) void fused_attn(
    const __half* __restrict__ qg, const __half* __restrict__ kg,
    const __half* __restrict__ vg, const uint32_t* __restrict__ bm,
    float* __restrict__ probs, float* __restrict__ ctx)
{
    extern __shared__ uint32_t sh[];
    uint32_t* Ps = sh + P_OFF;

    uint32_t sbase;
    asm("{ .reg .u64 t0; cvta.to.shared.u64 t0, %1; cvt.u32.u64 %0, t0; }"
        : "=r"(sbase) : "l"(sh));

    const int tid  = threadIdx.x;
    const int w    = tid >> 5;
    const int lane = tid & 31;
    const int g    = lane >> 2;
    const int t    = lane & 3;
    const int wr   = w * 16;
    const int q0   = blockIdx.x * 128;
    const int bh   = blockIdx.y;
    const int bb   = bh / H_;
    const int h    = bh % H_;
    const __half* qbase = qg + (size_t)bh * S_ * D_;
    const __half* kbase = kg + (size_t)bh * S_ * D_;
    const __half* vbase = vg + (size_t)bh * S_ * D_;

    const int lr0 = wr + g;
    const int lr1 = lr0 + 8;
    const int r0  = q0 + lr0;
    const int r1  = q0 + lr1;
    const uint32_t* bm0 = bm + ((size_t)bb * S_ + r0) * 64;
    const uint32_t* bm1 = bm + ((size_t)bb * S_ + r1) * 64;

    const int arow = wr + (lane & 15);
    const int ahi  = (lane >> 4) * 4;
    const int brow = (lane & 7) + ((lane >> 1) & 8);
    const int bhi  = ((lane >> 3) & 1) * 4;
    const int vrow = lane & 15;
    const int vhi  = (lane >> 4) * 4;
    const uint32_t qaddr  = sbase + (uint32_t)(Q_OFF + arow * FP_ + ahi) * 4;
    const uint32_t paddr  = sbase + (uint32_t)(P_OFF + arow * FP_ + ahi) * 4;
    const uint32_t kaddr0 = sbase + (uint32_t)(K_OFF + brow * FP_ + bhi) * 4;
    const uint32_t vaddr0 = sbase + (uint32_t)(V_OFF + vrow * FP_ + vhi) * 4;

    const int cr0 = tid >> 2, cc0 = (tid & 3) * 2;

#pragma unroll
    for (int i = 0; i < 4; i++) {
        int u = tid + 256 * i;
        int r = u >> 3, c = u & 7;
        cpa16(sbase + (uint32_t)(Q_OFF + r * FP_ + c * 4) * 4,
              qbase + (size_t)(q0 + r) * D_ + c * 8);
    }
#pragma unroll
    for (int i = 0; i < 2; i++)
        cpa16(sbase + (uint32_t)(K_OFF + cr0 * FP_ + (cc0 + i) * 4) * 4,
              kbase + (size_t)cr0 * D_ + (cc0 + i) * 8);
    CP_COMMIT();
    CP_WAIT0();
    __syncthreads();

    uint32_t qa[4][4];
#pragma unroll
    for (int s = 0; s < 4; s++)
        ldsm4(qa[s][0], qa[s][1], qa[s][2], qa[s][3], qaddr + s * 32);

    float s0v = 0.f, s1v = 0.f;
    int buf = 0;

    // ---------------- Pass 1: row sums ----------------
    for (int kt = 0; kt < 32; kt++) {
        if (kt < 31) {
            const __half* src = kbase + (size_t)(kt + 1) * 64 * D_;
            uint32_t dst = sbase + (uint32_t)(K_OFF + (buf ^ 1) * KBUFW) * 4;
#pragma unroll
            for (int i = 0; i < 2; i++)
                cpa16(dst + (uint32_t)(cr0 * FP_ + (cc0 + i) * 4) * 4,
                      src + (size_t)cr0 * D_ + (cc0 + i) * 8);
            CP_COMMIT();
        }

        float acc[8][4];
#pragma unroll
        for (int ni = 0; ni < 8; ni++)
#pragma unroll
            for (int r = 0; r < 4; r++) acc[ni][r] = 0.f;

        uint32_t ka = kaddr0 + (uint32_t)(buf * KBUFW) * 4;
#pragma unroll
        for (int s = 0; s < 4; s++) {
            uint32_t kb[16];
#pragma unroll
            for (int j = 0; j < 4; j++)
                ldsm4(kb[4 * j], kb[4 * j + 1], kb[4 * j + 2], kb[4 * j + 3],
                      ka + (uint32_t)(16 * j * FP_ + s * 8) * 4);
#pragma unroll
            for (int ni = 0; ni < 8; ni++)
                mma16(acc[ni], qa[s][0], qa[s][1], qa[s][2], qa[s][3],
                      kb[2 * ni], kb[2 * ni + 1]);
        }

        int k0 = kt * 64;
        uint2 w0 = *(const uint2*)(bm0 + (k0 >> 5));
        uint2 w1 = *(const uint2*)(bm1 + (k0 >> 5));
#pragma unroll
        for (int ni = 0; ni < 8; ni++) {
            uint32_t sel0 = (ni < 4) ? w0.x : w0.y;
            uint32_t sel1 = (ni < 4) ? w1.x : w1.y;
            int bit = (8 * ni + 2 * t) & 31;
            float e00 = ((sel0 >> bit) & 1)       ? 0.f : __expf(acc[ni][0] * SCALE_);
            float e01 = ((sel0 >> (bit + 1)) & 1) ? 0.f : __expf(acc[ni][1] * SCALE_);
            float e10 = ((sel1 >> bit) & 1)       ? 0.f : __expf(acc[ni][2] * SCALE_);
            float e11 = ((sel1 >> (bit + 1)) & 1) ? 0.f : __expf(acc[ni][3] * SCALE_);
            s0v += e00 + e01;
            s1v += e10 + e11;
        }

        if (kt < 31) CP_WAIT0();
        __syncthreads();
        buf ^= 1;
    }

    s0v += __shfl_xor_sync(0xffffffffu, s0v, 1);
    s0v += __shfl_xor_sync(0xffffffffu, s0v, 2);
    s1v += __shfl_xor_sync(0xffffffffu, s1v, 1);
    s1v += __shfl_xor_sync(0xffffffffu, s1v, 2);
    const float inv0 = 1.f / s0v;
    const float inv1 = 1.f / s1v;

    float accv[8][4];
#pragma unroll
    for (int ni = 0; ni < 8; ni++)
#pragma unroll
        for (int r = 0; r < 4; r++) accv[ni][r] = 0.f;

    float* pr0 = probs + ((size_t)bh * S_ + r0) * S_;
    float* pr1 = probs + ((size_t)bh * S_ + r1) * S_;

    buf = 0;
#pragma unroll
    for (int i = 0; i < 2; i++) {
        cpa16(sbase + (uint32_t)(K_OFF + cr0 * FP_ + (cc0 + i) * 4) * 4,
              kbase + (size_t)cr0 * D_ + (cc0 + i) * 8);
        cpa16(sbase + (uint32_t)(V_OFF + cr0 * FP_ + (cc0 + i) * 4) * 4,
              vbase + (size_t)cr0 * D_ + (cc0 + i) * 8);
    }
    CP_COMMIT();
    CP_WAIT0();
    __syncthreads();

    // ---------------- Pass 2: probs + PV ----------------
    for (int kt = 0; kt < 32; kt++) {
        if (kt < 31) {
            const __half* ksrc = kbase + (size_t)(kt + 1) * 64 * D_;
            const __half* vsrc = vbase + (size_t)(kt + 1) * 64 * D_;
            uint32_t kdst = sbase + (uint32_t)(K_OFF + (buf ^ 1) * KBUFW) * 4;
            uint32_t vdst = sbase + (uint32_t)(V_OFF + (buf ^ 1) * KBUFW) * 4;
#pragma unroll
            for (int i = 0; i < 2; i++) {
                cpa16(kdst + (uint32_t)(cr0 * FP_ + (cc0 + i) * 4) * 4,
                      ksrc + (size_t)cr0 * D_ + (cc0 + i) * 8);
                cpa16(vdst + (uint32_t)(cr0 * FP_ + (cc0 + i) * 4) * 4,
                      vsrc + (size_t)cr0 * D_ + (cc0 + i) * 8);
            }
            CP_COMMIT();
        }

        float acc[8][4];
#pragma unroll
        for (int ni = 0; ni < 8; ni++)
#pragma unroll
            for (int r = 0; r < 4; r++) acc[ni][r] = 0.f;

        uint32_t ka = kaddr0 + (uint32_t)(buf * KBUFW) * 4;
#pragma unroll
        for (int s = 0; s < 4; s++) {
            uint32_t kb[16];
#pragma unroll
            for (int j = 0; j < 4; j++)
                ldsm4(kb[4 * j], kb[4 * j + 1], kb[4 * j + 2], kb[4 * j + 3],
                      ka + (uint32_t)(16 * j * FP_ + s * 8) * 4);
#pragma unroll
            for (int ni = 0; ni < 8; ni++)
                mma16(acc[ni], qa[s][0], qa[s][1], qa[s][2], qa[s][3],
                      kb[2 * ni], kb[2 * ni + 1]);
        }

        int k0 = kt * 64;
        uint2 w0 = *(const uint2*)(bm0 + (k0 >> 5));
        uint2 w1 = *(const uint2*)(bm1 + (k0 >> 5));
#pragma unroll
        for (int ni = 0; ni < 8; ni++) {
            uint32_t sel0 = (ni < 4) ? w0.x : w0.y;
            uint32_t sel1 = (ni < 4) ? w1.x : w1.y;
            int bit = (8 * ni + 2 * t) & 31;
            float p00 = ((sel0 >> bit) & 1)       ? 0.f : __expf(acc[ni][0] * SCALE_) * inv0;
            float p01 = ((sel0 >> (bit + 1)) & 1) ? 0.f : __expf(acc[ni][1] * SCALE_) * inv0;
            float p10 = ((sel1 >> bit) & 1)       ? 0.f : __expf(acc[ni][2] * SCALE_) * inv1;
            float p11 = ((sel1 >> (bit + 1)) & 1) ? 0.f : __expf(acc[ni][3] * SCALE_) * inv1;
            int c = k0 + 8 * ni + 2 * t;
            *(float2*)(pr0 + c) = make_float2(p00, p01);
            *(float2*)(pr1 + c) = make_float2(p10, p11);
            int k2 = 4 * ni + t;
            Ps[lr0 * FP_ + k2] = ph2(p00, p01);
            Ps[lr1 * FP_ + k2] = ph2(p10, p11);
        }
        __syncwarp();

        uint32_t va = vaddr0 + (uint32_t)(buf * KBUFW) * 4;
#pragma unroll
        for (int s = 0; s < 4; s++) {
            uint32_t pa[4];
            ldsm4(pa[0], pa[1], pa[2], pa[3], paddr + s * 32);
#pragma unroll
            for (int j = 0; j < 4; j++) {
                uint32_t vb0, vb1, vb2, vb3;
                ldsm4t(vb0, vb1, vb2, vb3,
                       va + (uint32_t)(16 * s * FP_ + 8 * j) * 4);
                mma16(accv[2 * j],     pa[0], pa[1], pa[2], pa[3], vb0, vb1);
                mma16(accv[2 * j + 1], pa[0], pa[1], pa[2], pa[3], vb2, vb3);
            }
        }

        if (kt < 31) CP_WAIT0();
        __syncthreads();
        buf ^= 1;
    }

    // Epilogue: ctx written PRE-ROUNDED to tf32 (gemm_out consumes raw)
#pragma unroll
    for (int ni = 0; ni < 8; ni++) {
        int col = h * D_ + 8 * ni + 2 * t;
        float2 v0 = make_float2(__uint_as_float(f2t(accv[ni][0])),
                                __uint_as_float(f2t(accv[ni][1])));
        float2 v1 = make_float2(__uint_as_float(f2t(accv[ni][2])),
                                __uint_as_float(f2t(accv[ni][3])));
        *(float2*)&ctx[((size_t)(bb * S_ + r0)) * HID_ + col] = v0;
        *(float2*)&ctx[((size_t)(bb * S_ + r1)) * HID_ + col] = v1;
    }
}

// ---------------------------------------------------------------------------
extern "C" void kernel_launch(void* const* d_in, const int* in_sizes, int n_in,
                              void* d_out, int out_size)
{
    (void)in_sizes; (void)n_in; (void)out_size;
    const float* Q  = (const float*)d_in[0];
    const float* K  = (const float*)d_in[1];
    const float* V  = (const float*)d_in[2];
    const int*   mask = (const int*)d_in[3];
    const float* Wq = (const float*)d_in[4];
    const float* bq = (const float*)d_in[5];
    const float* Wk = (const float*)d_in[6];
    const float* bk = (const float*)d_in[7];
    const float* Wv = (const float*)d_in[8];
    const float* bv = (const float*)d_in[9];
    const float* Wo = (const float*)d_in[10];
    const float* bo = (const float*)d_in[11];

    float* out   = (float*)d_out;
    float* probs = out + OUTE;

    float* scratch = nullptr;
    cudaGetSymbolAddress((void**)&scratch, g_scratch);
    uint32_t* bmp = nullptr;
    cudaGetSymbolAddress((void**)&bmp, g_bm);

    float* rXq = scratch;
    float* rXk = scratch + (size_t)OUTE;
    float* rXv = scratch + 2ull * OUTE;
    float* rWq = scratch + 3ull * OUTE;
    float* rWk = rWq + WE;
    float* rWv = rWk + WE;
    float* rWo = rWv + WE;
    __half* gq = (__half*)(rWo + WE);
    __half* gk = gq + (size_t)OUTE;
    __half* gv = gk + (size_t)OUTE;
    float* gctx = (float*)(gv + (size_t)OUTE);

    cudaFuncSetAttribute(fused_attn, cudaFuncAttributeMaxDynamicSharedMemorySize,
                         FUSED_SMEM);
    cudaFuncSetAttribute(gemm_qkv, cudaFuncAttributeMaxDynamicSharedMemorySize,
                         GEMM_SMEM);
    cudaFuncSetAttribute(gemm_out, cudaFuncAttributeMaxDynamicSharedMemorySize,
                         GEMM_SMEM);

    build_bitmask<<<2048, 256>>>(mask, bmp);
    round_tf32<<<OUTE / 1024, 256>>>(Q, rXq);
    round_tf32<<<OUTE / 1024, 256>>>(K, rXk);
    round_tf32<<<OUTE / 1024, 256>>>(V, rXv);
    round_tf32<<<WE / 1024, 256>>>(Wq, rWq);
    round_tf32<<<WE / 1024, 256>>>(Wk, rWk);
    round_tf32<<<WE / 1024, 256>>>(Wv, rWv);
    round_tf32<<<WE / 1024, 256>>>(Wo, rWo);

    gemm_qkv<<<dim3(HID_ / 128, MROWS / 128, 3), 256, GEMM_SMEM>>>(
        rXq, rXk, rXv, rWq, rWk, rWv, bq, bk, bv, gq, gk, gv);
    fused_attn<<<dim3(S_ / 128, BH_), 256, FUSED_SMEM>>>(gq, gk, gv, bmp, probs, gctx);
    gemm_out<<<dim3(HID_ / 128, MROWS / 128), 256, GEMM_SMEM>>>(gctx, rWo, bo, out);
}

// round 14
// speedup vs baseline: 2.3227x; 1.1685x over previous
#include <cuda_runtime.h>
#include <cuda_fp16.h>
#include <stdint.h>
#include <stddef.h>

#define B_ 4
#define S_ 2048
#define HID_ 768
#define H_ 12
#define D_ 64
#define BH_ 48
#define MROWS 8192
#define OUTE 6291456
#define WE 589824
#define SCALE_ 0.125f

// Scratch (floats): rX half (1.5*OUTE) + rW half (2*WE) + qkv half (1.5*OUTE)
// + ctx half (0.5*OUTE)  -> fits well under the allocation below.
__device__ float g_scratch[36962304ull];
// Bitmask: [B][S][S/32]
__device__ uint32_t g_bm[524288];

// ---------------------------------------------------------------------------
__device__ __forceinline__ uint32_t ph2(float a, float b) {
    __half2 h = __floats2half2_rn(a, b);
    return *(uint32_t*)&h;
}

// fp16 m16n8k16
__device__ __forceinline__ void mma16(float* c,
    uint32_t a0, uint32_t a1, uint32_t a2, uint32_t a3,
    uint32_t b0, uint32_t b1)
{
    asm volatile(
        "mma.sync.aligned.m16n8k16.row.col.f32.f16.f16.f32 "
        "{%0,%1,%2,%3}, {%4,%5,%6,%7}, {%8,%9}, {%0,%1,%2,%3};"
        : "+f"(c[0]), "+f"(c[1]), "+f"(c[2]), "+f"(c[3])
        : "r"(a0), "r"(a1), "r"(a2), "r"(a3), "r"(b0), "r"(b1));
}
__device__ __forceinline__ void ldsm4(uint32_t& r0, uint32_t& r1,
                                      uint32_t& r2, uint32_t& r3, uint32_t saddr)
{
    asm volatile("ldmatrix.sync.aligned.m8n8.x4.shared.b16 {%0,%1,%2,%3}, [%4];"
        : "=r"(r0), "=r"(r1), "=r"(r2), "=r"(r3) : "r"(saddr));
}
__device__ __forceinline__ void ldsm4t(uint32_t& r0, uint32_t& r1,
                                       uint32_t& r2, uint32_t& r3, uint32_t saddr)
{
    asm volatile("ldmatrix.sync.aligned.m8n8.x4.trans.shared.b16 {%0,%1,%2,%3}, [%4];"
        : "=r"(r0), "=r"(r1), "=r"(r2), "=r"(r3) : "r"(saddr));
}
__device__ __forceinline__ void cpa16(uint32_t saddr, const void* g) {
    asm volatile("cp.async.cg.shared.global [%0], [%1], 16;"
        :: "r"(saddr), "l"(g));
}
#define CP_COMMIT() asm volatile("cp.async.commit_group;" ::: "memory")
#define CP_WAIT0()  asm volatile("cp.async.wait_group 0;" ::: "memory")

// ---------------------------------------------------------------------------
// Pre-convert fp32 -> fp16 (rn). One float4 per thread.
// ---------------------------------------------------------------------------
__global__ __launch_bounds__(256) void round_half(
    const float* __restrict__ src, __half* __restrict__ dst)
{
    size_t i = (size_t)blockIdx.x * 256 + threadIdx.x;
    float4 v = ((const float4*)src)[i];
    uint2 u = make_uint2(ph2(v.x, v.y), ph2(v.z, v.w));
    ((uint2*)dst)[i] = u;
}

// ---------------------------------------------------------------------------
// Bitmask builder
// ---------------------------------------------------------------------------
__global__ __launch_bounds__(256) void build_bitmask(
    const int* __restrict__ mask, uint32_t* __restrict__ bm)
{
    int idx = blockIdx.x * 256 + threadIdx.x;
    const int* p = mask + (size_t)idx * 32;
    uint32_t r = 0;
#pragma unroll
    for (int j = 0; j < 8; j++) {
        int4 v = *(const int4*)(p + 4 * j);
        r |= (v.x != 0 ? 1u : 0u) << (4 * j);
        r |= (v.y != 0 ? 1u : 0u) << (4 * j + 1);
        r |= (v.z != 0 ? 1u : 0u) << (4 * j + 2);
        r |= (v.w != 0 ? 1u : 0u) << (4 * j + 3);
    }
    bm[idx] = r;
}

// ---------------------------------------------------------------------------
// fp16 projection GEMM: C[8192,768] = X(half) @ W(half) + bias
// Block 128x128, BK=32, warp tile 64x32, m16n8k16, cp.async double-buffered,
// ldmatrix fragments (A normal from [m][k], B trans from [k][n]).
// Smem words: Xs[2][128][20] + Ws[2][32][68] = 9472 words (37888 B)
// ---------------------------------------------------------------------------
#define XP 20
#define WP 68
#define XBUFW (128 * XP)
#define WBUFW (32 * WP)
#define GW_OFF (2 * XBUFW)
#define GEMM_SMEM ((2 * XBUFW + 2 * WBUFW) * 4)

template <int MODE>
__device__ __forceinline__ void gemm16_core(
    const __half* __restrict__ X, const __half* __restrict__ W,
    const float* __restrict__ bias, void* __restrict__ outp,
    uint32_t* sh, int m0, int n0)
{
    uint32_t sbase;
    asm("{ .reg .u64 t0; cvta.to.shared.u64 t0, %1; cvt.u32.u64 %0, t0; }"
        : "=r"(sbase) : "l"(sh));

    const int tid  = threadIdx.x;
    const int w    = tid >> 5;
    const int lane = tid & 31;
    const int g    = lane >> 2;
    const int t    = lane & 3;
    const int wm   = (w & 1) * 64;
    const int wn   = (w >> 1) * 32;

    float acc[4][4][4];
#pragma unroll
    for (int mi = 0; mi < 4; mi++)
#pragma unroll
        for (int ni = 0; ni < 4; ni++)
#pragma unroll
            for (int r = 0; r < 4; r++) acc[mi][ni][r] = 0.f;

    // fragment lane addresses
    const uint32_t xbase = sbase +
        (uint32_t)((wm + (lane & 15)) * XP + (lane >> 4) * 4) * 4;
    const uint32_t wbase = sbase +
        (uint32_t)(GW_OFF + (lane & 15) * WP + wn / 2 + (lane >> 4) * 4) * 4;

    auto stage = [&](int k0, int buf) {
#pragma unroll
        for (int i = 0; i < 2; i++) {
            int u = tid + 256 * i;
            int r = u >> 2, c = u & 3;     // X: 128 rows x 4 chunks
            cpa16(sbase + (uint32_t)(buf * XBUFW + r * XP + c * 4) * 4,
                  X + (size_t)(m0 + r) * HID_ + k0 + c * 8);
        }
#pragma unroll
        for (int i = 0; i < 2; i++) {
            int u = tid + 256 * i;
            int r = u >> 4, c = u & 15;    // W: 32 rows x 16 chunks
            cpa16(sbase + (uint32_t)(GW_OFF + buf * WBUFW + r * WP + c * 4) * 4,
                  W + (size_t)(k0 + r) * HID_ + n0 + c * 8);
        }
    };

    stage(0, 0);
    CP_COMMIT(); CP_WAIT0();
    __syncthreads();

    int buf = 0;
    for (int kt = 0; kt < 24; kt++) {
        if (kt < 23) { stage((kt + 1) * 32, buf ^ 1); CP_COMMIT(); }

#pragma unroll
        for (int s = 0; s < 2; s++) {
            uint32_t a[4][4];
#pragma unroll
            for (int mi = 0; mi < 4; mi++)
                ldsm4(a[mi][0], a[mi][1], a[mi][2], a[mi][3],
                      xbase + (uint32_t)(buf * XBUFW + mi * 16 * XP + s * 8) * 4);
#pragma unroll
            for (int j = 0; j < 2; j++) {
                uint32_t b0, b1, b2, b3;
                ldsm4t(b0, b1, b2, b3,
                       wbase + (uint32_t)(buf * WBUFW + s * 16 * WP + 8 * j) * 4);
#pragma unroll
                for (int mi = 0; mi < 4; mi++) {
                    mma16(acc[mi][2 * j],     a[mi][0], a[mi][1], a[mi][2], a[mi][3], b0, b1);
                    mma16(acc[mi][2 * j + 1], a[mi][0], a[mi][1], a[mi][2], a[mi][3], b2, b3);
                }
            }
        }

        if (kt < 23) CP_WAIT0();
        __syncthreads();
        buf ^= 1;
    }

#pragma unroll
    for (int mi = 0; mi < 4; mi++) {
        int r0 = m0 + wm + 16 * mi + g;
        int r1 = r0 + 8;
#pragma unroll
        for (int ni = 0; ni < 4; ni++) {
            int col = n0 + wn + 8 * ni + 2 * t;
            float bb0 = bias[col], bb1 = bias[col + 1];
            float c00 = acc[mi][ni][0] + bb0, c01 = acc[mi][ni][1] + bb1;
            float c10 = acc[mi][ni][2] + bb0, c11 = acc[mi][ni][3] + bb1;
            if (MODE == 0) {
                __half* outh = (__half*)outp;
                int h = col >> 6, d = col & 63;
                int b0r = r0 >> 11, s0 = r0 & 2047;
                int b1r = r1 >> 11, s1 = r1 & 2047;
                *(uint32_t*)&outh[(((size_t)(b0r * H_ + h) * S_ + s0) << 6) + d] = ph2(c00, c01);
                *(uint32_t*)&outh[(((size_t)(b1r * H_ + h) * S_ + s1) << 6) + d] = ph2(c10, c11);
            } else {
                float* outf = (float*)outp;
                *(float2*)&outf[(size_t)r0 * HID_ + col] = make_float2(c00, c01);
                *(float2*)&outf[(size_t)r1 * HID_ + col] = make_float2(c10, c11);
            }
        }
    }
}

__global__ __launch_bounds__(256, 2) void gemm_qkv(
    const __half* __restrict__ Xq, const __half* __restrict__ Xk, const __half* __restrict__ Xv,
    const __half* __restrict__ Wq, const __half* __restrict__ Wk, const __half* __restrict__ Wv,
    const float* __restrict__ bq, const float* __restrict__ bk, const float* __restrict__ bv,
    __half* __restrict__ oq, __half* __restrict__ ok, __half* __restrict__ ov)
{
    extern __shared__ uint32_t gsh[];
    const int z = blockIdx.z;
    const __half* X   = (z == 0) ? Xq : (z == 1) ? Xk : Xv;
    const __half* W   = (z == 0) ? Wq : (z == 1) ? Wk : Wv;
    const float* bias = (z == 0) ? bq : (z == 1) ? bk : bv;
    __half* out       = (z == 0) ? oq : (z == 1) ? ok : ov;
    gemm16_core<0>(X, W, bias, out, gsh, blockIdx.y * 128, blockIdx.x * 128);
}

__global__ __launch_bounds__(256, 2) void gemm_out(
    const __half* __restrict__ X, const __half* __restrict__ W,
    const float* __restrict__ bias, float* __restrict__ out)
{
    extern __shared__ uint32_t gsh[];
    gemm16_core<1>(X, W, bias, out, gsh, blockIdx.y * 128, blockIdx.x * 128);
}

// ---------------------------------------------------------------------------
// Fused attention (R12/R13 proven; ctx now written as half).
// Smem words: Qs[128][36] Kb[2][64][36] Vb[2][64][36] Ps[128][36]
// ---------------------------------------------------------------------------
#define FP_ 36
#define KBUFW (64 * FP_)
#define Q_OFF 0
#define K_OFF (128 * FP_)
#define V_OFF (K_OFF + 2 * KBUFW)
#define P_OFF (V_OFF + 2 * KBUFW)
#define FUSED_SMEM ((P_OFF + 128 * FP_) * 4)

__global__ __launch_bounds__(256, 2) void fused_attn(
    const __half* __restrict__ qg, const __half* __restrict__ kg,
    const __half* __restrict__ vg, const uint32_t* __restrict__ bm,
    float* __restrict__ probs, __half* __restrict__ ctx)
{
    extern __shared__ uint32_t sh[];
    uint32_t* Ps = sh + P_OFF;

    uint32_t sbase;
    asm("{ .reg .u64 t0; cvta.to.shared.u64 t0, %1; cvt.u32.u64 %0, t0; }"
        : "=r"(sbase) : "l"(sh));

    const int tid  = threadIdx.x;
    const int w    = tid >> 5;
    const int lane = tid & 31;
    const int g    = lane >> 2;
    const int t    = lane & 3;
    const int wr   = w * 16;
    const int q0   = blockIdx.x * 128;
    const int bh   = blockIdx.y;
    const int bb   = bh / H_;
    const int h    = bh % H_;
    const __half* qbase = qg + (size_t)bh * S_ * D_;
    const __half* kbase = kg + (size_t)bh * S_ * D_;
    const __half* vbase = vg + (size_t)bh * S_ * D_;

    const int lr0 = wr + g;
    const int lr1 = lr0 + 8;
    const int r0  = q0 + lr0;
    const int r1  = q0 + lr1;
    const uint32_t* bm0 = bm + ((size_t)bb * S_ + r0) * 64;
    const uint32_t* bm1 = bm + ((size_t)bb * S_ + r1) * 64;

    const int arow = wr + (lane & 15);
    const int ahi  = (lane >> 4) * 4;
    const int brow = (lane & 7) + ((lane >> 1) & 8);
    const int bhi  = ((lane >> 3) & 1) * 4;
    const int vrow = lane & 15;
    const int vhi  = (lane >> 4) * 4;
    const uint32_t qaddr  = sbase + (uint32_t)(Q_OFF + arow * FP_ + ahi) * 4;
    const uint32_t paddr  = sbase + (uint32_t)(P_OFF + arow * FP_ + ahi) * 4;
    const uint32_t kaddr0 = sbase + (uint32_t)(K_OFF + brow * FP_ + bhi) * 4;
    const uint32_t vaddr0 = sbase + (uint32_t)(V_OFF + vrow * FP_ + vhi) * 4;

    const int cr0 = tid >> 2, cc0 = (tid & 3) * 2;

#pragma unroll
    for (int i = 0; i < 4; i++) {
        int u = tid + 256 * i;
        int r = u >> 3, c = u & 7;
        cpa16(sbase + (uint32_t)(Q_OFF + r * FP_ + c * 4) * 4,
              qbase + (size_t)(q0 + r) * D_ + c * 8);
    }
#pragma unroll
    for (int i = 0; i < 2; i++)
        cpa16(sbase + (uint32_t)(K_OFF + cr0 * FP_ + (cc0 + i) * 4) * 4,
              kbase + (size_t)cr0 * D_ + (cc0 + i) * 8);
    CP_COMMIT();
    CP_WAIT0();
    __syncthreads();

    uint32_t qa[4][4];
#pragma unroll
    for (int s = 0; s < 4; s++)
        ldsm4(qa[s][0], qa[s][1], qa[s][2], qa[s][3], qaddr + s * 32);

    float s0v = 0.f, s1v = 0.f;
    int buf = 0;

    // ---------------- Pass 1: row sums ----------------
    for (int kt = 0; kt < 32; kt++) {
        if (kt < 31) {
            const __half* src = kbase + (size_t)(kt + 1) * 64 * D_;
            uint32_t dst = sbase + (uint32_t)(K_OFF + (buf ^ 1) * KBUFW) * 4;
#pragma unroll
            for (int i = 0; i < 2; i++)
                cpa16(dst + (uint32_t)(cr0 * FP_ + (cc0 + i) * 4) * 4,
                      src + (size_t)cr0 * D_ + (cc0 + i) * 8);
            CP_COMMIT();
        }

        float acc[8][4];
#pragma unroll
        for (int ni = 0; ni < 8; ni++)
#pragma unroll
            for (int r = 0; r < 4; r++) acc[ni][r] = 0.f;

        uint32_t ka = kaddr0 + (uint32_t)(buf * KBUFW) * 4;
#pragma unroll
        for (int s = 0; s < 4; s++) {
            uint32_t kb[16];
#pragma unroll
            for (int j = 0; j < 4; j++)
                ldsm4(kb[4 * j], kb[4 * j + 1], kb[4 * j + 2], kb[4 * j + 3],
                      ka + (uint32_t)(16 * j * FP_ + s * 8) * 4);
#pragma unroll
            for (int ni = 0; ni < 8; ni++)
                mma16(acc[ni], qa[s][0], qa[s][1], qa[s][2], qa[s][3],
                      kb[2 * ni], kb[2 * ni + 1]);
        }

        int k0 = kt * 64;
        uint2 w0 = *(const uint2*)(bm0 + (k0 >> 5));
        uint2 w1 = *(const uint2*)(bm1 + (k0 >> 5));
#pragma unroll
        for (int ni = 0; ni < 8; ni++) {
            uint32_t sel0 = (ni < 4) ? w0.x : w0.y;
            uint32_t sel1 = (ni < 4) ? w1.x : w1.y;
            int bit = (8 * ni + 2 * t) & 31;
            float e00 = ((sel0 >> bit) & 1)       ? 0.f : __expf(acc[ni][0] * SCALE_);
            float e01 = ((sel0 >> (bit + 1)) & 1) ? 0.f : __expf(acc[ni][1] * SCALE_);
            float e10 = ((sel1 >> bit) & 1)       ? 0.f : __expf(acc[ni][2] * SCALE_);
            float e11 = ((sel1 >> (bit + 1)) & 1) ? 0.f : __expf(acc[ni][3] * SCALE_);
            s0v += e00 + e01;
            s1v += e10 + e11;
        }

        if (kt < 31) CP_WAIT0();
        __syncthreads();
        buf ^= 1;
    }

    s0v += __shfl_xor_sync(0xffffffffu, s0v, 1);
    s0v += __shfl_xor_sync(0xffffffffu, s0v, 2);
    s1v += __shfl_xor_sync(0xffffffffu, s1v, 1);
    s1v += __shfl_xor_sync(0xffffffffu, s1v, 2);
    const float inv0 = 1.f / s0v;
    const float inv1 = 1.f / s1v;

    float accv[8][4];
#pragma unroll
    for (int ni = 0; ni < 8; ni++)
#pragma unroll
        for (int r = 0; r < 4; r++) accv[ni][r] = 0.f;

    float* pr0 = probs + ((size_t)bh * S_ + r0) * S_;
    float* pr1 = probs + ((size_t)bh * S_ + r1) * S_;

    buf = 0;
#pragma unroll
    for (int i = 0; i < 2; i++) {
        cpa16(sbase + (uint32_t)(K_OFF + cr0 * FP_ + (cc0 + i) * 4) * 4,
              kbase + (size_t)cr0 * D_ + (cc0 + i) * 8);
        cpa16(sbase + (uint32_t)(V_OFF + cr0 * FP_ + (cc0 + i) * 4) * 4,
              vbase + (size_t)cr0 * D_ + (cc0 + i) * 8);
    }
    CP_COMMIT();
    CP_WAIT0();
    __syncthreads();

    // ---------------- Pass 2: probs + PV ----------------
    for (int kt = 0; kt < 32; kt++) {
        if (kt < 31) {
            const __half* ksrc = kbase + (size_t)(kt + 1) * 64 * D_;
            const __half* vsrc = vbase + (size_t)(kt + 1) * 64 * D_;
            uint32_t kdst = sbase + (uint32_t)(K_OFF + (buf ^ 1) * KBUFW) * 4;
            uint32_t vdst = sbase + (uint32_t)(V_OFF + (buf ^ 1) * KBUFW) * 4;
#pragma unroll
            for (int i = 0; i < 2; i++) {
                cpa16(kdst + (uint32_t)(cr0 * FP_ + (cc0 + i) * 4) * 4,
                      ksrc + (size_t)cr0 * D_ + (cc0 + i) * 8);
                cpa16(vdst + (uint32_t)(cr0 * FP_ + (cc0 + i) * 4) * 4,
                      vsrc + (size_t)cr0 * D_ + (cc0 + i) * 8);
            }
            CP_COMMIT();
        }

        float acc[8][4];
#pragma unroll
        for (int ni = 0; ni < 8; ni++)
#pragma unroll
            for (int r = 0; r < 4; r++) acc[ni][r] = 0.f;

        uint32_t ka = kaddr0 + (uint32_t)(buf * KBUFW) * 4;
#pragma unroll
        for (int s = 0; s < 4; s++) {
            uint32_t kb[16];
#pragma unroll
            for (int j = 0; j < 4; j++)
                ldsm4(kb[4 * j], kb[4 * j + 1], kb[4 * j + 2], kb[4 * j + 3],
                      ka + (uint32_t)(16 * j * FP_ + s * 8) * 4);
#pragma unroll
            for (int ni = 0; ni < 8; ni++)
                mma16(acc[ni], qa[s][0], qa[s][1], qa[s][2], qa[s][3],
                      kb[2 * ni], kb[2 * ni + 1]);
        }

        int k0 = kt * 64;
        uint2 w0 = *(const uint2*)(bm0 + (k0 >> 5));
        uint2 w1 = *(const uint2*)(bm1 + (k0 >> 5));
#pragma unroll
        for (int ni = 0; ni < 8; ni++) {
            uint32_t sel0 = (ni < 4) ? w0.x : w0.y;
            uint32_t sel1 = (ni < 4) ? w1.x : w1.y;
            int bit = (8 * ni + 2 * t) & 31;
            float p00 = ((sel0 >> bit) & 1)       ? 0.f : __expf(acc[ni][0] * SCALE_) * inv0;
            float p01 = ((sel0 >> (bit + 1)) & 1) ? 0.f : __expf(acc[ni][1] * SCALE_) * inv0;
            float p10 = ((sel1 >> bit) & 1)       ? 0.f : __expf(acc[ni][2] * SCALE_) * inv1;
            float p11 = ((sel1 >> (bit + 1)) & 1) ? 0.f : __expf(acc[ni][3] * SCALE_) * inv1;
            int c = k0 + 8 * ni + 2 * t;
            *(float2*)(pr0 + c) = make_float2(p00, p01);
            *(float2*)(pr1 + c) = make_float2(p10, p11);
            int k2 = 4 * ni + t;
            Ps[lr0 * FP_ + k2] = ph2(p00, p01);
            Ps[lr1 * FP_ + k2] = ph2(p10, p11);
        }
        __syncwarp();

        uint32_t va = vaddr0 + (uint32_t)(buf * KBUFW) * 4;
#pragma unroll
        for (int s = 0; s < 4; s++) {
            uint32_t pa[4];
            ldsm4(pa[0], pa[1], pa[2], pa[3], paddr + s * 32);
#pragma unroll
            for (int j = 0; j < 4; j++) {
                uint32_t vb0, vb1, vb2, vb3;
                ldsm4t(vb0, vb1, vb2, vb3,
                       va + (uint32_t)(16 * s * FP_ + 8 * j) * 4);
                mma16(accv[2 * j],     pa[0], pa[1], pa[2], pa[3], vb0, vb1);
                mma16(accv[2 * j + 1], pa[0], pa[1], pa[2], pa[3], vb2, vb3);
            }
        }

        if (kt < 31) CP_WAIT0();
        __syncthreads();
        buf ^= 1;
    }

    // Epilogue: ctx as half (consumed raw by fp16 gemm_out)
#pragma unroll
    for (int ni = 0; ni < 8; ni++) {
        int col = h * D_ + 8 * ni + 2 * t;
        *(uint32_t*)&ctx[((size_t)(bb * S_ + r0)) * HID_ + col] =
            ph2(accv[ni][0], accv[ni][1]);
        *(uint32_t*)&ctx[((size_t)(bb * S_ + r1)) * HID_ + col] =
            ph2(accv[ni][2], accv[ni][3]);
    }
}

// ---------------------------------------------------------------------------
extern "C" void kernel_launch(void* const* d_in, const int* in_sizes, int n_in,
                              void* d_out, int out_size)
{
    (void)in_sizes; (void)n_in; (void)out_size;
    const float* Q  = (const float*)d_in[0];
    const float* K  = (const float*)d_in[1];
    const float* V  = (const float*)d_in[2];
    const int*   mask = (const int*)d_in[3];
    const float* Wq = (const float*)d_in[4];
    const float* bq = (const float*)d_in[5];
    const float* Wk = (const float*)d_in[6];
    const float* bk = (const float*)d_in[7];
    const float* Wv = (const float*)d_in[8];
    const float* bv = (const float*)d_in[9];
    const float* Wo = (const float*)d_in[10];
    const float* bo = (const float*)d_in[11];

    float* out   = (float*)d_out;
    float* probs = out + OUTE;

    float* scratch = nullptr;
    cudaGetSymbolAddress((void**)&scratch, g_scratch);
    uint32_t* bmp = nullptr;
    cudaGetSymbolAddress((void**)&bmp, g_bm);

    __half* rXq = (__half*)scratch;                 // OUTE halves each
    __half* rXk = rXq + (size_t)OUTE;
    __half* rXv = rXk + (size_t)OUTE;
    __half* rWq = rXv + (size_t)OUTE;               // WE halves each
    __half* rWk = rWq + WE;
    __half* rWv = rWk + WE;
    __half* rWo = rWv + WE;
    __half* gq  = rWo + WE;                         // OUTE halves each
    __half* gk  = gq + (size_t)OUTE;
    __half* gv  = gk + (size_t)OUTE;
    __half* gctx = gv + (size_t)OUTE;               // OUTE halves

    cudaFuncSetAttribute(fused_attn, cudaFuncAttributeMaxDynamicSharedMemorySize,
                         FUSED_SMEM);
    cudaFuncSetAttribute(gemm_qkv, cudaFuncAttributeMaxDynamicSharedMemorySize,
                         GEMM_SMEM);
    cudaFuncSetAttribute(gemm_out, cudaFuncAttributeMaxDynamicSharedMemorySize,
                         GEMM_SMEM);

    build_bitmask<<<2048, 256>>>(mask, bmp);
    round_half<<<OUTE / 1024, 256>>>(Q, rXq);
    round_half<<<OUTE / 1024, 256>>>(K, rXk);
    round_half<<<OUTE / 1024, 256>>>(V, rXv);
    round_half<<<WE / 1024, 256>>>(Wq, rWq);
    round_half<<<WE / 1024, 256>>>(Wk, rWk);
    round_half<<<WE / 1024, 256>>>(Wv, rWv);
    round_half<<<WE / 1024, 256>>>(Wo, rWo);

    gemm_qkv<<<dim3(HID_ / 128, MROWS / 128, 3), 256, GEMM_SMEM>>>(
        rXq, rXk, rXv, rWq, rWk, rWv, bq, bk, bv, gq, gk, gv);
    fused_attn<<<dim3(S_ / 128, BH_), 256, FUSED_SMEM>>>(gq, gk, gv, bmp, probs, gctx);
    gemm_out<<<dim3(HID_ / 128, MROWS / 128), 256, GEMM_SMEM>>>(gctx, rWo, bo, out);
}

// round 15
// speedup vs baseline: 2.5686x; 1.1059x over previous
#include <cuda_runtime.h>
#include <cuda_fp16.h>
#include <stdint.h>
#include <stddef.h>

#define B_ 4
#define S_ 2048
#define HID_ 768
#define H_ 12
#define D_ 64
#define BH_ 48
#define MROWS 8192
#define OUTE 6291456
#define WE 589824
#define SCALE_ 0.125f

// Scratch (fp32 units): rX half (1.5*OUTE) + rW half (2*WE) + qkv half (1.5*OUTE)
// + ctx half (0.5*OUTE)
__device__ float g_scratch[36962304ull];
// Bitmask: [B][S][S/32]
__device__ uint32_t g_bm[524288];
// e-scratch: [bh 48][qt 16][kt 32][4096 words] of half2 = 402MB
__device__ uint32_t g_escr[100663296ull];

// ---------------------------------------------------------------------------
__device__ __forceinline__ uint32_t ph2(float a, float b) {
    __half2 h = __floats2half2_rn(a, b);
    return *(uint32_t*)&h;
}

// fp16 m16n8k16
__device__ __forceinline__ void mma16(float* c,
    uint32_t a0, uint32_t a1, uint32_t a2, uint32_t a3,
    uint32_t b0, uint32_t b1)
{
    asm volatile(
        "mma.sync.aligned.m16n8k16.row.col.f32.f16.f16.f32 "
        "{%0,%1,%2,%3}, {%4,%5,%6,%7}, {%8,%9}, {%0,%1,%2,%3};"
        : "+f"(c[0]), "+f"(c[1]), "+f"(c[2]), "+f"(c[3])
        : "r"(a0), "r"(a1), "r"(a2), "r"(a3), "r"(b0), "r"(b1));
}
__device__ __forceinline__ void ldsm4(uint32_t& r0, uint32_t& r1,
                                      uint32_t& r2, uint32_t& r3, uint32_t saddr)
{
    asm volatile("ldmatrix.sync.aligned.m8n8.x4.shared.b16 {%0,%1,%2,%3}, [%4];"
        : "=r"(r0), "=r"(r1), "=r"(r2), "=r"(r3) : "r"(saddr));
}
__device__ __forceinline__ void ldsm4t(uint32_t& r0, uint32_t& r1,
                                       uint32_t& r2, uint32_t& r3, uint32_t saddr)
{
    asm volatile("ldmatrix.sync.aligned.m8n8.x4.trans.shared.b16 {%0,%1,%2,%3}, [%4];"
        : "=r"(r0), "=r"(r1), "=r"(r2), "=r"(r3) : "r"(saddr));
}
__device__ __forceinline__ void cpa16(uint32_t saddr, const void* g) {
    asm volatile("cp.async.cg.shared.global [%0], [%1], 16;"
        :: "r"(saddr), "l"(g));
}
#define CP_COMMIT() asm volatile("cp.async.commit_group;" ::: "memory")
#define CP_WAIT0()  asm volatile("cp.async.wait_group 0;" ::: "memory")

// ---------------------------------------------------------------------------
__global__ __launch_bounds__(256) void round_half(
    const float* __restrict__ src, __half* __restrict__ dst)
{
    size_t i = (size_t)blockIdx.x * 256 + threadIdx.x;
    float4 v = ((const float4*)src)[i];
    uint2 u = make_uint2(ph2(v.x, v.y), ph2(v.z, v.w));
    ((uint2*)dst)[i] = u;
}

__global__ __launch_bounds__(256) void build_bitmask(
    const int* __restrict__ mask, uint32_t* __restrict__ bm)
{
    int idx = blockIdx.x * 256 + threadIdx.x;
    const int* p = mask + (size_t)idx * 32;
    uint32_t r = 0;
#pragma unroll
    for (int j = 0; j < 8; j++) {
        int4 v = *(const int4*)(p + 4 * j);
        r |= (v.x != 0 ? 1u : 0u) << (4 * j);
        r |= (v.y != 0 ? 1u : 0u) << (4 * j + 1);
        r |= (v.z != 0 ? 1u : 0u) << (4 * j + 2);
        r |= (v.w != 0 ? 1u : 0u) << (4 * j + 3);
    }
    bm[idx] = r;
}

// ---------------------------------------------------------------------------
// fp16 projection GEMM (R14 proven)
// ---------------------------------------------------------------------------
#define XP 20
#define WP 68
#define XBUFW (128 * XP)
#define WBUFW (32 * WP)
#define GW_OFF (2 * XBUFW)
#define GEMM_SMEM ((2 * XBUFW + 2 * WBUFW) * 4)

template <int MODE>
__device__ __forceinline__ void gemm16_core(
    const __half* __restrict__ X, const __half* __restrict__ W,
    const float* __restrict__ bias, void* __restrict__ outp,
    uint32_t* sh, int m0, int n0)
{
    uint32_t sbase;
    asm("{ .reg .u64 t0; cvta.to.shared.u64 t0, %1; cvt.u32.u64 %0, t0; }"
        : "=r"(sbase) : "l"(sh));

    const int tid  = threadIdx.x;
    const int w    = tid >> 5;
    const int lane = tid & 31;
    const int g    = lane >> 2;
    const int t    = lane & 3;
    const int wm   = (w & 1) * 64;
    const int wn   = (w >> 1) * 32;

    float acc[4][4][4];
#pragma unroll
    for (int mi = 0; mi < 4; mi++)
#pragma unroll
        for (int ni = 0; ni < 4; ni++)
#pragma unroll
            for (int r = 0; r < 4; r++) acc[mi][ni][r] = 0.f;

    const uint32_t xbase = sbase +
        (uint32_t)((wm + (lane & 15)) * XP + (lane >> 4) * 4) * 4;
    const uint32_t wbase = sbase +
        (uint32_t)(GW_OFF + (lane & 15) * WP + wn / 2 + (lane >> 4) * 4) * 4;

    auto stage = [&](int k0, int buf) {
#pragma unroll
        for (int i = 0; i < 2; i++) {
            int u = tid + 256 * i;
            int r = u >> 2, c = u & 3;
            cpa16(sbase + (uint32_t)(buf * XBUFW + r * XP + c * 4) * 4,
                  X + (size_t)(m0 + r) * HID_ + k0 + c * 8);
        }
#pragma unroll
        for (int i = 0; i < 2; i++) {
            int u = tid + 256 * i;
            int r = u >> 4, c = u & 15;
            cpa16(sbase + (uint32_t)(GW_OFF + buf * WBUFW + r * WP + c * 4) * 4,
                  W + (size_t)(k0 + r) * HID_ + n0 + c * 8);
        }
    };

    stage(0, 0);
    CP_COMMIT(); CP_WAIT0();
    __syncthreads();

    int buf = 0;
    for (int kt = 0; kt < 24; kt++) {
        if (kt < 23) { stage((kt + 1) * 32, buf ^ 1); CP_COMMIT(); }

#pragma unroll
        for (int s = 0; s < 2; s++) {
            uint32_t a[4][4];
#pragma unroll
            for (int mi = 0; mi < 4; mi++)
                ldsm4(a[mi][0], a[mi][1], a[mi][2], a[mi][3],
                      xbase + (uint32_t)(buf * XBUFW + mi * 16 * XP + s * 8) * 4);
#pragma unroll
            for (int j = 0; j < 2; j++) {
                uint32_t b0, b1, b2, b3;
                ldsm4t(b0, b1, b2, b3,
                       wbase + (uint32_t)(buf * WBUFW + s * 16 * WP + 8 * j) * 4);
#pragma unroll
                for (int mi = 0; mi < 4; mi++) {
                    mma16(acc[mi][2 * j],     a[mi][0], a[mi][1], a[mi][2], a[mi][3], b0, b1);
                    mma16(acc[mi][2 * j + 1], a[mi][0], a[mi][1], a[mi][2], a[mi][3], b2, b3);
                }
            }
        }

        if (kt < 23) CP_WAIT0();
        __syncthreads();
        buf ^= 1;
    }

#pragma unroll
    for (int mi = 0; mi < 4; mi++) {
        int r0 = m0 + wm + 16 * mi + g;
        int r1 = r0 + 8;
#pragma unroll
        for (int ni = 0; ni < 4; ni++) {
            int col = n0 + wn + 8 * ni + 2 * t;
            float bb0 = bias[col], bb1 = bias[col + 1];
            float c00 = acc[mi][ni][0] + bb0, c01 = acc[mi][ni][1] + bb1;
            float c10 = acc[mi][ni][2] + bb0, c11 = acc[mi][ni][3] + bb1;
            if (MODE == 0) {
                __half* outh = (__half*)outp;
                int h = col >> 6, d = col & 63;
                int b0r = r0 >> 11, s0 = r0 & 2047;
                int b1r = r1 >> 11, s1 = r1 & 2047;
                *(uint32_t*)&outh[(((size_t)(b0r * H_ + h) * S_ + s0) << 6) + d] = ph2(c00, c01);
                *(uint32_t*)&outh[(((size_t)(b1r * H_ + h) * S_ + s1) << 6) + d] = ph2(c10, c11);
            } else {
                float* outf = (float*)outp;
                *(float2*)&outf[(size_t)r0 * HID_ + col] = make_float2(c00, c01);
                *(float2*)&outf[(size_t)r1 * HID_ + col] = make_float2(c10, c11);
            }
        }
    }
}

__global__ __launch_bounds__(256, 2) void gemm_qkv(
    const __half* __restrict__ Xq, const __half* __restrict__ Xk, const __half* __restrict__ Xv,
    const __half* __restrict__ Wq, const __half* __restrict__ Wk, const __half* __restrict__ Wv,
    const float* __restrict__ bq, const float* __restrict__ bk, const float* __restrict__ bv,
    __half* __restrict__ oq, __half* __restrict__ ok, __half* __restrict__ ov)
{
    extern __shared__ uint32_t gsh[];
    const int z = blockIdx.z;
    const __half* X   = (z == 0) ? Xq : (z == 1) ? Xk : Xv;
    const __half* W   = (z == 0) ? Wq : (z == 1) ? Wk : Wv;
    const float* bias = (z == 0) ? bq : (z == 1) ? bk : bv;
    __half* out       = (z == 0) ? oq : (z == 1) ? ok : ov;
    gemm16_core<0>(X, W, bias, out, gsh, blockIdx.y * 128, blockIdx.x * 128);
}

__global__ __launch_bounds__(256, 2) void gemm_out(
    const __half* __restrict__ X, const __half* __restrict__ W,
    const float* __restrict__ bias, float* __restrict__ out)
{
    extern __shared__ uint32_t gsh[];
    gemm16_core<1>(X, W, bias, out, gsh, blockIdx.y * 128, blockIdx.x * 128);
}

// ---------------------------------------------------------------------------
// Fused attention:
// Pass 1: QK mma -> masked e=exp(s*scale) -> rowsum; e packed half2, stored
//         to g_escr in a fragment-native thread-private layout.
// Pass 2: reload e (4 LDG.128/tile) -> probs p = float(e)*inv (streaming
//         store); PV uses e regs DIRECTLY as A-fragments; V cp.async +
//         ldmatrix.trans. ctx = accv * inv at epilogue.
// Smem words: Qs[128][36] Kb[2][64][36] Vb[2][64][36]
// ---------------------------------------------------------------------------
#define FP_ 36
#define KBUFW (64 * FP_)
#define Q_OFF 0
#define K_OFF (128 * FP_)
#define V_OFF (K_OFF + 2 * KBUFW)
#define FUSED_SMEM ((V_OFF + 2 * KBUFW) * 4)

__global__ __launch_bounds__(256, 2) void fused_attn(
    const __half* __restrict__ qg, const __half* __restrict__ kg,
    const __half* __restrict__ vg, const uint32_t* __restrict__ bm,
    uint32_t* __restrict__ escr,
    float* __restrict__ probs, __half* __restrict__ ctx)
{
    extern __shared__ uint32_t sh[];
    uint32_t sbase;
    asm("{ .reg .u64 t0; cvta.to.shared.u64 t0, %1; cvt.u32.u64 %0, t0; }"
        : "=r"(sbase) : "l"(sh));

    const int tid  = threadIdx.x;
    const int w    = tid >> 5;
    const int lane = tid & 31;
    const int g    = lane >> 2;
    const int t    = lane & 3;
    const int wr   = w * 16;
    const int q0   = blockIdx.x * 128;
    const int bh   = blockIdx.y;
    const int bb   = bh / H_;
    const int h    = bh % H_;
    const __half* qbase = qg + (size_t)bh * S_ * D_;
    const __half* kbase = kg + (size_t)bh * S_ * D_;
    const __half* vbase = vg + (size_t)bh * S_ * D_;

    const int lr0 = wr + g;
    const int lr1 = lr0 + 8;
    const int r0  = q0 + lr0;
    const int r1  = q0 + lr1;
    const uint32_t* bm0 = bm + ((size_t)bb * S_ + r0) * 64;
    const uint32_t* bm1 = bm + ((size_t)bb * S_ + r1) * 64;

    // e-scratch base for this (bh, q-tile): [kt][4096 words]
    uint32_t* eb = escr + (((size_t)bh * 16 + blockIdx.x) * 32) * 4096 + tid * 4;

    const int arow = wr + (lane & 15);
    const int ahi  = (lane >> 4) * 4;
    const int brow = (lane & 7) + ((lane >> 1) & 8);
    const int bhi  = ((lane >> 3) & 1) * 4;
    const int vrow = lane & 15;
    const int vhi  = (lane >> 4) * 4;
    const uint32_t qaddr  = sbase + (uint32_t)(Q_OFF + arow * FP_ + ahi) * 4;
    const uint32_t kaddr0 = sbase + (uint32_t)(K_OFF + brow * FP_ + bhi) * 4;
    const uint32_t vaddr0 = sbase + (uint32_t)(V_OFF + vrow * FP_ + vhi) * 4;

    const int cr0 = tid >> 2, cc0 = (tid & 3) * 2;

    // Q tile + K tile 0
#pragma unroll
    for (int i = 0; i < 4; i++) {
        int u = tid + 256 * i;
        int r = u >> 3, c = u & 7;
        cpa16(sbase + (uint32_t)(Q_OFF + r * FP_ + c * 4) * 4,
              qbase + (size_t)(q0 + r) * D_ + c * 8);
    }
#pragma unroll
    for (int i = 0; i < 2; i++)
        cpa16(sbase + (uint32_t)(K_OFF + cr0 * FP_ + (cc0 + i) * 4) * 4,
              kbase + (size_t)cr0 * D_ + (cc0 + i) * 8);
    CP_COMMIT();
    CP_WAIT0();
    __syncthreads();

    uint32_t qa[4][4];
#pragma unroll
    for (int s = 0; s < 4; s++)
        ldsm4(qa[s][0], qa[s][1], qa[s][2], qa[s][3], qaddr + s * 32);

    float s0v = 0.f, s1v = 0.f;
    int buf = 0;

    // ---------------- Pass 1: QK -> e (store) + row sums ----------------
    for (int kt = 0; kt < 32; kt++) {
        if (kt < 31) {
            const __half* src = kbase + (size_t)(kt + 1) * 64 * D_;
            uint32_t dst = sbase + (uint32_t)(K_OFF + (buf ^ 1) * KBUFW) * 4;
#pragma unroll
            for (int i = 0; i < 2; i++)
                cpa16(dst + (uint32_t)(cr0 * FP_ + (cc0 + i) * 4) * 4,
                      src + (size_t)cr0 * D_ + (cc0 + i) * 8);
            CP_COMMIT();
        }

        float acc[8][4];
#pragma unroll
        for (int ni = 0; ni < 8; ni++)
#pragma unroll
            for (int r = 0; r < 4; r++) acc[ni][r] = 0.f;

        uint32_t ka = kaddr0 + (uint32_t)(buf * KBUFW) * 4;
#pragma unroll
        for (int s = 0; s < 4; s++) {
            uint32_t kb[16];
#pragma unroll
            for (int j = 0; j < 4; j++)
                ldsm4(kb[4 * j], kb[4 * j + 1], kb[4 * j + 2], kb[4 * j + 3],
                      ka + (uint32_t)(16 * j * FP_ + s * 8) * 4);
#pragma unroll
            for (int ni = 0; ni < 8; ni++)
                mma16(acc[ni], qa[s][0], qa[s][1], qa[s][2], qa[s][3],
                      kb[2 * ni], kb[2 * ni + 1]);
        }

        int k0 = kt * 64;
        uint2 w0 = *(const uint2*)(bm0 + (k0 >> 5));
        uint2 w1 = *(const uint2*)(bm1 + (k0 >> 5));
        uint32_t ue[16];
#pragma unroll
        for (int ni = 0; ni < 8; ni++) {
            uint32_t sel0 = (ni < 4) ? w0.x : w0.y;
            uint32_t sel1 = (ni < 4) ? w1.x : w1.y;
            int bit = (8 * ni + 2 * t) & 31;
            float e00 = ((sel0 >> bit) & 1)       ? 0.f : __expf(acc[ni][0] * SCALE_);
            float e01 = ((sel0 >> (bit + 1)) & 1) ? 0.f : __expf(acc[ni][1] * SCALE_);
            float e10 = ((sel1 >> bit) & 1)       ? 0.f : __expf(acc[ni][2] * SCALE_);
            float e11 = ((sel1 >> (bit + 1)) & 1) ? 0.f : __expf(acc[ni][3] * SCALE_);
            s0v += e00 + e01;
            s1v += e10 + e11;
            ue[2 * ni]     = ph2(e00, e01);
            ue[2 * ni + 1] = ph2(e10, e11);
        }
        uint32_t* ep = eb + (size_t)kt * 4096;
#pragma unroll
        for (int i4 = 0; i4 < 4; i4++)
            *(uint4*)(ep + i4 * 1024) = *(const uint4*)&ue[4 * i4];

        if (kt < 31) CP_WAIT0();
        __syncthreads();
        buf ^= 1;
    }

    s0v += __shfl_xor_sync(0xffffffffu, s0v, 1);
    s0v += __shfl_xor_sync(0xffffffffu, s0v, 2);
    s1v += __shfl_xor_sync(0xffffffffu, s1v, 1);
    s1v += __shfl_xor_sync(0xffffffffu, s1v, 2);
    const float inv0 = 1.f / s0v;
    const float inv1 = 1.f / s1v;

    float accv[8][4];
#pragma unroll
    for (int ni = 0; ni < 8; ni++)
#pragma unroll
        for (int r = 0; r < 4; r++) accv[ni][r] = 0.f;

    float* pr0 = probs + ((size_t)bh * S_ + r0) * S_;
    float* pr1 = probs + ((size_t)bh * S_ + r1) * S_;

    // Preload V tile 0 + e tile 0
    buf = 0;
#pragma unroll
    for (int i = 0; i < 2; i++)
        cpa16(sbase + (uint32_t)(V_OFF + cr0 * FP_ + (cc0 + i) * 4) * 4,
              vbase + (size_t)cr0 * D_ + (cc0 + i) * 8);
    CP_COMMIT();

    uint32_t uc[16];
#pragma unroll
    for (int i4 = 0; i4 < 4; i4++)
        *(uint4*)&uc[4 * i4] = *(const uint4*)(eb + i4 * 1024);

    CP_WAIT0();
    __syncthreads();

    // ---------------- Pass 2: probs + PV (no QK, no exp) ----------------
    for (int kt = 0; kt < 32; kt++) {
        uint32_t un[16];
        if (kt < 31) {
            // prefetch next e tile
            uint32_t* ep = eb + (size_t)(kt + 1) * 4096;
#pragma unroll
            for (int i4 = 0; i4 < 4; i4++)
                *(uint4*)&un[4 * i4] = *(const uint4*)(ep + i4 * 1024);
            // prefetch next V tile
            const __half* vsrc = vbase + (size_t)(kt + 1) * 64 * D_;
            uint32_t vdst = sbase + (uint32_t)(V_OFF + (buf ^ 1) * KBUFW) * 4;
#pragma unroll
            for (int i = 0; i < 2; i++)
                cpa16(vdst + (uint32_t)(cr0 * FP_ + (cc0 + i) * 4) * 4,
                      vsrc + (size_t)cr0 * D_ + (cc0 + i) * 8);
            CP_COMMIT();
        }

        // probs: p = float(e) * inv
        int k0 = kt * 64;
#pragma unroll
        for (int ni = 0; ni < 8; ni++) {
            float2 e0 = __half22float2(*(const __half2*)&uc[2 * ni]);
            float2 e1 = __half22float2(*(const __half2*)&uc[2 * ni + 1]);
            int c = k0 + 8 * ni + 2 * t;
            float2 p0 = make_float2(e0.x * inv0, e0.y * inv0);
            float2 p1 = make_float2(e1.x * inv1, e1.y * inv1);
            __stcs((float2*)(pr0 + c), p0);
            __stcs((float2*)(pr1 + c), p1);
        }

        // PV: A = e regs directly (uc[4s..4s+3] is the s-th k16 A-fragment)
        uint32_t va = vaddr0 + (uint32_t)(buf * KBUFW) * 4;
#pragma unroll
        for (int s = 0; s < 4; s++) {
#pragma unroll
            for (int j = 0; j < 4; j++) {
                uint32_t vb0, vb1, vb2, vb3;
                ldsm4t(vb0, vb1, vb2, vb3,
                       va + (uint32_t)(16 * s * FP_ + 8 * j) * 4);
                mma16(accv[2 * j],     uc[4 * s], uc[4 * s + 1], uc[4 * s + 2], uc[4 * s + 3], vb0, vb1);
                mma16(accv[2 * j + 1], uc[4 * s], uc[4 * s + 1], uc[4 * s + 2], uc[4 * s + 3], vb2, vb3);
            }
        }

        if (kt < 31) {
            CP_WAIT0();
#pragma unroll
            for (int i = 0; i < 16; i++) uc[i] = un[i];
        }
        __syncthreads();
        buf ^= 1;
    }

    // Epilogue: ctx = accv * inv (half)
#pragma unroll
    for (int ni = 0; ni < 8; ni++) {
        int col = h * D_ + 8 * ni + 2 * t;
        *(uint32_t*)&ctx[((size_t)(bb * S_ + r0)) * HID_ + col] =
            ph2(accv[ni][0] * inv0, accv[ni][1] * inv0);
        *(uint32_t*)&ctx[((size_t)(bb * S_ + r1)) * HID_ + col] =
            ph2(accv[ni][2] * inv1, accv[ni][3] * inv1);
    }
}

// ---------------------------------------------------------------------------
extern "C" void kernel_launch(void* const* d_in, const int* in_sizes, int n_in,
                              void* d_out, int out_size)
{
    (void)in_sizes; (void)n_in; (void)out_size;
    const float* Q  = (const float*)d_in[0];
    const float* K  = (const float*)d_in[1];
    const float* V  = (const float*)d_in[2];
    const int*   mask = (const int*)d_in[3];
    const float* Wq = (const float*)d_in[4];
    const float* bq = (const float*)d_in[5];
    const float* Wk = (const float*)d_in[6];
    const float* bk = (const float*)d_in[7];
    const float* Wv = (const float*)d_in[8];
    const float* bv = (const float*)d_in[9];
    const float* Wo = (const float*)d_in[10];
    const float* bo = (const float*)d_in[11];

    float* out   = (float*)d_out;
    float* probs = out + OUTE;

    float* scratch = nullptr;
    cudaGetSymbolAddress((void**)&scratch, g_scratch);
    uint32_t* bmp = nullptr;
    cudaGetSymbolAddress((void**)&bmp, g_bm);
    uint32_t* escr = nullptr;
    cudaGetSymbolAddress((void**)&escr, g_escr);

    __half* rXq = (__half*)scratch;
    __half* rXk = rXq + (size_t)OUTE;
    __half* rXv = rXk + (size_t)OUTE;
    __half* rWq = rXv + (size_t)OUTE;
    __half* rWk = rWq + WE;
    __half* rWv = rWk + WE;
    __half* rWo = rWv + WE;
    __half* gq  = rWo + WE;
    __half* gk  = gq + (size_t)OUTE;
    __half* gv  = gk + (size_t)OUTE;
    __half* gctx = gv + (size_t)OUTE;

    cudaFuncSetAttribute(fused_attn, cudaFuncAttributeMaxDynamicSharedMemorySize,
                         FUSED_SMEM);
    cudaFuncSetAttribute(gemm_qkv, cudaFuncAttributeMaxDynamicSharedMemorySize,
                         GEMM_SMEM);
    cudaFuncSetAttribute(gemm_out, cudaFuncAttributeMaxDynamicSharedMemorySize,
                         GEMM_SMEM);

    build_bitmask<<<2048, 256>>>(mask, bmp);
    round_half<<<OUTE / 1024, 256>>>(Q, rXq);
    round_half<<<OUTE / 1024, 256>>>(K, rXk);
    round_half<<<OUTE / 1024, 256>>>(V, rXv);
    round_half<<<WE / 1024, 256>>>(Wq, rWq);
    round_half<<<WE / 1024, 256>>>(Wk, rWk);
    round_half<<<WE / 1024, 256>>>(Wv, rWv);
    round_half<<<WE / 1024, 256>>>(Wo, rWo);

    gemm_qkv<<<dim3(HID_ / 128, MROWS / 128, 3), 256, GEMM_SMEM>>>(
        rXq, rXk, rXv, rWq, rWk, rWv, bq, bk, bv, gq, gk, gv);
    fused_attn<<<dim3(S_ / 128, BH_), 256, FUSED_SMEM>>>(
        gq, gk, gv, bmp, escr, probs, gctx);
    gemm_out<<<dim3(HID_ / 128, MROWS / 128), 256, GEMM_SMEM>>>(gctx, rWo, bo, out);
}

// round 16
// speedup vs baseline: 2.6469x; 1.0305x over previous
#include <cuda_runtime.h>
#include <cuda_fp16.h>
#include <stdint.h>
#include <stddef.h>

#define B_ 4
#define S_ 2048
#define HID_ 768
#define H_ 12
#define D_ 64
#define BH_ 48
#define MROWS 8192
#define OUTE 6291456
#define WE 589824
#define SCALE_ 0.125f

__device__ float g_scratch[36962304ull];
__device__ uint32_t g_bm[524288];
// e-scratch: [bh 48][qt 16][kt 32][4096 words] of half2
__device__ uint32_t g_escr[100663296ull];

// ---------------------------------------------------------------------------
__device__ __forceinline__ uint32_t ph2(float a, float b) {
    __half2 h = __floats2half2_rn(a, b);
    return *(uint32_t*)&h;
}

__device__ __forceinline__ void mma16(float* c,
    uint32_t a0, uint32_t a1, uint32_t a2, uint32_t a3,
    uint32_t b0, uint32_t b1)
{
    asm volatile(
        "mma.sync.aligned.m16n8k16.row.col.f32.f16.f16.f32 "
        "{%0,%1,%2,%3}, {%4,%5,%6,%7}, {%8,%9}, {%0,%1,%2,%3};"
        : "+f"(c[0]), "+f"(c[1]), "+f"(c[2]), "+f"(c[3])
        : "r"(a0), "r"(a1), "r"(a2), "r"(a3), "r"(b0), "r"(b1));
}
__device__ __forceinline__ void ldsm4(uint32_t& r0, uint32_t& r1,
                                      uint32_t& r2, uint32_t& r3, uint32_t saddr)
{
    asm volatile("ldmatrix.sync.aligned.m8n8.x4.shared.b16 {%0,%1,%2,%3}, [%4];"
        : "=r"(r0), "=r"(r1), "=r"(r2), "=r"(r3) : "r"(saddr));
}
__device__ __forceinline__ void ldsm4t(uint32_t& r0, uint32_t& r1,
                                       uint32_t& r2, uint32_t& r3, uint32_t saddr)
{
    asm volatile("ldmatrix.sync.aligned.m8n8.x4.trans.shared.b16 {%0,%1,%2,%3}, [%4];"
        : "=r"(r0), "=r"(r1), "=r"(r2), "=r"(r3) : "r"(saddr));
}
__device__ __forceinline__ void cpa16(uint32_t saddr, const void* g) {
    asm volatile("cp.async.cg.shared.global [%0], [%1], 16;"
        :: "r"(saddr), "l"(g));
}
#define CP_COMMIT() asm volatile("cp.async.commit_group;" ::: "memory")
#define CP_WAIT0()  asm volatile("cp.async.wait_group 0;" ::: "memory")

// ---------------------------------------------------------------------------
// prep_all: one launch does bitmask + all 7 fp32->fp16 conversions.
// Block ranges: [0,18432) X rounds (3 x 6144), [18432,20736) W rounds (4x576),
// [20736,22784) bitmask (2048).
// ---------------------------------------------------------------------------
__global__ __launch_bounds__(256) void prep_all(
    const float* __restrict__ Q, const float* __restrict__ K, const float* __restrict__ V,
    const float* __restrict__ Wq, const float* __restrict__ Wk,
    const float* __restrict__ Wv, const float* __restrict__ Wo,
    __half* __restrict__ rXq, __half* __restrict__ rXk, __half* __restrict__ rXv,
    __half* __restrict__ rWq, __half* __restrict__ rWk,
    __half* __restrict__ rWv, __half* __restrict__ rWo,
    const int* __restrict__ mask, uint32_t* __restrict__ bm)
{
    int bid = blockIdx.x;
    if (bid < 18432) {
        int which = bid / 6144;
        int lb = bid - which * 6144;
        const float* src = (which == 0) ? Q : (which == 1) ? K : V;
        __half* dst = (which == 0) ? rXq : (which == 1) ? rXk : rXv;
        size_t i = (size_t)lb * 256 + threadIdx.x;
        float4 v = ((const float4*)src)[i];
        ((uint2*)dst)[i] = make_uint2(ph2(v.x, v.y), ph2(v.z, v.w));
    } else if (bid < 20736) {
        int r = bid - 18432;
        int which = r / 576;
        int lb = r - which * 576;
        const float* src = (which == 0) ? Wq : (which == 1) ? Wk
                         : (which == 2) ? Wv : Wo;
        __half* dst = (which == 0) ? rWq : (which == 1) ? rWk
                    : (which == 2) ? rWv : rWo;
        size_t i = (size_t)lb * 256 + threadIdx.x;
        float4 v = ((const float4*)src)[i];
        ((uint2*)dst)[i] = make_uint2(ph2(v.x, v.y), ph2(v.z, v.w));
    } else {
        int idx = (bid - 20736) * 256 + threadIdx.x;
        const int* p = mask + (size_t)idx * 32;
        uint32_t r = 0;
#pragma unroll
        for (int j = 0; j < 8; j++) {
            int4 v = *(const int4*)(p + 4 * j);
            r |= (v.x != 0 ? 1u : 0u) << (4 * j);
            r |= (v.y != 0 ? 1u : 0u) << (4 * j + 1);
            r |= (v.z != 0 ? 1u : 0u) << (4 * j + 2);
            r |= (v.w != 0 ? 1u : 0u) << (4 * j + 3);
        }
        bm[idx] = r;
    }
}

// ---------------------------------------------------------------------------
// fp16 projection GEMM, BK=64, cp.async double-buffered, ldmatrix fragments.
// Smem words: Xs[2][128][36] + Ws[2][64][68] = 17920 words (71680 B)
// ---------------------------------------------------------------------------
#define XP 36
#define WP 68
#define XBUFW (128 * XP)
#define WBUFW (64 * WP)
#define GW_OFF (2 * XBUFW)
#define GEMM_SMEM ((2 * XBUFW + 2 * WBUFW) * 4)

template <int MODE>
__device__ __forceinline__ void gemm16_core(
    const __half* __restrict__ X, const __half* __restrict__ W,
    const float* __restrict__ bias, void* __restrict__ outp,
    uint32_t* sh, int m0, int n0)
{
    uint32_t sbase;
    asm("{ .reg .u64 t0; cvta.to.shared.u64 t0, %1; cvt.u32.u64 %0, t0; }"
        : "=r"(sbase) : "l"(sh));

    const int tid  = threadIdx.x;
    const int w    = tid >> 5;
    const int lane = tid & 31;
    const int g    = lane >> 2;
    const int t    = lane & 3;
    const int wm   = (w & 1) * 64;
    const int wn   = (w >> 1) * 32;

    float acc[4][4][4];
#pragma unroll
    for (int mi = 0; mi < 4; mi++)
#pragma unroll
        for (int ni = 0; ni < 4; ni++)
#pragma unroll
            for (int r = 0; r < 4; r++) acc[mi][ni][r] = 0.f;

    const uint32_t xbase = sbase +
        (uint32_t)((wm + (lane & 15)) * XP + (lane >> 4) * 4) * 4;
    const uint32_t wbase = sbase +
        (uint32_t)(GW_OFF + (lane & 15) * WP + wn / 2 + (lane >> 4) * 4) * 4;

    auto stage = [&](int k0, int buf) {
        // X tile 128x64 halves: 1024 chunks, 4/thread
#pragma unroll
        for (int i = 0; i < 4; i++) {
            int u = tid + 256 * i;
            int r = u >> 3, c = u & 7;
            cpa16(sbase + (uint32_t)(buf * XBUFW + r * XP + c * 4) * 4,
                  X + (size_t)(m0 + r) * HID_ + k0 + c * 8);
        }
        // W tile 64x128 halves: 1024 chunks, 4/thread
#pragma unroll
        for (int i = 0; i < 4; i++) {
            int u = tid + 256 * i;
            int r = u >> 4, c = u & 15;
            cpa16(sbase + (uint32_t)(GW_OFF + buf * WBUFW + r * WP + c * 4) * 4,
                  W + (size_t)(k0 + r) * HID_ + n0 + c * 8);
        }
    };

    stage(0, 0);
    CP_COMMIT(); CP_WAIT0();
    __syncthreads();

    int buf = 0;
    for (int kt = 0; kt < 12; kt++) {
        if (kt < 11) { stage((kt + 1) * 64, buf ^ 1); CP_COMMIT(); }

#pragma unroll
        for (int s = 0; s < 4; s++) {
            uint32_t a[4][4];
#pragma unroll
            for (int mi = 0; mi < 4; mi++)
                ldsm4(a[mi][0], a[mi][1], a[mi][2], a[mi][3],
                      xbase + (uint32_t)(buf * XBUFW + mi * 16 * XP + s * 8) * 4);
#pragma unroll
            for (int j = 0; j < 2; j++) {
                uint32_t b0, b1, b2, b3;
                ldsm4t(b0, b1, b2, b3,
                       wbase + (uint32_t)(buf * WBUFW + s * 16 * WP + 8 * j) * 4);
#pragma unroll
                for (int mi = 0; mi < 4; mi++) {
                    mma16(acc[mi][2 * j],     a[mi][0], a[mi][1], a[mi][2], a[mi][3], b0, b1);
                    mma16(acc[mi][2 * j + 1], a[mi][0], a[mi][1], a[mi][2], a[mi][3], b2, b3);
                }
            }
        }

        if (kt < 11) CP_WAIT0();
        __syncthreads();
        buf ^= 1;
    }

#pragma unroll
    for (int mi = 0; mi < 4; mi++) {
        int r0 = m0 + wm + 16 * mi + g;
        int r1 = r0 + 8;
#pragma unroll
        for (int ni = 0; ni < 4; ni++) {
            int col = n0 + wn + 8 * ni + 2 * t;
            float bb0 = bias[col], bb1 = bias[col + 1];
            float c00 = acc[mi][ni][0] + bb0, c01 = acc[mi][ni][1] + bb1;
            float c10 = acc[mi][ni][2] + bb0, c11 = acc[mi][ni][3] + bb1;
            if (MODE == 0) {
                __half* outh = (__half*)outp;
                int h = col >> 6, d = col & 63;
                int b0r = r0 >> 11, s0 = r0 & 2047;
                int b1r = r1 >> 11, s1 = r1 & 2047;
                *(uint32_t*)&outh[(((size_t)(b0r * H_ + h) * S_ + s0) << 6) + d] = ph2(c00, c01);
                *(uint32_t*)&outh[(((size_t)(b1r * H_ + h) * S_ + s1) << 6) + d] = ph2(c10, c11);
            } else {
                float* outf = (float*)outp;
                *(float2*)&outf[(size_t)r0 * HID_ + col] = make_float2(c00, c01);
                *(float2*)&outf[(size_t)r1 * HID_ + col] = make_float2(c10, c11);
            }
        }
    }
}

__global__ __launch_bounds__(256, 2) void gemm_qkv(
    const __half* __restrict__ Xq, const __half* __restrict__ Xk, const __half* __restrict__ Xv,
    const __half* __restrict__ Wq, const __half* __restrict__ Wk, const __half* __restrict__ Wv,
    const float* __restrict__ bq, const float* __restrict__ bk, const float* __restrict__ bv,
    __half* __restrict__ oq, __half* __restrict__ ok, __half* __restrict__ ov)
{
    extern __shared__ uint32_t gsh[];
    const int z = blockIdx.z;
    const __half* X   = (z == 0) ? Xq : (z == 1) ? Xk : Xv;
    const __half* W   = (z == 0) ? Wq : (z == 1) ? Wk : Wv;
    const float* bias = (z == 0) ? bq : (z == 1) ? bk : bv;
    __half* out       = (z == 0) ? oq : (z == 1) ? ok : ov;
    gemm16_core<0>(X, W, bias, out, gsh, blockIdx.y * 128, blockIdx.x * 128);
}

__global__ __launch_bounds__(256, 2) void gemm_out(
    const __half* __restrict__ X, const __half* __restrict__ W,
    const float* __restrict__ bias, float* __restrict__ out)
{
    extern __shared__ uint32_t gsh[];
    gemm16_core<1>(X, W, bias, out, gsh, blockIdx.y * 128, blockIdx.x * 128);
}

// ---------------------------------------------------------------------------
// Fused attention (R15 proven, unchanged).
// ---------------------------------------------------------------------------
#define FP_ 36
#define KBUFW (64 * FP_)
#define Q_OFF 0
#define K_OFF (128 * FP_)
#define V_OFF (K_OFF + 2 * KBUFW)
#define FUSED_SMEM ((V_OFF + 2 * KBUFW) * 4)

__global__ __launch_bounds__(256, 2) void fused_attn(
    const __half* __restrict__ qg, const __half* __restrict__ kg,
    const __half* __restrict__ vg, const uint32_t* __restrict__ bm,
    uint32_t* __restrict__ escr,
    float* __restrict__ probs, __half* __restrict__ ctx)
{
    extern __shared__ uint32_t sh[];
    uint32_t sbase;
    asm("{ .reg .u64 t0; cvta.to.shared.u64 t0, %1; cvt.u32.u64 %0, t0; }"
        : "=r"(sbase) : "l"(sh));

    const int tid  = threadIdx.x;
    const int w    = tid >> 5;
    const int lane = tid & 31;
    const int g    = lane >> 2;
    const int t    = lane & 3;
    const int wr   = w * 16;
    const int q0   = blockIdx.x * 128;
    const int bh   = blockIdx.y;
    const int bb   = bh / H_;
    const int h    = bh % H_;
    const __half* qbase = qg + (size_t)bh * S_ * D_;
    const __half* kbase = kg + (size_t)bh * S_ * D_;
    const __half* vbase = vg + (size_t)bh * S_ * D_;

    const int lr0 = wr + g;
    const int lr1 = lr0 + 8;
    const int r0  = q0 + lr0;
    const int r1  = q0 + lr1;
    const uint32_t* bm0 = bm + ((size_t)bb * S_ + r0) * 64;
    const uint32_t* bm1 = bm + ((size_t)bb * S_ + r1) * 64;

    uint32_t* eb = escr + (((size_t)bh * 16 + blockIdx.x) * 32) * 4096 + tid * 4;

    const int arow = wr + (lane & 15);
    const int ahi  = (lane >> 4) * 4;
    const int brow = (lane & 7) + ((lane >> 1) & 8);
    const int bhi  = ((lane >> 3) & 1) * 4;
    const int vrow = lane & 15;
    const int vhi  = (lane >> 4) * 4;
    const uint32_t qaddr  = sbase + (uint32_t)(Q_OFF + arow * FP_ + ahi) * 4;
    const uint32_t kaddr0 = sbase + (uint32_t)(K_OFF + brow * FP_ + bhi) * 4;
    const uint32_t vaddr0 = sbase + (uint32_t)(V_OFF + vrow * FP_ + vhi) * 4;

    const int cr0 = tid >> 2, cc0 = (tid & 3) * 2;

#pragma unroll
    for (int i = 0; i < 4; i++) {
        int u = tid + 256 * i;
        int r = u >> 3, c = u & 7;
        cpa16(sbase + (uint32_t)(Q_OFF + r * FP_ + c * 4) * 4,
              qbase + (size_t)(q0 + r) * D_ + c * 8);
    }
#pragma unroll
    for (int i = 0; i < 2; i++)
        cpa16(sbase + (uint32_t)(K_OFF + cr0 * FP_ + (cc0 + i) * 4) * 4,
              kbase + (size_t)cr0 * D_ + (cc0 + i) * 8);
    CP_COMMIT();
    CP_WAIT0();
    __syncthreads();

    uint32_t qa[4][4];
#pragma unroll
    for (int s = 0; s < 4; s++)
        ldsm4(qa[s][0], qa[s][1], qa[s][2], qa[s][3], qaddr + s * 32);

    float s0v = 0.f, s1v = 0.f;
    int buf = 0;

    // Pass 1: QK -> e (store) + row sums
    for (int kt = 0; kt < 32; kt++) {
        if (kt < 31) {
            const __half* src = kbase + (size_t)(kt + 1) * 64 * D_;
            uint32_t dst = sbase + (uint32_t)(K_OFF + (buf ^ 1) * KBUFW) * 4;
#pragma unroll
            for (int i = 0; i < 2; i++)
                cpa16(dst + (uint32_t)(cr0 * FP_ + (cc0 + i) * 4) * 4,
                      src + (size_t)cr0 * D_ + (cc0 + i) * 8);
            CP_COMMIT();
        }

        float acc[8][4];
#pragma unroll
        for (int ni = 0; ni < 8; ni++)
#pragma unroll
            for (int r = 0; r < 4; r++) acc[ni][r] = 0.f;

        uint32_t ka = kaddr0 + (uint32_t)(buf * KBUFW) * 4;
#pragma unroll
        for (int s = 0; s < 4; s++) {
            uint32_t kb[16];
#pragma unroll
            for (int j = 0; j < 4; j++)
                ldsm4(kb[4 * j], kb[4 * j + 1], kb[4 * j + 2], kb[4 * j + 3],
                      ka + (uint32_t)(16 * j * FP_ + s * 8) * 4);
#pragma unroll
            for (int ni = 0; ni < 8; ni++)
                mma16(acc[ni], qa[s][0], qa[s][1], qa[s][2], qa[s][3],
                      kb[2 * ni], kb[2 * ni + 1]);
        }

        int k0 = kt * 64;
        uint2 w0 = *(const uint2*)(bm0 + (k0 >> 5));
        uint2 w1 = *(const uint2*)(bm1 + (k0 >> 5));
        uint32_t ue[16];
#pragma unroll
        for (int ni = 0; ni < 8; ni++) {
            uint32_t sel0 = (ni < 4) ? w0.x : w0.y;
            uint32_t sel1 = (ni < 4) ? w1.x : w1.y;
            int bit = (8 * ni + 2 * t) & 31;
            float e00 = ((sel0 >> bit) & 1)       ? 0.f : __expf(acc[ni][0] * SCALE_);
            float e01 = ((sel0 >> (bit + 1)) & 1) ? 0.f : __expf(acc[ni][1] * SCALE_);
            float e10 = ((sel1 >> bit) & 1)       ? 0.f : __expf(acc[ni][2] * SCALE_);
            float e11 = ((sel1 >> (bit + 1)) & 1) ? 0.f : __expf(acc[ni][3] * SCALE_);
            s0v += e00 + e01;
            s1v += e10 + e11;
            ue[2 * ni]     = ph2(e00, e01);
            ue[2 * ni + 1] = ph2(e10, e11);
        }
        uint32_t* ep = eb + (size_t)kt * 4096;
#pragma unroll
        for (int i4 = 0; i4 < 4; i4++)
            *(uint4*)(ep + i4 * 1024) = *(const uint4*)&ue[4 * i4];

        if (kt < 31) CP_WAIT0();
        __syncthreads();
        buf ^= 1;
    }

    s0v += __shfl_xor_sync(0xffffffffu, s0v, 1);
    s0v += __shfl_xor_sync(0xffffffffu, s0v, 2);
    s1v += __shfl_xor_sync(0xffffffffu, s1v, 1);
    s1v += __shfl_xor_sync(0xffffffffu, s1v, 2);
    const float inv0 = 1.f / s0v;
    const float inv1 = 1.f / s1v;

    float accv[8][4];
#pragma unroll
    for (int ni = 0; ni < 8; ni++)
#pragma unroll
        for (int r = 0; r < 4; r++) accv[ni][r] = 0.f;

    float* pr0 = probs + ((size_t)bh * S_ + r0) * S_;
    float* pr1 = probs + ((size_t)bh * S_ + r1) * S_;

    buf = 0;
#pragma unroll
    for (int i = 0; i < 2; i++)
        cpa16(sbase + (uint32_t)(V_OFF + cr0 * FP_ + (cc0 + i) * 4) * 4,
              vbase + (size_t)cr0 * D_ + (cc0 + i) * 8);
    CP_COMMIT();

    uint32_t uc[16];
#pragma unroll
    for (int i4 = 0; i4 < 4; i4++)
        *(uint4*)&uc[4 * i4] = *(const uint4*)(eb + i4 * 1024);

    CP_WAIT0();
    __syncthreads();

    // Pass 2: probs + PV (no QK, no exp)
    for (int kt = 0; kt < 32; kt++) {
        uint32_t un[16];
        if (kt < 31) {
            uint32_t* ep = eb + (size_t)(kt + 1) * 4096;
#pragma unroll
            for (int i4 = 0; i4 < 4; i4++)
                *(uint4*)&un[4 * i4] = *(const uint4*)(ep + i4 * 1024);
            const __half* vsrc = vbase + (size_t)(kt + 1) * 64 * D_;
            uint32_t vdst = sbase + (uint32_t)(V_OFF + (buf ^ 1) * KBUFW) * 4;
#pragma unroll
            for (int i = 0; i < 2; i++)
                cpa16(vdst + (uint32_t)(cr0 * FP_ + (cc0 + i) * 4) * 4,
                      vsrc + (size_t)cr0 * D_ + (cc0 + i) * 8);
            CP_COMMIT();
        }

        int k0 = kt * 64;
#pragma unroll
        for (int ni = 0; ni < 8; ni++) {
            float2 e0 = __half22float2(*(const __half2*)&uc[2 * ni]);
            float2 e1 = __half22float2(*(const __half2*)&uc[2 * ni + 1]);
            int c = k0 + 8 * ni + 2 * t;
            __stcs((float2*)(pr0 + c), make_float2(e0.x * inv0, e0.y * inv0));
            __stcs((float2*)(pr1 + c), make_float2(e1.x * inv1, e1.y * inv1));
        }

        uint32_t va = vaddr0 + (uint32_t)(buf * KBUFW) * 4;
#pragma unroll
        for (int s = 0; s < 4; s++) {
#pragma unroll
            for (int j = 0; j < 4; j++) {
                uint32_t vb0, vb1, vb2, vb3;
                ldsm4t(vb0, vb1, vb2, vb3,
                       va + (uint32_t)(16 * s * FP_ + 8 * j) * 4);
                mma16(accv[2 * j],     uc[4 * s], uc[4 * s + 1], uc[4 * s + 2], uc[4 * s + 3], vb0, vb1);
                mma16(accv[2 * j + 1], uc[4 * s], uc[4 * s + 1], uc[4 * s + 2], uc[4 * s + 3], vb2, vb3);
            }
        }

        if (kt < 31) {
            CP_WAIT0();
#pragma unroll
            for (int i = 0; i < 16; i++) uc[i] = un[i];
        }
        __syncthreads();
        buf ^= 1;
    }

#pragma unroll
    for (int ni = 0; ni < 8; ni++) {
        int col = h * D_ + 8 * ni + 2 * t;
        *(uint32_t*)&ctx[((size_t)(bb * S_ + r0)) * HID_ + col] =
            ph2(accv[ni][0] * inv0, accv[ni][1] * inv0);
        *(uint32_t*)&ctx[((size_t)(bb * S_ + r1)) * HID_ + col] =
            ph2(accv[ni][2] * inv1, accv[ni][3] * inv1);
    }
}

// ---------------------------------------------------------------------------
extern "C" void kernel_launch(void* const* d_in, const int* in_sizes, int n_in,
                              void* d_out, int out_size)
{
    (void)in_sizes; (void)n_in; (void)out_size;
    const float* Q  = (const float*)d_in[0];
    const float* K  = (const float*)d_in[1];
    const float* V  = (const float*)d_in[2];
    const int*   mask = (const int*)d_in[3];
    const float* Wq = (const float*)d_in[4];
    const float* bq = (const float*)d_in[5];
    const float* Wk = (const float*)d_in[6];
    const float* bk = (const float*)d_in[7];
    const float* Wv = (const float*)d_in[8];
    const float* bv = (const float*)d_in[9];
    const float* Wo = (const float*)d_in[10];
    const float* bo = (const float*)d_in[11];

    float* out   = (float*)d_out;
    float* probs = out + OUTE;

    float* scratch = nullptr;
    cudaGetSymbolAddress((void**)&scratch, g_scratch);
    uint32_t* bmp = nullptr;
    cudaGetSymbolAddress((void**)&bmp, g_bm);
    uint32_t* escr = nullptr;
    cudaGetSymbolAddress((void**)&escr, g_escr);

    __half* rXq = (__half*)scratch;
    __half* rXk = rXq + (size_t)OUTE;
    __half* rXv = rXk + (size_t)OUTE;
    __half* rWq = rXv + (size_t)OUTE;
    __half* rWk = rWq + WE;
    __half* rWv = rWk + WE;
    __half* rWo = rWv + WE;
    __half* gq  = rWo + WE;
    __half* gk  = gq + (size_t)OUTE;
    __half* gv  = gk + (size_t)OUTE;
    __half* gctx = gv + (size_t)OUTE;

    cudaFuncSetAttribute(fused_attn, cudaFuncAttributeMaxDynamicSharedMemorySize,
                         FUSED_SMEM);
    cudaFuncSetAttribute(gemm_qkv, cudaFuncAttributeMaxDynamicSharedMemorySize,
                         GEMM_SMEM);
    cudaFuncSetAttribute(gemm_out, cudaFuncAttributeMaxDynamicSharedMemorySize,
                         GEMM_SMEM);

    prep_all<<<22784, 256>>>(Q, K, V, Wq, Wk, Wv, Wo,
                             rXq, rXk, rXv, rWq, rWk, rWv, rWo, mask, bmp);

    gemm_qkv<<<dim3(HID_ / 128, MROWS / 128, 3), 256, GEMM_SMEM>>>(
        rXq, rXk, rXv, rWq, rWk, rWv, bq, bk, bv, gq, gk, gv);
    fused_attn<<<dim3(S_ / 128, BH_), 256, FUSED_SMEM>>>(
        gq, gk, gv, bmp, escr, probs, gctx);
    gemm_out<<<dim3(HID_ / 128, MROWS / 128), 256, GEMM_SMEM>>>(gctx, rWo, bo, out);
}